// round 7
// baseline (speedup 1.0000x reference)
#include <cuda_runtime.h>
#include <cuda_bf16.h>
#include <cstdint>

// ---------------------------------------------------------------------------
// RegionAttention: x(16384,512) -> qkv gemm -> per-(region,head) attention with
// EPEG conv (depthwise k=5 along query axis) + softmax -> proj gemm -> out.
// R7: attention j-tile 32, single-buffer, 54.6KB smem -> 4 CTAs/SM
//     (32 warps/SM, latency hiding x2). GEMMs unchanged (mma.sync bf16 hi/lo).
// ---------------------------------------------------------------------------

#define LTOK   16384
#define DIMC   512
#define QKVC   1536
#define NH     8
#define HD     64
#define NREG   1024
#define SCALE_Q 0.125f   // 64^-0.5

__device__ float g_qkv[LTOK * QKVC];   // (l, 3*512): q at +0, k at +512, v at +1024
__device__ float g_att[LTOK * DIMC];   // attention output in token order

// region token (rg, n) -> original token index l
__device__ __forceinline__ int tok_index(int rg, int n) {
    return ((rg >> 2) << 12) | ((n >> 5) << 7) | ((rg & 3) << 5) | (n & 31);
}

// ===========================================================================
// mma.sync bf16 GEMM (unchanged from R6): C = A @ W^T + bias, hi/lo 3-term.
// ===========================================================================
__device__ __forceinline__ void mma16816(float c[4],
                                         uint32_t a0, uint32_t a1,
                                         uint32_t a2, uint32_t a3,
                                         uint32_t b0, uint32_t b1) {
    asm volatile(
        "mma.sync.aligned.m16n8k16.row.col.f32.bf16.bf16.f32 "
        "{%0,%1,%2,%3}, {%4,%5,%6,%7}, {%8,%9}, {%0,%1,%2,%3};"
        : "+f"(c[0]), "+f"(c[1]), "+f"(c[2]), "+f"(c[3])
        : "r"(a0), "r"(a1), "r"(a2), "r"(a3), "r"(b0), "r"(b1));
}

#define GSTRIDE 72
#define GOFF_AHI 0
#define GOFF_ALO (128 * GSTRIDE)
#define GOFF_WHI (2 * 128 * GSTRIDE)
#define GOFF_WLO (3 * 128 * GSTRIDE)
#define GEMM_SMEM_BYTES (4 * 128 * GSTRIDE * 2)   // 73728

__global__ __launch_bounds__(256) void gemm_mma_kernel(
    const float* __restrict__ A, const float* __restrict__ W,
    const float* __restrict__ bias, float* __restrict__ C,
    int M, int N, int K)
{
    extern __shared__ char smc[];
    __nv_bfloat16* sb = (__nv_bfloat16*)smc;

    const int tid  = threadIdx.x;
    const int m0   = blockIdx.y << 7;
    const int n0   = blockIdx.x << 7;
    const int wid  = tid >> 5;
    const int lane = tid & 31;
    const int wm   = wid & 1;
    const int wn   = wid >> 1;

    const int lr = tid >> 4;
    const int lc = (tid & 15) << 2;

    const int qrow = lane >> 2;
    const int qk2  = (lane & 3) << 1;

    float acc[4][4][4];
#pragma unroll
    for (int i = 0; i < 4; i++)
#pragma unroll
        for (int j = 0; j < 4; j++)
#pragma unroll
            for (int c = 0; c < 4; c++) acc[i][j][c] = 0.f;

    const int nchunks = K >> 6;
    for (int kc = 0; kc < nchunks; kc++) {
        const int k0 = kc << 6;
        const float* Ab = A + (size_t)m0 * K + k0;
        const float* Wb = W + (size_t)n0 * K + k0;

        if (kc > 0) __syncthreads();

#pragma unroll
        for (int it = 0; it < 8; it++) {
            int r = it * 16 + lr;
            float4 a4 = *(const float4*)(Ab + (size_t)r * K + lc);
            float4 w4 = *(const float4*)(Wb + (size_t)r * K + lc);

            int base = r * GSTRIDE + lc;

            __nv_bfloat162 ah01 = __floats2bfloat162_rn(a4.x, a4.y);
            __nv_bfloat162 ah23 = __floats2bfloat162_rn(a4.z, a4.w);
            __nv_bfloat162 al01 = __floats2bfloat162_rn(a4.x - __low2float(ah01),
                                                        a4.y - __high2float(ah01));
            __nv_bfloat162 al23 = __floats2bfloat162_rn(a4.z - __low2float(ah23),
                                                        a4.w - __high2float(ah23));
            uint2 hv, lv;
            hv.x = *(uint32_t*)&ah01; hv.y = *(uint32_t*)&ah23;
            lv.x = *(uint32_t*)&al01; lv.y = *(uint32_t*)&al23;
            *(uint2*)(sb + GOFF_AHI + base) = hv;
            *(uint2*)(sb + GOFF_ALO + base) = lv;

            __nv_bfloat162 wh01 = __floats2bfloat162_rn(w4.x, w4.y);
            __nv_bfloat162 wh23 = __floats2bfloat162_rn(w4.z, w4.w);
            __nv_bfloat162 wl01 = __floats2bfloat162_rn(w4.x - __low2float(wh01),
                                                        w4.y - __high2float(wh01));
            __nv_bfloat162 wl23 = __floats2bfloat162_rn(w4.z - __low2float(wh23),
                                                        w4.w - __high2float(wh23));
            hv.x = *(uint32_t*)&wh01; hv.y = *(uint32_t*)&wh23;
            lv.x = *(uint32_t*)&wl01; lv.y = *(uint32_t*)&wl23;
            *(uint2*)(sb + GOFF_WHI + base) = hv;
            *(uint2*)(sb + GOFF_WLO + base) = lv;
        }
        __syncthreads();

#pragma unroll
        for (int ks = 0; ks < 4; ks++) {
            const int kb = ks * 16 + qk2;
            uint32_t a[4][4], bh[4][2], bl[4][2];

#pragma unroll
            for (int i = 0; i < 4; i++) {
                int r0 = wm * 64 + i * 16 + qrow;
                a[i][0] = *(const uint32_t*)(sb + GOFF_AHI + r0 * GSTRIDE + kb);
                a[i][1] = *(const uint32_t*)(sb + GOFF_AHI + (r0 + 8) * GSTRIDE + kb);
                a[i][2] = *(const uint32_t*)(sb + GOFF_AHI + r0 * GSTRIDE + kb + 8);
                a[i][3] = *(const uint32_t*)(sb + GOFF_AHI + (r0 + 8) * GSTRIDE + kb + 8);
            }
#pragma unroll
            for (int j = 0; j < 4; j++) {
                int nr = wn * 32 + j * 8 + qrow;
                bh[j][0] = *(const uint32_t*)(sb + GOFF_WHI + nr * GSTRIDE + kb);
                bh[j][1] = *(const uint32_t*)(sb + GOFF_WHI + nr * GSTRIDE + kb + 8);
            }
#pragma unroll
            for (int i = 0; i < 4; i++)
#pragma unroll
                for (int j = 0; j < 4; j++)
                    mma16816(acc[i][j], a[i][0], a[i][1], a[i][2], a[i][3],
                             bh[j][0], bh[j][1]);

#pragma unroll
            for (int j = 0; j < 4; j++) {
                int nr = wn * 32 + j * 8 + qrow;
                bl[j][0] = *(const uint32_t*)(sb + GOFF_WLO + nr * GSTRIDE + kb);
                bl[j][1] = *(const uint32_t*)(sb + GOFF_WLO + nr * GSTRIDE + kb + 8);
            }
#pragma unroll
            for (int i = 0; i < 4; i++)
#pragma unroll
                for (int j = 0; j < 4; j++)
                    mma16816(acc[i][j], a[i][0], a[i][1], a[i][2], a[i][3],
                             bl[j][0], bl[j][1]);

#pragma unroll
            for (int i = 0; i < 4; i++) {
                int r0 = wm * 64 + i * 16 + qrow;
                a[i][0] = *(const uint32_t*)(sb + GOFF_ALO + r0 * GSTRIDE + kb);
                a[i][1] = *(const uint32_t*)(sb + GOFF_ALO + (r0 + 8) * GSTRIDE + kb);
                a[i][2] = *(const uint32_t*)(sb + GOFF_ALO + r0 * GSTRIDE + kb + 8);
                a[i][3] = *(const uint32_t*)(sb + GOFF_ALO + (r0 + 8) * GSTRIDE + kb + 8);
            }
#pragma unroll
            for (int i = 0; i < 4; i++)
#pragma unroll
                for (int j = 0; j < 4; j++)
                    mma16816(acc[i][j], a[i][0], a[i][1], a[i][2], a[i][3],
                             bh[j][0], bh[j][1]);
        }
    }

#pragma unroll
    for (int i = 0; i < 4; i++) {
        int gr = m0 + wm * 64 + i * 16 + qrow;
#pragma unroll
        for (int j = 0; j < 4; j++) {
            int gc = n0 + wn * 32 + j * 8 + qk2;
            float2 bv = *(const float2*)(bias + gc);
            float2 o0, o1;
            o0.x = acc[i][j][0] + bv.x; o0.y = acc[i][j][1] + bv.y;
            o1.x = acc[i][j][2] + bv.x; o1.y = acc[i][j][3] + bv.y;
            *(float2*)(C + (size_t)gr * N + gc)       = o0;
            *(float2*)(C + (size_t)(gr + 8) * N + gc) = o1;
        }
    }
}

// ---------------------------------------------------------------------------
// Fused region attention R7: 64-row Q tiles, 32-key j-tiles, 4 CTAs/SM.
// grid: (row_tile 0..15, head 0..7, region 0..15), 256 threads.
// ---------------------------------------------------------------------------
#define NJ 32            // keys per j-tile
#define NJT 32           // number of j-tiles (1024/32)

// smem float offsets (total 13648 floats = 54592 B -> 4 CTAs/SM)
#define OFF_QST   0        // [64 d][68]  cols 0..63 main rows, 64..67 halo
#define OFF_KST   4352     // [64 d][36]
#define OFF_VS    6656     // [32 j][68]
#define OFF_SS    8832     // [68 p][36]  p <-> region row i0-2+p
#define OFF_PST   11280    // [32 j][68]  (j, row)
#define OFF_ALPHA 13456    // [64]
#define OFF_M     13520    // [64]
#define OFF_L     13584    // [64]
#define SMEM_ATTN_FLOATS 13648
#define SMEM_ATTN_BYTES (SMEM_ATTN_FLOATS * 4)

__global__ __launch_bounds__(256, 4) void region_attn_kernel(
    const float* __restrict__ epeg_w, const float* __restrict__ epeg_b)
{
    extern __shared__ char smc[];
    float* sm = (float*)smc;
    float* QsT     = sm + OFF_QST;
    float* KsT     = sm + OFF_KST;
    float* Vs      = sm + OFF_VS;
    float* Ss      = sm + OFF_SS;
    float* PsT     = sm + OFF_PST;
    float* alpha_s = sm + OFF_ALPHA;
    float* m_row   = sm + OFF_M;
    float* l_row   = sm + OFF_L;

    const int tid  = threadIdx.x;
    const int it   = blockIdx.x;
    const int h    = blockIdx.y;
    const int rg   = blockIdx.z;
    const int i0   = it << 6;

    const int ty   = tid >> 4;   // 0..15
    const int tx   = tid & 15;   // 0..15
    const int warp = tid >> 5;   // 0..7
    const int lane = tid & 31;

    const float cw0 = epeg_w[h * 5 + 0];
    const float cw1 = epeg_w[h * 5 + 1];
    const float cw2 = epeg_w[h * 5 + 2];
    const float cw3 = epeg_w[h * 5 + 3];
    const float cw4 = epeg_w[h * 5 + 4];
    const float cb  = epeg_b[h];

    if (tid < 64) { m_row[tid] = -3.0e38f; l_row[tid] = 0.f; }

    // ---- load Q (scaled), transposed to (d, row-col); zero out-of-region halo
    for (int idx = tid; idx < 68 * 16; idx += 256) {
        int p  = idx >> 4;            // 0..67 (Ss row index)
        int c4 = (idx & 15) << 2;     // d base
        int col = (p < 2) ? (64 + p) : ((p < 66) ? (p - 2) : p);
        int ireg = i0 - 2 + p;
        float4 q = make_float4(0.f, 0.f, 0.f, 0.f);
        if (ireg >= 0 && ireg < NREG) {
            int l = tok_index(rg, ireg);
            q = *(const float4*)(g_qkv + (size_t)l * QKVC + h * HD + c4);
        }
        QsT[(c4 + 0) * 68 + col] = q.x * SCALE_Q;
        QsT[(c4 + 1) * 68 + col] = q.y * SCALE_Q;
        QsT[(c4 + 2) * 68 + col] = q.z * SCALE_Q;
        QsT[(c4 + 3) * 68 + col] = q.w * SCALE_Q;
    }

    float accO[4][4];
#pragma unroll
    for (int i = 0; i < 4; i++)
#pragma unroll
        for (int j = 0; j < 4; j++) accO[i][j] = 0.f;

    __syncthreads();

    for (int jt = 0; jt < NJT; jt++) {
        // ---- load K (transposed) and V tile: 32 j x 16 c4 = 512 float4 slots
#pragma unroll
        for (int s = 0; s < 2; s++) {
            int idx = tid + s * 256;
            int j   = idx >> 4;             // 0..31
            int c4  = (idx & 15) << 2;
            int l   = tok_index(rg, (jt << 5) + j);
            const float* base = g_qkv + (size_t)l * QKVC + h * HD + c4;
            float4 k4 = *(const float4*)(base + 512);
            float4 v4 = *(const float4*)(base + 1024);
            KsT[(c4 + 0) * 36 + j] = k4.x;
            KsT[(c4 + 1) * 36 + j] = k4.y;
            KsT[(c4 + 2) * 36 + j] = k4.z;
            KsT[(c4 + 3) * 36 + j] = k4.w;
            *(float4*)(Vs + j * 68 + c4) = v4;
        }
        __syncthreads();

        // ---- S = Qscaled @ K^T : main 64x32 (4x2 per thread) + 4 halo rows
        {
            float accS[4][2];
#pragma unroll
            for (int i = 0; i < 4; i++) { accS[i][0] = 0.f; accS[i][1] = 0.f; }

#pragma unroll 8
            for (int d = 0; d < 64; d++) {
                float af[4], bf[2];
                *(float4*)(af) = *(const float4*)(QsT + d * 68 + ty * 4);
                *(float2*)(bf) = *(const float2*)(KsT + d * 36 + tx * 2);
#pragma unroll
                for (int i = 0; i < 4; i++) {
                    accS[i][0] += af[i] * bf[0];
                    accS[i][1] += af[i] * bf[1];
                }
            }
#pragma unroll
            for (int i = 0; i < 4; i++) {
                *(float2*)(Ss + (ty * 4 + i + 2) * 36 + tx * 2) =
                    make_float2(accS[i][0], accS[i][1]);
            }

            // halo rows: 4 rows x 32 cols, threads 0..127 one dot each
            if (tid < 128) {
                int hr = tid >> 5;      // 0..3
                int j  = tid & 31;
                float a = 0.f;
#pragma unroll 8
                for (int d = 0; d < 64; d++)
                    a += QsT[d * 68 + 64 + hr] * KsT[d * 36 + j];
                int ps = (hr < 2) ? hr : (64 + hr);   // 0,1,66,67
                Ss[ps * 36 + j] = a;
            }
        }
        __syncthreads();

        // ---- conv + bias + online softmax (warp w owns rows w*8..w*8+7)
        for (int rr = 0; rr < 8; rr++) {
            int r = (warp << 3) + rr;
            int j = lane;
            float s0 = Ss[(r + 0) * 36 + j];
            float s1 = Ss[(r + 1) * 36 + j];
            float s2 = Ss[(r + 2) * 36 + j];
            float s3 = Ss[(r + 3) * 36 + j];
            float s4 = Ss[(r + 4) * 36 + j];
            float lg = s2 + cb + cw0 * s0 + cw1 * s1 + cw2 * s2 + cw3 * s3 + cw4 * s4;

            float mx = lg;
#pragma unroll
            for (int off = 16; off > 0; off >>= 1)
                mx = fmaxf(mx, __shfl_xor_sync(0xffffffffu, mx, off));
            float m_old = m_row[r];
            float m_new = fmaxf(m_old, mx);
            float p0 = __expf(lg - m_new);
            float rs = p0;
#pragma unroll
            for (int off = 16; off > 0; off >>= 1)
                rs += __shfl_xor_sync(0xffffffffu, rs, off);
            if (lane == 0) {
                float alpha = __expf(m_old - m_new);
                l_row[r] = l_row[r] * alpha + rs;
                m_row[r] = m_new;
                alpha_s[r] = alpha;
            }
            PsT[lane * 68 + r] = p0;
        }
        __syncthreads();

        // ---- O = O*alpha + P @ V  (4 rows x 4 d-cols per thread)
        {
#pragma unroll
            for (int i = 0; i < 4; i++) {
                float al = alpha_s[ty * 4 + i];
#pragma unroll
                for (int j = 0; j < 4; j++) accO[i][j] *= al;
            }
#pragma unroll 8
            for (int j = 0; j < NJ; j++) {
                float pf[4], vf[4];
                *(float4*)(pf) = *(const float4*)(PsT + j * 68 + ty * 4);
                *(float4*)(vf) = *(const float4*)(Vs + j * 68 + tx * 4);
#pragma unroll
                for (int i = 0; i < 4; i++)
#pragma unroll
                    for (int c = 0; c < 4; c++)
                        accO[i][c] += pf[i] * vf[c];
            }
        }
        __syncthreads();   // protect KsT/Vs/Ss/PsT for next tile
    }

    // ---- normalize and write to g_att in token order (undoes region permute)
#pragma unroll
    for (int i = 0; i < 4; i++) {
        int r = ty * 4 + i;
        float inv = 1.0f / l_row[r];
        int l = tok_index(rg, i0 + r);
        *(float4*)(g_att + (size_t)l * DIMC + h * HD + tx * 4) =
            make_float4(accO[i][0] * inv, accO[i][1] * inv,
                        accO[i][2] * inv, accO[i][3] * inv);
    }
}

// ---------------------------------------------------------------------------
extern "C" void kernel_launch(void* const* d_in, const int* in_sizes, int n_in,
                              void* d_out, int out_size) {
    const float* x      = (const float*)d_in[0];
    const float* qkv_w  = (const float*)d_in[1];
    const float* qkv_b  = (const float*)d_in[2];
    const float* proj_w = (const float*)d_in[3];
    const float* proj_b = (const float*)d_in[4];
    const float* epeg_w = (const float*)d_in[5];
    const float* epeg_b = (const float*)d_in[6];
    float* out = (float*)d_out;

    float* qkv_buf = nullptr;
    float* att_buf = nullptr;
    cudaGetSymbolAddress((void**)&qkv_buf, g_qkv);
    cudaGetSymbolAddress((void**)&att_buf, g_att);

    cudaFuncSetAttribute(gemm_mma_kernel,
                         cudaFuncAttributeMaxDynamicSharedMemorySize,
                         GEMM_SMEM_BYTES);
    cudaFuncSetAttribute(region_attn_kernel,
                         cudaFuncAttributeMaxDynamicSharedMemorySize,
                         SMEM_ATTN_BYTES);

    // qkv = x @ qkv_w^T + qkv_b   (bf16 mma.sync, hi/lo split)
    gemm_mma_kernel<<<dim3(QKVC / 128, LTOK / 128), 256, GEMM_SMEM_BYTES>>>(
        x, qkv_w, qkv_b, qkv_buf, LTOK, QKVC, DIMC);

    // fused region attention (writes g_att in token order)
    region_attn_kernel<<<dim3(16, NH, 16), 256, SMEM_ATTN_BYTES>>>(epeg_w, epeg_b);

    // out = att @ proj_w^T + proj_b   (bf16 mma.sync, hi/lo split)
    gemm_mma_kernel<<<dim3(DIMC / 128, LTOK / 128), 256, GEMM_SMEM_BYTES>>>(
        att_buf, proj_w, proj_b, out, LTOK, DIMC, DIMC);
}

// round 8
// speedup vs baseline: 2.4463x; 2.4463x over previous
#include <cuda_runtime.h>
#include <cuda_bf16.h>
#include <cstdint>

// ---------------------------------------------------------------------------
// RegionAttention R8:
//  - dense GEMMs: mma.sync bf16 hi/lo 3-term (unchanged from R6)
//  - attention: EPEG conv folded into Q' = SCALE*(q + conv5(q)) (per-head bias
//    dropped: softmax-invariant). Flash attention on mma.sync bf16 hi/lo,
//    register-resident online softmax (each warp owns 16 complete rows).
// ---------------------------------------------------------------------------

#define LTOK   16384
#define DIMC   512
#define QKVC   1536
#define NH     8
#define HD     64
#define NREG   1024
#define SCALE_Q 0.125f

__device__ float g_qkv[LTOK * QKVC];   // (l, 3*512): q +0, k +512, v +1024
__device__ float g_att[LTOK * DIMC];   // attention output in token order

__device__ __forceinline__ int tok_index(int rg, int n) {
    return ((rg >> 2) << 12) | ((n >> 5) << 7) | ((rg & 3) << 5) | (n & 31);
}

__device__ __forceinline__ uint32_t smem_u32(const void* p) {
    uint32_t a;
    asm("{ .reg .u64 t; cvta.to.shared.u64 t, %1; cvt.u32.u64 %0, t; }"
        : "=r"(a) : "l"(p));
    return a;
}

__device__ __forceinline__ void mma16816(float c[4],
                                         uint32_t a0, uint32_t a1,
                                         uint32_t a2, uint32_t a3,
                                         uint32_t b0, uint32_t b1) {
    asm volatile(
        "mma.sync.aligned.m16n8k16.row.col.f32.bf16.bf16.f32 "
        "{%0,%1,%2,%3}, {%4,%5,%6,%7}, {%8,%9}, {%0,%1,%2,%3};"
        : "+f"(c[0]), "+f"(c[1]), "+f"(c[2]), "+f"(c[3])
        : "r"(a0), "r"(a1), "r"(a2), "r"(a3), "r"(b0), "r"(b1));
}

// split a float pair into bf16 hi/lo packed u32s
__device__ __forceinline__ void split2(float x, float y, uint32_t& hi, uint32_t& lo) {
    __nv_bfloat162 h = __floats2bfloat162_rn(x, y);
    __nv_bfloat162 l = __floats2bfloat162_rn(x - __low2float(h), y - __high2float(h));
    hi = *(uint32_t*)&h;
    lo = *(uint32_t*)&l;
}

// ===========================================================================
// mma.sync bf16 GEMM (unchanged from R6): C = A @ W^T + bias, hi/lo 3-term.
// ===========================================================================
#define GSTRIDE 72
#define GOFF_AHI 0
#define GOFF_ALO (128 * GSTRIDE)
#define GOFF_WHI (2 * 128 * GSTRIDE)
#define GOFF_WLO (3 * 128 * GSTRIDE)
#define GEMM_SMEM_BYTES (4 * 128 * GSTRIDE * 2)   // 73728

__global__ __launch_bounds__(256) void gemm_mma_kernel(
    const float* __restrict__ A, const float* __restrict__ W,
    const float* __restrict__ bias, float* __restrict__ C,
    int M, int N, int K)
{
    extern __shared__ char smc[];
    __nv_bfloat16* sb = (__nv_bfloat16*)smc;

    const int tid  = threadIdx.x;
    const int m0   = blockIdx.y << 7;
    const int n0   = blockIdx.x << 7;
    const int wid  = tid >> 5;
    const int lane = tid & 31;
    const int wm   = wid & 1;
    const int wn   = wid >> 1;

    const int lr = tid >> 4;
    const int lc = (tid & 15) << 2;

    const int qrow = lane >> 2;
    const int qk2  = (lane & 3) << 1;

    float acc[4][4][4];
#pragma unroll
    for (int i = 0; i < 4; i++)
#pragma unroll
        for (int j = 0; j < 4; j++)
#pragma unroll
            for (int c = 0; c < 4; c++) acc[i][j][c] = 0.f;

    const int nchunks = K >> 6;
    for (int kc = 0; kc < nchunks; kc++) {
        const int k0 = kc << 6;
        const float* Ab = A + (size_t)m0 * K + k0;
        const float* Wb = W + (size_t)n0 * K + k0;

        if (kc > 0) __syncthreads();

#pragma unroll
        for (int it = 0; it < 8; it++) {
            int r = it * 16 + lr;
            float4 a4 = *(const float4*)(Ab + (size_t)r * K + lc);
            float4 w4 = *(const float4*)(Wb + (size_t)r * K + lc);
            int base = r * GSTRIDE + lc;
            uint2 hv, lv;
            split2(a4.x, a4.y, hv.x, lv.x);
            split2(a4.z, a4.w, hv.y, lv.y);
            *(uint2*)(sb + GOFF_AHI + base) = hv;
            *(uint2*)(sb + GOFF_ALO + base) = lv;
            split2(w4.x, w4.y, hv.x, lv.x);
            split2(w4.z, w4.w, hv.y, lv.y);
            *(uint2*)(sb + GOFF_WHI + base) = hv;
            *(uint2*)(sb + GOFF_WLO + base) = lv;
        }
        __syncthreads();

#pragma unroll
        for (int ks = 0; ks < 4; ks++) {
            const int kb = ks * 16 + qk2;
            uint32_t a[4][4], bh[4][2], bl[4][2];

#pragma unroll
            for (int i = 0; i < 4; i++) {
                int r0 = wm * 64 + i * 16 + qrow;
                a[i][0] = *(const uint32_t*)(sb + GOFF_AHI + r0 * GSTRIDE + kb);
                a[i][1] = *(const uint32_t*)(sb + GOFF_AHI + (r0 + 8) * GSTRIDE + kb);
                a[i][2] = *(const uint32_t*)(sb + GOFF_AHI + r0 * GSTRIDE + kb + 8);
                a[i][3] = *(const uint32_t*)(sb + GOFF_AHI + (r0 + 8) * GSTRIDE + kb + 8);
            }
#pragma unroll
            for (int j = 0; j < 4; j++) {
                int nr = wn * 32 + j * 8 + qrow;
                bh[j][0] = *(const uint32_t*)(sb + GOFF_WHI + nr * GSTRIDE + kb);
                bh[j][1] = *(const uint32_t*)(sb + GOFF_WHI + nr * GSTRIDE + kb + 8);
            }
#pragma unroll
            for (int i = 0; i < 4; i++)
#pragma unroll
                for (int j = 0; j < 4; j++)
                    mma16816(acc[i][j], a[i][0], a[i][1], a[i][2], a[i][3],
                             bh[j][0], bh[j][1]);

#pragma unroll
            for (int j = 0; j < 4; j++) {
                int nr = wn * 32 + j * 8 + qrow;
                bl[j][0] = *(const uint32_t*)(sb + GOFF_WLO + nr * GSTRIDE + kb);
                bl[j][1] = *(const uint32_t*)(sb + GOFF_WLO + nr * GSTRIDE + kb + 8);
            }
#pragma unroll
            for (int i = 0; i < 4; i++)
#pragma unroll
                for (int j = 0; j < 4; j++)
                    mma16816(acc[i][j], a[i][0], a[i][1], a[i][2], a[i][3],
                             bl[j][0], bl[j][1]);

#pragma unroll
            for (int i = 0; i < 4; i++) {
                int r0 = wm * 64 + i * 16 + qrow;
                a[i][0] = *(const uint32_t*)(sb + GOFF_ALO + r0 * GSTRIDE + kb);
                a[i][1] = *(const uint32_t*)(sb + GOFF_ALO + (r0 + 8) * GSTRIDE + kb);
                a[i][2] = *(const uint32_t*)(sb + GOFF_ALO + r0 * GSTRIDE + kb + 8);
                a[i][3] = *(const uint32_t*)(sb + GOFF_ALO + (r0 + 8) * GSTRIDE + kb + 8);
            }
#pragma unroll
            for (int i = 0; i < 4; i++)
#pragma unroll
                for (int j = 0; j < 4; j++)
                    mma16816(acc[i][j], a[i][0], a[i][1], a[i][2], a[i][3],
                             bh[j][0], bh[j][1]);
        }
    }

#pragma unroll
    for (int i = 0; i < 4; i++) {
        int gr = m0 + wm * 64 + i * 16 + qrow;
#pragma unroll
        for (int j = 0; j < 4; j++) {
            int gc = n0 + wn * 32 + j * 8 + qk2;
            float2 bv = *(const float2*)(bias + gc);
            float2 o0, o1;
            o0.x = acc[i][j][0] + bv.x; o0.y = acc[i][j][1] + bv.y;
            o1.x = acc[i][j][2] + bv.x; o1.y = acc[i][j][3] + bv.y;
            *(float2*)(C + (size_t)gr * N + gc)       = o0;
            *(float2*)(C + (size_t)(gr + 8) * N + gc) = o1;
        }
    }
}

// ===========================================================================
// Flash attention on mma.sync, conv folded into Q'.
// grid: (row_tile 0..7 [128 rows], head 0..7, region 0..15), 256 thr, 8 warps.
// Each warp owns 16 full rows -> register-only online softmax.
// smem (bf16 units, stride 72/row): Q'hi, Q'lo, Khi, Klo, Vhi, Vlo
// ===========================================================================
#define AQH 0
#define AQL (128 * 72)
#define AKH (2 * 128 * 72)
#define AKL (3 * 128 * 72)
#define AVH (4 * 128 * 72)
#define AVL (5 * 128 * 72)
#define ATT_SMEM_BYTES (6 * 128 * 72 * 2)   // 110592

__global__ __launch_bounds__(256) void region_attn_mma_kernel(
    const float* __restrict__ epeg_w)
{
    extern __shared__ char smc[];
    __nv_bfloat16* sb = (__nv_bfloat16*)smc;
    const uint32_t sbu = smem_u32(smc);

    const int tid  = threadIdx.x;
    const int it   = blockIdx.x;
    const int h    = blockIdx.y;
    const int rg   = blockIdx.z;
    const int i0   = it << 7;

    const int warp = tid >> 5;
    const int lane = tid & 31;
    const int qr   = lane >> 2;          // 0..7
    const int q2   = (lane & 3) << 1;    // 0,2,4,6

    const float w0 = epeg_w[h * 5 + 0];
    const float w1 = epeg_w[h * 5 + 1];
    const float w2 = epeg_w[h * 5 + 2];
    const float w3 = epeg_w[h * 5 + 3];
    const float w4 = epeg_w[h * 5 + 4];

    // ---- stage q rows i0-2 .. i0+129 fp32 into scratch (K/V smem area)
    float* Qf = (float*)(smc + AKH * 2);   // [132][68] fp32
    for (int idx = tid; idx < 132 * 64; idx += 256) {
        int p = idx >> 6, d = idx & 63;
        int ii = i0 - 2 + p;
        float v = 0.f;
        if (ii >= 0 && ii < NREG)
            v = g_qkv[(size_t)tok_index(rg, ii) * QKVC + h * HD + d];
        Qf[p * 68 + d] = v;
    }
    __syncthreads();

    // ---- Q' = SCALE * (q_i + sum_t w_t q_{i-2+t}) -> bf16 hi/lo smem
    for (int idx = tid; idx < 128 * 64; idx += 256) {
        int i = idx >> 6, d = idx & 63;
        const float* col = Qf + i * 68 + d;   // p = i corresponds to row i0+i-2
        float v = col[2 * 68]
                + w0 * col[0] + w1 * col[68] + w2 * col[2 * 68]
                + w3 * col[3 * 68] + w4 * col[4 * 68];
        v *= SCALE_Q;
        __nv_bfloat16 hi = __float2bfloat16(v);
        __nv_bfloat16 lo = __float2bfloat16(v - __bfloat162float(hi));
        sb[AQH + i * 72 + d] = hi;
        sb[AQL + i * 72 + d] = lo;
    }
    __syncthreads();

    // ---- preload Q a-frags (persistent; warp rows r0..r0+15)
    uint32_t aQh[4][4], aQl[4][4];
    {
        int r0 = warp * 16;
#pragma unroll
        for (int ks = 0; ks < 4; ks++) {
            int kb = ks * 16 + q2;
            aQh[ks][0] = *(const uint32_t*)(sb + AQH + (r0 + qr) * 72 + kb);
            aQh[ks][1] = *(const uint32_t*)(sb + AQH + (r0 + qr + 8) * 72 + kb);
            aQh[ks][2] = *(const uint32_t*)(sb + AQH + (r0 + qr) * 72 + kb + 8);
            aQh[ks][3] = *(const uint32_t*)(sb + AQH + (r0 + qr + 8) * 72 + kb + 8);
            aQl[ks][0] = *(const uint32_t*)(sb + AQL + (r0 + qr) * 72 + kb);
            aQl[ks][1] = *(const uint32_t*)(sb + AQL + (r0 + qr + 8) * 72 + kb);
            aQl[ks][2] = *(const uint32_t*)(sb + AQL + (r0 + qr) * 72 + kb + 8);
            aQl[ks][3] = *(const uint32_t*)(sb + AQL + (r0 + qr + 8) * 72 + kb + 8);
        }
    }

    float sO[8][4];
#pragma unroll
    for (int i = 0; i < 8; i++)
#pragma unroll
        for (int c = 0; c < 4; c++) sO[i][c] = 0.f;
    float mA = -1e30f, mB = -1e30f, lA = 0.f, lB = 0.f;

    for (int jt = 0; jt < 8; jt++) {
        if (jt) __syncthreads();   // prev tile's smem readers done

        // ---- load K,V tile (128 tokens x 64 d), split hi/lo
#pragma unroll
        for (int s = 0; s < 8; s++) {
            int idx = tid + s * 256;
            int j = idx >> 4, c4 = (idx & 15) << 2;
            const float* base =
                g_qkv + (size_t)tok_index(rg, (jt << 7) + j) * QKVC + h * HD + c4;
            float4 k4 = *(const float4*)(base + 512);
            float4 v4 = *(const float4*)(base + 1024);
            uint2 hv, lv;
            split2(k4.x, k4.y, hv.x, lv.x);
            split2(k4.z, k4.w, hv.y, lv.y);
            *(uint2*)(sb + AKH + j * 72 + c4) = hv;
            *(uint2*)(sb + AKL + j * 72 + c4) = lv;
            split2(v4.x, v4.y, hv.x, lv.x);
            split2(v4.z, v4.w, hv.y, lv.y);
            *(uint2*)(sb + AVH + j * 72 + c4) = hv;
            *(uint2*)(sb + AVL + j * 72 + c4) = lv;
        }
        __syncthreads();

        // ---- S = Q' @ K^T  (warp: 16 rows x 128 cols, 3-term)
        float s[16][4];
#pragma unroll
        for (int nj = 0; nj < 16; nj++)
#pragma unroll
            for (int c = 0; c < 4; c++) s[nj][c] = 0.f;

#pragma unroll
        for (int ks = 0; ks < 4; ks++) {
            int kb = ks * 16 + q2;
#pragma unroll
            for (int nj = 0; nj < 16; nj++) {
                int nr = nj * 8 + qr;
                uint32_t bh0 = *(const uint32_t*)(sb + AKH + nr * 72 + kb);
                uint32_t bh1 = *(const uint32_t*)(sb + AKH + nr * 72 + kb + 8);
                uint32_t bl0 = *(const uint32_t*)(sb + AKL + nr * 72 + kb);
                uint32_t bl1 = *(const uint32_t*)(sb + AKL + nr * 72 + kb + 8);
                mma16816(s[nj], aQh[ks][0], aQh[ks][1], aQh[ks][2], aQh[ks][3], bh0, bh1);
                mma16816(s[nj], aQh[ks][0], aQh[ks][1], aQh[ks][2], aQh[ks][3], bl0, bl1);
                mma16816(s[nj], aQl[ks][0], aQl[ks][1], aQl[ks][2], aQl[ks][3], bh0, bh1);
            }
        }

        // ---- register online softmax (rows A=qr, B=qr+8 of warp block)
        float mtA = -1e30f, mtB = -1e30f;
#pragma unroll
        for (int nj = 0; nj < 16; nj++) {
            mtA = fmaxf(mtA, fmaxf(s[nj][0], s[nj][1]));
            mtB = fmaxf(mtB, fmaxf(s[nj][2], s[nj][3]));
        }
        mtA = fmaxf(mtA, __shfl_xor_sync(0xffffffffu, mtA, 1));
        mtA = fmaxf(mtA, __shfl_xor_sync(0xffffffffu, mtA, 2));
        mtB = fmaxf(mtB, __shfl_xor_sync(0xffffffffu, mtB, 1));
        mtB = fmaxf(mtB, __shfl_xor_sync(0xffffffffu, mtB, 2));
        float mnA = fmaxf(mA, mtA), mnB = fmaxf(mB, mtB);
        float alA = __expf(mA - mnA), alB = __expf(mB - mnB);
        mA = mnA; mB = mnB;

        float rsA = 0.f, rsB = 0.f;
#pragma unroll
        for (int nj = 0; nj < 16; nj++) {
            s[nj][0] = __expf(s[nj][0] - mnA);
            s[nj][1] = __expf(s[nj][1] - mnA);
            s[nj][2] = __expf(s[nj][2] - mnB);
            s[nj][3] = __expf(s[nj][3] - mnB);
            rsA += s[nj][0] + s[nj][1];
            rsB += s[nj][2] + s[nj][3];
        }
        rsA += __shfl_xor_sync(0xffffffffu, rsA, 1);
        rsA += __shfl_xor_sync(0xffffffffu, rsA, 2);
        rsB += __shfl_xor_sync(0xffffffffu, rsB, 1);
        rsB += __shfl_xor_sync(0xffffffffu, rsB, 2);
        lA = lA * alA + rsA;
        lB = lB * alB + rsB;

#pragma unroll
        for (int nd = 0; nd < 8; nd++) {
            sO[nd][0] *= alA; sO[nd][1] *= alA;
            sO[nd][2] *= alB; sO[nd][3] *= alB;
        }

        // ---- O += P @ V  (P frags from S regs; V frags via ldmatrix.trans)
#pragma unroll
        for (int kk = 0; kk < 8; kk++) {
            uint32_t pah[4], pal[4];
            split2(s[2 * kk][0],     s[2 * kk][1],     pah[0], pal[0]);
            split2(s[2 * kk][2],     s[2 * kk][3],     pah[1], pal[1]);
            split2(s[2 * kk + 1][0], s[2 * kk + 1][1], pah[2], pal[2]);
            split2(s[2 * kk + 1][2], s[2 * kk + 1][3], pah[3], pal[3]);
            int j0 = kk * 16;
            int vrow = j0 + (lane & 15);
            int vcol = (lane >> 4) << 3;
#pragma unroll
            for (int ndp = 0; ndp < 4; ndp++) {
                int d0 = ndp * 16;
                uint32_t vh0, vh1, vh2, vh3, vl0, vl1, vl2, vl3;
                uint32_t ah = sbu + (uint32_t)(AVH + vrow * 72 + d0 + vcol) * 2u;
                uint32_t al = sbu + (uint32_t)(AVL + vrow * 72 + d0 + vcol) * 2u;
                asm volatile(
                    "ldmatrix.sync.aligned.m8n8.x4.trans.shared.b16 {%0,%1,%2,%3}, [%4];"
                    : "=r"(vh0), "=r"(vh1), "=r"(vh2), "=r"(vh3) : "r"(ah));
                asm volatile(
                    "ldmatrix.sync.aligned.m8n8.x4.trans.shared.b16 {%0,%1,%2,%3}, [%4];"
                    : "=r"(vl0), "=r"(vl1), "=r"(vl2), "=r"(vl3) : "r"(al));
                mma16816(sO[2 * ndp],     pah[0], pah[1], pah[2], pah[3], vh0, vh1);
                mma16816(sO[2 * ndp],     pah[0], pah[1], pah[2], pah[3], vl0, vl1);
                mma16816(sO[2 * ndp],     pal[0], pal[1], pal[2], pal[3], vh0, vh1);
                mma16816(sO[2 * ndp + 1], pah[0], pah[1], pah[2], pah[3], vh2, vh3);
                mma16816(sO[2 * ndp + 1], pah[0], pah[1], pah[2], pah[3], vl2, vl3);
                mma16816(sO[2 * ndp + 1], pal[0], pal[1], pal[2], pal[3], vh2, vh3);
            }
        }
    }

    // ---- epilogue: O/l -> g_att (token order)
    float iA = 1.0f / lA, iB = 1.0f / lB;
    int rA = i0 + warp * 16 + qr;
    int tokA = tok_index(rg, rA);
    int tokB = tok_index(rg, rA + 8);
#pragma unroll
    for (int nd = 0; nd < 8; nd++) {
        int c = h * HD + nd * 8 + q2;
        float2 oa, ob;
        oa.x = sO[nd][0] * iA; oa.y = sO[nd][1] * iA;
        ob.x = sO[nd][2] * iB; ob.y = sO[nd][3] * iB;
        *(float2*)(g_att + (size_t)tokA * DIMC + c) = oa;
        *(float2*)(g_att + (size_t)tokB * DIMC + c) = ob;
    }
}

// ---------------------------------------------------------------------------
extern "C" void kernel_launch(void* const* d_in, const int* in_sizes, int n_in,
                              void* d_out, int out_size) {
    const float* x      = (const float*)d_in[0];
    const float* qkv_w  = (const float*)d_in[1];
    const float* qkv_b  = (const float*)d_in[2];
    const float* proj_w = (const float*)d_in[3];
    const float* proj_b = (const float*)d_in[4];
    const float* epeg_w = (const float*)d_in[5];
    float* out = (float*)d_out;

    float* qkv_buf = nullptr;
    float* att_buf = nullptr;
    cudaGetSymbolAddress((void**)&qkv_buf, g_qkv);
    cudaGetSymbolAddress((void**)&att_buf, g_att);

    cudaFuncSetAttribute(gemm_mma_kernel,
                         cudaFuncAttributeMaxDynamicSharedMemorySize,
                         GEMM_SMEM_BYTES);
    cudaFuncSetAttribute(region_attn_mma_kernel,
                         cudaFuncAttributeMaxDynamicSharedMemorySize,
                         ATT_SMEM_BYTES);

    // qkv = x @ qkv_w^T + qkv_b
    gemm_mma_kernel<<<dim3(QKVC / 128, LTOK / 128), 256, GEMM_SMEM_BYTES>>>(
        x, qkv_w, qkv_b, qkv_buf, LTOK, QKVC, DIMC);

    // flash region attention (conv folded into Q')
    region_attn_mma_kernel<<<dim3(8, NH, 16), 256, ATT_SMEM_BYTES>>>(epeg_w);

    // out = att @ proj_w^T + proj_b
    gemm_mma_kernel<<<dim3(DIMC / 128, LTOK / 128), 256, GEMM_SMEM_BYTES>>>(
        att_buf, proj_w, proj_b, out, LTOK, DIMC, DIMC);
}

// round 9
// speedup vs baseline: 2.5668x; 1.0493x over previous
#include <cuda_runtime.h>
#include <cuda_bf16.h>
#include <cstdint>

// ---------------------------------------------------------------------------
// RegionAttention R9:
//  - dense GEMMs: mma.sync bf16 hi/lo 3-term, NOW double-buffered smem with
//    register prefetch (LDG of chunk k+1 in flight under MMAs of chunk k).
//  - attention: unchanged from R8 (flash mma.sync, conv folded into Q').
// ---------------------------------------------------------------------------

#define LTOK   16384
#define DIMC   512
#define QKVC   1536
#define NH     8
#define HD     64
#define NREG   1024
#define SCALE_Q 0.125f

__device__ float g_qkv[LTOK * QKVC];   // (l, 3*512): q +0, k +512, v +1024
__device__ float g_att[LTOK * DIMC];   // attention output in token order

__device__ __forceinline__ int tok_index(int rg, int n) {
    return ((rg >> 2) << 12) | ((n >> 5) << 7) | ((rg & 3) << 5) | (n & 31);
}

__device__ __forceinline__ uint32_t smem_u32(const void* p) {
    uint32_t a;
    asm("{ .reg .u64 t; cvta.to.shared.u64 t, %1; cvt.u32.u64 %0, t; }"
        : "=r"(a) : "l"(p));
    return a;
}

__device__ __forceinline__ void mma16816(float c[4],
                                         uint32_t a0, uint32_t a1,
                                         uint32_t a2, uint32_t a3,
                                         uint32_t b0, uint32_t b1) {
    asm volatile(
        "mma.sync.aligned.m16n8k16.row.col.f32.bf16.bf16.f32 "
        "{%0,%1,%2,%3}, {%4,%5,%6,%7}, {%8,%9}, {%0,%1,%2,%3};"
        : "+f"(c[0]), "+f"(c[1]), "+f"(c[2]), "+f"(c[3])
        : "r"(a0), "r"(a1), "r"(a2), "r"(a3), "r"(b0), "r"(b1));
}

__device__ __forceinline__ void split2(float x, float y, uint32_t& hi, uint32_t& lo) {
    __nv_bfloat162 h = __floats2bfloat162_rn(x, y);
    __nv_bfloat162 l = __floats2bfloat162_rn(x - __low2float(h), y - __high2float(h));
    hi = *(uint32_t*)&h;
    lo = *(uint32_t*)&l;
}

// ===========================================================================
// mma.sync bf16 GEMM, double-buffered: C = A @ W^T + bias, hi/lo 3-term.
// CTA tile 128x128, K-chunk 64, 256 threads = 8 warps (2m x 4n), warp 64x32.
// ===========================================================================
#define GSTRIDE 72
#define GOFF_AHI 0
#define GOFF_ALO (128 * GSTRIDE)
#define GOFF_WHI (2 * 128 * GSTRIDE)
#define GOFF_WLO (3 * 128 * GSTRIDE)
#define GBUF (4 * 128 * GSTRIDE)                 // bf16 elems per buffer
#define GEMM_SMEM_BYTES (2 * GBUF * 2)           // 147456

__device__ __forceinline__ void gemm_ldg_chunk(
    const float* __restrict__ Ab, const float* __restrict__ Wb, int K,
    int lr, int lc, float4* a, float4* w)
{
#pragma unroll
    for (int it = 0; it < 8; it++) {
        int r = it * 16 + lr;
        a[it] = *(const float4*)(Ab + (size_t)r * K + lc);
        w[it] = *(const float4*)(Wb + (size_t)r * K + lc);
    }
}

__device__ __forceinline__ void gemm_sts_chunk(
    __nv_bfloat16* sb, int lr, int lc, const float4* a, const float4* w)
{
#pragma unroll
    for (int it = 0; it < 8; it++) {
        int r = it * 16 + lr;
        int base = r * GSTRIDE + lc;
        uint2 hv, lv;
        split2(a[it].x, a[it].y, hv.x, lv.x);
        split2(a[it].z, a[it].w, hv.y, lv.y);
        *(uint2*)(sb + GOFF_AHI + base) = hv;
        *(uint2*)(sb + GOFF_ALO + base) = lv;
        split2(w[it].x, w[it].y, hv.x, lv.x);
        split2(w[it].z, w[it].w, hv.y, lv.y);
        *(uint2*)(sb + GOFF_WHI + base) = hv;
        *(uint2*)(sb + GOFF_WLO + base) = lv;
    }
}

__global__ __launch_bounds__(256) void gemm_mma_kernel(
    const float* __restrict__ A, const float* __restrict__ W,
    const float* __restrict__ bias, float* __restrict__ C,
    int M, int N, int K)
{
    extern __shared__ char smc[];
    __nv_bfloat16* sb0 = (__nv_bfloat16*)smc;

    const int tid  = threadIdx.x;
    const int m0   = blockIdx.y << 7;
    const int n0   = blockIdx.x << 7;
    const int wid  = tid >> 5;
    const int lane = tid & 31;
    const int wm   = wid & 1;
    const int wn   = wid >> 1;

    const int lr = tid >> 4;
    const int lc = (tid & 15) << 2;

    const int qrow = lane >> 2;
    const int qk2  = (lane & 3) << 1;

    float acc[4][4][4];
#pragma unroll
    for (int i = 0; i < 4; i++)
#pragma unroll
        for (int j = 0; j < 4; j++)
#pragma unroll
            for (int c = 0; c < 4; c++) acc[i][j][c] = 0.f;

    const float* Abase = A + (size_t)m0 * K;
    const float* Wbase = W + (size_t)n0 * K;

    const int nchunks = K >> 6;
    float4 pa[8], pw[8];

    // prologue: stage chunk 0
    gemm_ldg_chunk(Abase, Wbase, K, lr, lc, pa, pw);
    gemm_sts_chunk(sb0, lr, lc, pa, pw);
    __syncthreads();

    for (int kc = 0; kc < nchunks; kc++) {
        const int cur = kc & 1;
        __nv_bfloat16* sb = sb0 + cur * GBUF;
        const bool have_next = (kc + 1) < nchunks;

        // issue next chunk's loads (in flight under the MMAs below)
        if (have_next)
            gemm_ldg_chunk(Abase + ((kc + 1) << 6), Wbase + ((kc + 1) << 6),
                           K, lr, lc, pa, pw);

#pragma unroll
        for (int ks = 0; ks < 4; ks++) {
            const int kb = ks * 16 + qk2;
            uint32_t a[4][4], bh[4][2], bl[4][2];

#pragma unroll
            for (int i = 0; i < 4; i++) {
                int r0 = wm * 64 + i * 16 + qrow;
                a[i][0] = *(const uint32_t*)(sb + GOFF_AHI + r0 * GSTRIDE + kb);
                a[i][1] = *(const uint32_t*)(sb + GOFF_AHI + (r0 + 8) * GSTRIDE + kb);
                a[i][2] = *(const uint32_t*)(sb + GOFF_AHI + r0 * GSTRIDE + kb + 8);
                a[i][3] = *(const uint32_t*)(sb + GOFF_AHI + (r0 + 8) * GSTRIDE + kb + 8);
            }
#pragma unroll
            for (int j = 0; j < 4; j++) {
                int nr = wn * 32 + j * 8 + qrow;
                bh[j][0] = *(const uint32_t*)(sb + GOFF_WHI + nr * GSTRIDE + kb);
                bh[j][1] = *(const uint32_t*)(sb + GOFF_WHI + nr * GSTRIDE + kb + 8);
            }
#pragma unroll
            for (int i = 0; i < 4; i++)
#pragma unroll
                for (int j = 0; j < 4; j++)
                    mma16816(acc[i][j], a[i][0], a[i][1], a[i][2], a[i][3],
                             bh[j][0], bh[j][1]);

#pragma unroll
            for (int j = 0; j < 4; j++) {
                int nr = wn * 32 + j * 8 + qrow;
                bl[j][0] = *(const uint32_t*)(sb + GOFF_WLO + nr * GSTRIDE + kb);
                bl[j][1] = *(const uint32_t*)(sb + GOFF_WLO + nr * GSTRIDE + kb + 8);
            }
#pragma unroll
            for (int i = 0; i < 4; i++)
#pragma unroll
                for (int j = 0; j < 4; j++)
                    mma16816(acc[i][j], a[i][0], a[i][1], a[i][2], a[i][3],
                             bl[j][0], bl[j][1]);

#pragma unroll
            for (int i = 0; i < 4; i++) {
                int r0 = wm * 64 + i * 16 + qrow;
                a[i][0] = *(const uint32_t*)(sb + GOFF_ALO + r0 * GSTRIDE + kb);
                a[i][1] = *(const uint32_t*)(sb + GOFF_ALO + (r0 + 8) * GSTRIDE + kb);
                a[i][2] = *(const uint32_t*)(sb + GOFF_ALO + r0 * GSTRIDE + kb + 8);
                a[i][3] = *(const uint32_t*)(sb + GOFF_ALO + (r0 + 8) * GSTRIDE + kb + 8);
            }
#pragma unroll
            for (int i = 0; i < 4; i++)
#pragma unroll
                for (int j = 0; j < 4; j++)
                    mma16816(acc[i][j], a[i][0], a[i][1], a[i][2], a[i][3],
                             bh[j][0], bh[j][1]);
        }

        // split/store next chunk into alternate buffer (MMA readers on cur)
        if (have_next)
            gemm_sts_chunk(sb0 + (cur ^ 1) * GBUF, lr, lc, pa, pw);
        __syncthreads();
    }

#pragma unroll
    for (int i = 0; i < 4; i++) {
        int gr = m0 + wm * 64 + i * 16 + qrow;
#pragma unroll
        for (int j = 0; j < 4; j++) {
            int gc = n0 + wn * 32 + j * 8 + qk2;
            float2 bv = *(const float2*)(bias + gc);
            float2 o0, o1;
            o0.x = acc[i][j][0] + bv.x; o0.y = acc[i][j][1] + bv.y;
            o1.x = acc[i][j][2] + bv.x; o1.y = acc[i][j][3] + bv.y;
            *(float2*)(C + (size_t)gr * N + gc)       = o0;
            *(float2*)(C + (size_t)(gr + 8) * N + gc) = o1;
        }
    }
}

// ===========================================================================
// Flash attention on mma.sync (unchanged from R8), conv folded into Q'.
// ===========================================================================
#define AQH 0
#define AQL (128 * 72)
#define AKH (2 * 128 * 72)
#define AKL (3 * 128 * 72)
#define AVH (4 * 128 * 72)
#define AVL (5 * 128 * 72)
#define ATT_SMEM_BYTES (6 * 128 * 72 * 2)   // 110592

__global__ __launch_bounds__(256) void region_attn_mma_kernel(
    const float* __restrict__ epeg_w)
{
    extern __shared__ char smc[];
    __nv_bfloat16* sb = (__nv_bfloat16*)smc;
    const uint32_t sbu = smem_u32(smc);

    const int tid  = threadIdx.x;
    const int it   = blockIdx.x;
    const int h    = blockIdx.y;
    const int rg   = blockIdx.z;
    const int i0   = it << 7;

    const int warp = tid >> 5;
    const int lane = tid & 31;
    const int qr   = lane >> 2;
    const int q2   = (lane & 3) << 1;

    const float w0 = epeg_w[h * 5 + 0];
    const float w1 = epeg_w[h * 5 + 1];
    const float w2 = epeg_w[h * 5 + 2];
    const float w3 = epeg_w[h * 5 + 3];
    const float w4 = epeg_w[h * 5 + 4];

    float* Qf = (float*)(smc + AKH * 2);   // [132][68] fp32 staging
    for (int idx = tid; idx < 132 * 64; idx += 256) {
        int p = idx >> 6, d = idx & 63;
        int ii = i0 - 2 + p;
        float v = 0.f;
        if (ii >= 0 && ii < NREG)
            v = g_qkv[(size_t)tok_index(rg, ii) * QKVC + h * HD + d];
        Qf[p * 68 + d] = v;
    }
    __syncthreads();

    for (int idx = tid; idx < 128 * 64; idx += 256) {
        int i = idx >> 6, d = idx & 63;
        const float* col = Qf + i * 68 + d;
        float v = col[2 * 68]
                + w0 * col[0] + w1 * col[68] + w2 * col[2 * 68]
                + w3 * col[3 * 68] + w4 * col[4 * 68];
        v *= SCALE_Q;
        __nv_bfloat16 hi = __float2bfloat16(v);
        __nv_bfloat16 lo = __float2bfloat16(v - __bfloat162float(hi));
        sb[AQH + i * 72 + d] = hi;
        sb[AQL + i * 72 + d] = lo;
    }
    __syncthreads();

    uint32_t aQh[4][4], aQl[4][4];
    {
        int r0 = warp * 16;
#pragma unroll
        for (int ks = 0; ks < 4; ks++) {
            int kb = ks * 16 + q2;
            aQh[ks][0] = *(const uint32_t*)(sb + AQH + (r0 + qr) * 72 + kb);
            aQh[ks][1] = *(const uint32_t*)(sb + AQH + (r0 + qr + 8) * 72 + kb);
            aQh[ks][2] = *(const uint32_t*)(sb + AQH + (r0 + qr) * 72 + kb + 8);
            aQh[ks][3] = *(const uint32_t*)(sb + AQH + (r0 + qr + 8) * 72 + kb + 8);
            aQl[ks][0] = *(const uint32_t*)(sb + AQL + (r0 + qr) * 72 + kb);
            aQl[ks][1] = *(const uint32_t*)(sb + AQL + (r0 + qr + 8) * 72 + kb);
            aQl[ks][2] = *(const uint32_t*)(sb + AQL + (r0 + qr) * 72 + kb + 8);
            aQl[ks][3] = *(const uint32_t*)(sb + AQL + (r0 + qr + 8) * 72 + kb + 8);
        }
    }

    float sO[8][4];
#pragma unroll
    for (int i = 0; i < 8; i++)
#pragma unroll
        for (int c = 0; c < 4; c++) sO[i][c] = 0.f;
    float mA = -1e30f, mB = -1e30f, lA = 0.f, lB = 0.f;

    for (int jt = 0; jt < 8; jt++) {
        if (jt) __syncthreads();

#pragma unroll
        for (int s = 0; s < 8; s++) {
            int idx = tid + s * 256;
            int j = idx >> 4, c4 = (idx & 15) << 2;
            const float* base =
                g_qkv + (size_t)tok_index(rg, (jt << 7) + j) * QKVC + h * HD + c4;
            float4 k4 = *(const float4*)(base + 512);
            float4 v4 = *(const float4*)(base + 1024);
            uint2 hv, lv;
            split2(k4.x, k4.y, hv.x, lv.x);
            split2(k4.z, k4.w, hv.y, lv.y);
            *(uint2*)(sb + AKH + j * 72 + c4) = hv;
            *(uint2*)(sb + AKL + j * 72 + c4) = lv;
            split2(v4.x, v4.y, hv.x, lv.x);
            split2(v4.z, v4.w, hv.y, lv.y);
            *(uint2*)(sb + AVH + j * 72 + c4) = hv;
            *(uint2*)(sb + AVL + j * 72 + c4) = lv;
        }
        __syncthreads();

        float s[16][4];
#pragma unroll
        for (int nj = 0; nj < 16; nj++)
#pragma unroll
            for (int c = 0; c < 4; c++) s[nj][c] = 0.f;

#pragma unroll
        for (int ks = 0; ks < 4; ks++) {
            int kb = ks * 16 + q2;
#pragma unroll
            for (int nj = 0; nj < 16; nj++) {
                int nr = nj * 8 + qr;
                uint32_t bh0 = *(const uint32_t*)(sb + AKH + nr * 72 + kb);
                uint32_t bh1 = *(const uint32_t*)(sb + AKH + nr * 72 + kb + 8);
                uint32_t bl0 = *(const uint32_t*)(sb + AKL + nr * 72 + kb);
                uint32_t bl1 = *(const uint32_t*)(sb + AKL + nr * 72 + kb + 8);
                mma16816(s[nj], aQh[ks][0], aQh[ks][1], aQh[ks][2], aQh[ks][3], bh0, bh1);
                mma16816(s[nj], aQh[ks][0], aQh[ks][1], aQh[ks][2], aQh[ks][3], bl0, bl1);
                mma16816(s[nj], aQl[ks][0], aQl[ks][1], aQl[ks][2], aQl[ks][3], bh0, bh1);
            }
        }

        float mtA = -1e30f, mtB = -1e30f;
#pragma unroll
        for (int nj = 0; nj < 16; nj++) {
            mtA = fmaxf(mtA, fmaxf(s[nj][0], s[nj][1]));
            mtB = fmaxf(mtB, fmaxf(s[nj][2], s[nj][3]));
        }
        mtA = fmaxf(mtA, __shfl_xor_sync(0xffffffffu, mtA, 1));
        mtA = fmaxf(mtA, __shfl_xor_sync(0xffffffffu, mtA, 2));
        mtB = fmaxf(mtB, __shfl_xor_sync(0xffffffffu, mtB, 1));
        mtB = fmaxf(mtB, __shfl_xor_sync(0xffffffffu, mtB, 2));
        float mnA = fmaxf(mA, mtA), mnB = fmaxf(mB, mtB);
        float alA = __expf(mA - mnA), alB = __expf(mB - mnB);
        mA = mnA; mB = mnB;

        float rsA = 0.f, rsB = 0.f;
#pragma unroll
        for (int nj = 0; nj < 16; nj++) {
            s[nj][0] = __expf(s[nj][0] - mnA);
            s[nj][1] = __expf(s[nj][1] - mnA);
            s[nj][2] = __expf(s[nj][2] - mnB);
            s[nj][3] = __expf(s[nj][3] - mnB);
            rsA += s[nj][0] + s[nj][1];
            rsB += s[nj][2] + s[nj][3];
        }
        rsA += __shfl_xor_sync(0xffffffffu, rsA, 1);
        rsA += __shfl_xor_sync(0xffffffffu, rsA, 2);
        rsB += __shfl_xor_sync(0xffffffffu, rsB, 1);
        rsB += __shfl_xor_sync(0xffffffffu, rsB, 2);
        lA = lA * alA + rsA;
        lB = lB * alB + rsB;

#pragma unroll
        for (int nd = 0; nd < 8; nd++) {
            sO[nd][0] *= alA; sO[nd][1] *= alA;
            sO[nd][2] *= alB; sO[nd][3] *= alB;
        }

#pragma unroll
        for (int kk = 0; kk < 8; kk++) {
            uint32_t pah[4], pal[4];
            split2(s[2 * kk][0],     s[2 * kk][1],     pah[0], pal[0]);
            split2(s[2 * kk][2],     s[2 * kk][3],     pah[1], pal[1]);
            split2(s[2 * kk + 1][0], s[2 * kk + 1][1], pah[2], pal[2]);
            split2(s[2 * kk + 1][2], s[2 * kk + 1][3], pah[3], pal[3]);
            int j0 = kk * 16;
            int vrow = j0 + (lane & 15);
            int vcol = (lane >> 4) << 3;
#pragma unroll
            for (int ndp = 0; ndp < 4; ndp++) {
                int d0 = ndp * 16;
                uint32_t vh0, vh1, vh2, vh3, vl0, vl1, vl2, vl3;
                uint32_t ah = sbu + (uint32_t)(AVH + vrow * 72 + d0 + vcol) * 2u;
                uint32_t al = sbu + (uint32_t)(AVL + vrow * 72 + d0 + vcol) * 2u;
                asm volatile(
                    "ldmatrix.sync.aligned.m8n8.x4.trans.shared.b16 {%0,%1,%2,%3}, [%4];"
                    : "=r"(vh0), "=r"(vh1), "=r"(vh2), "=r"(vh3) : "r"(ah));
                asm volatile(
                    "ldmatrix.sync.aligned.m8n8.x4.trans.shared.b16 {%0,%1,%2,%3}, [%4];"
                    : "=r"(vl0), "=r"(vl1), "=r"(vl2), "=r"(vl3) : "r"(al));
                mma16816(sO[2 * ndp],     pah[0], pah[1], pah[2], pah[3], vh0, vh1);
                mma16816(sO[2 * ndp],     pah[0], pah[1], pah[2], pah[3], vl0, vl1);
                mma16816(sO[2 * ndp],     pal[0], pal[1], pal[2], pal[3], vh0, vh1);
                mma16816(sO[2 * ndp + 1], pah[0], pah[1], pah[2], pah[3], vh2, vh3);
                mma16816(sO[2 * ndp + 1], pah[0], pah[1], pah[2], pah[3], vl2, vl3);
                mma16816(sO[2 * ndp + 1], pal[0], pal[1], pal[2], pal[3], vh2, vh3);
            }
        }
    }

    float iA = 1.0f / lA, iB = 1.0f / lB;
    int rA = i0 + warp * 16 + qr;
    int tokA = tok_index(rg, rA);
    int tokB = tok_index(rg, rA + 8);
#pragma unroll
    for (int nd = 0; nd < 8; nd++) {
        int c = h * HD + nd * 8 + q2;
        float2 oa, ob;
        oa.x = sO[nd][0] * iA; oa.y = sO[nd][1] * iA;
        ob.x = sO[nd][2] * iB; ob.y = sO[nd][3] * iB;
        *(float2*)(g_att + (size_t)tokA * DIMC + c) = oa;
        *(float2*)(g_att + (size_t)tokB * DIMC + c) = ob;
    }
}

// ---------------------------------------------------------------------------
extern "C" void kernel_launch(void* const* d_in, const int* in_sizes, int n_in,
                              void* d_out, int out_size) {
    const float* x      = (const float*)d_in[0];
    const float* qkv_w  = (const float*)d_in[1];
    const float* qkv_b  = (const float*)d_in[2];
    const float* proj_w = (const float*)d_in[3];
    const float* proj_b = (const float*)d_in[4];
    const float* epeg_w = (const float*)d_in[5];
    float* out = (float*)d_out;

    float* qkv_buf = nullptr;
    float* att_buf = nullptr;
    cudaGetSymbolAddress((void**)&qkv_buf, g_qkv);
    cudaGetSymbolAddress((void**)&att_buf, g_att);

    cudaFuncSetAttribute(gemm_mma_kernel,
                         cudaFuncAttributeMaxDynamicSharedMemorySize,
                         GEMM_SMEM_BYTES);
    cudaFuncSetAttribute(region_attn_mma_kernel,
                         cudaFuncAttributeMaxDynamicSharedMemorySize,
                         ATT_SMEM_BYTES);

    // qkv = x @ qkv_w^T + qkv_b
    gemm_mma_kernel<<<dim3(QKVC / 128, LTOK / 128), 256, GEMM_SMEM_BYTES>>>(
        x, qkv_w, qkv_b, qkv_buf, LTOK, QKVC, DIMC);

    // flash region attention (conv folded into Q')
    region_attn_mma_kernel<<<dim3(8, NH, 16), 256, ATT_SMEM_BYTES>>>(epeg_w);

    // out = att @ proj_w^T + proj_b
    gemm_mma_kernel<<<dim3(DIMC / 128, LTOK / 128), 256, GEMM_SMEM_BYTES>>>(
        att_buf, proj_w, proj_b, out, LTOK, DIMC, DIMC);
}

// round 10
// speedup vs baseline: 2.7273x; 1.0625x over previous
#include <cuda_runtime.h>
#include <cuda_bf16.h>
#include <cstdint>

// ---------------------------------------------------------------------------
// RegionAttention R10:
//  - dense GEMMs: mma.sync bf16 hi/lo 3-term, single-buffered smem (73.7KB),
//    __launch_bounds__(256,2) -> 2 CTAs/SM; cross-CTA phase interleave hides
//    the load/convert phase under the other CTA's MMAs.
//  - attention: unchanged from R8/R9 (flash mma.sync, conv folded into Q').
// ---------------------------------------------------------------------------

#define LTOK   16384
#define DIMC   512
#define QKVC   1536
#define NH     8
#define HD     64
#define NREG   1024
#define SCALE_Q 0.125f

__device__ float g_qkv[LTOK * QKVC];   // (l, 3*512): q +0, k +512, v +1024
__device__ float g_att[LTOK * DIMC];   // attention output in token order

__device__ __forceinline__ int tok_index(int rg, int n) {
    return ((rg >> 2) << 12) | ((n >> 5) << 7) | ((rg & 3) << 5) | (n & 31);
}

__device__ __forceinline__ uint32_t smem_u32(const void* p) {
    uint32_t a;
    asm("{ .reg .u64 t; cvta.to.shared.u64 t, %1; cvt.u32.u64 %0, t; }"
        : "=r"(a) : "l"(p));
    return a;
}

__device__ __forceinline__ void mma16816(float c[4],
                                         uint32_t a0, uint32_t a1,
                                         uint32_t a2, uint32_t a3,
                                         uint32_t b0, uint32_t b1) {
    asm volatile(
        "mma.sync.aligned.m16n8k16.row.col.f32.bf16.bf16.f32 "
        "{%0,%1,%2,%3}, {%4,%5,%6,%7}, {%8,%9}, {%0,%1,%2,%3};"
        : "+f"(c[0]), "+f"(c[1]), "+f"(c[2]), "+f"(c[3])
        : "r"(a0), "r"(a1), "r"(a2), "r"(a3), "r"(b0), "r"(b1));
}

__device__ __forceinline__ void split2(float x, float y, uint32_t& hi, uint32_t& lo) {
    __nv_bfloat162 h = __floats2bfloat162_rn(x, y);
    __nv_bfloat162 l = __floats2bfloat162_rn(x - __low2float(h), y - __high2float(h));
    hi = *(uint32_t*)&h;
    lo = *(uint32_t*)&l;
}

// ===========================================================================
// mma.sync bf16 GEMM, single-buffer, 2 CTAs/SM: C = A @ W^T + bias, 3-term.
// CTA tile 128x128, K-chunk 64, 256 threads = 8 warps (2m x 4n), warp 64x32.
// ===========================================================================
#define GSTRIDE 72
#define GOFF_AHI 0
#define GOFF_ALO (128 * GSTRIDE)
#define GOFF_WHI (2 * 128 * GSTRIDE)
#define GOFF_WLO (3 * 128 * GSTRIDE)
#define GEMM_SMEM_BYTES (4 * 128 * GSTRIDE * 2)   // 73728

__global__ __launch_bounds__(256, 2) void gemm_mma_kernel(
    const float* __restrict__ A, const float* __restrict__ W,
    const float* __restrict__ bias, float* __restrict__ C,
    int M, int N, int K)
{
    extern __shared__ char smc[];
    __nv_bfloat16* sb = (__nv_bfloat16*)smc;

    const int tid  = threadIdx.x;
    const int m0   = blockIdx.y << 7;
    const int n0   = blockIdx.x << 7;
    const int wid  = tid >> 5;
    const int lane = tid & 31;
    const int wm   = wid & 1;
    const int wn   = wid >> 1;

    const int lr = tid >> 4;
    const int lc = (tid & 15) << 2;

    const int qrow = lane >> 2;
    const int qk2  = (lane & 3) << 1;

    float acc[4][4][4];
#pragma unroll
    for (int i = 0; i < 4; i++)
#pragma unroll
        for (int j = 0; j < 4; j++)
#pragma unroll
            for (int c = 0; c < 4; c++) acc[i][j][c] = 0.f;

    const int nchunks = K >> 6;
    for (int kc = 0; kc < nchunks; kc++) {
        const int k0 = kc << 6;
        const float* Ab = A + (size_t)m0 * K + k0;
        const float* Wb = W + (size_t)n0 * K + k0;

        if (kc > 0) __syncthreads();

#pragma unroll
        for (int it = 0; it < 8; it++) {
            int r = it * 16 + lr;
            float4 a4 = *(const float4*)(Ab + (size_t)r * K + lc);
            float4 w4 = *(const float4*)(Wb + (size_t)r * K + lc);
            int base = r * GSTRIDE + lc;
            uint2 hv, lv;
            split2(a4.x, a4.y, hv.x, lv.x);
            split2(a4.z, a4.w, hv.y, lv.y);
            *(uint2*)(sb + GOFF_AHI + base) = hv;
            *(uint2*)(sb + GOFF_ALO + base) = lv;
            split2(w4.x, w4.y, hv.x, lv.x);
            split2(w4.z, w4.w, hv.y, lv.y);
            *(uint2*)(sb + GOFF_WHI + base) = hv;
            *(uint2*)(sb + GOFF_WLO + base) = lv;
        }
        __syncthreads();

#pragma unroll
        for (int ks = 0; ks < 4; ks++) {
            const int kb = ks * 16 + qk2;
            uint32_t a[4][4], bh[4][2], bl[4][2];

#pragma unroll
            for (int i = 0; i < 4; i++) {
                int r0 = wm * 64 + i * 16 + qrow;
                a[i][0] = *(const uint32_t*)(sb + GOFF_AHI + r0 * GSTRIDE + kb);
                a[i][1] = *(const uint32_t*)(sb + GOFF_AHI + (r0 + 8) * GSTRIDE + kb);
                a[i][2] = *(const uint32_t*)(sb + GOFF_AHI + r0 * GSTRIDE + kb + 8);
                a[i][3] = *(const uint32_t*)(sb + GOFF_AHI + (r0 + 8) * GSTRIDE + kb + 8);
            }
#pragma unroll
            for (int j = 0; j < 4; j++) {
                int nr = wn * 32 + j * 8 + qrow;
                bh[j][0] = *(const uint32_t*)(sb + GOFF_WHI + nr * GSTRIDE + kb);
                bh[j][1] = *(const uint32_t*)(sb + GOFF_WHI + nr * GSTRIDE + kb + 8);
            }
#pragma unroll
            for (int i = 0; i < 4; i++)
#pragma unroll
                for (int j = 0; j < 4; j++)
                    mma16816(acc[i][j], a[i][0], a[i][1], a[i][2], a[i][3],
                             bh[j][0], bh[j][1]);

#pragma unroll
            for (int j = 0; j < 4; j++) {
                int nr = wn * 32 + j * 8 + qrow;
                bl[j][0] = *(const uint32_t*)(sb + GOFF_WLO + nr * GSTRIDE + kb);
                bl[j][1] = *(const uint32_t*)(sb + GOFF_WLO + nr * GSTRIDE + kb + 8);
            }
#pragma unroll
            for (int i = 0; i < 4; i++)
#pragma unroll
                for (int j = 0; j < 4; j++)
                    mma16816(acc[i][j], a[i][0], a[i][1], a[i][2], a[i][3],
                             bl[j][0], bl[j][1]);

#pragma unroll
            for (int i = 0; i < 4; i++) {
                int r0 = wm * 64 + i * 16 + qrow;
                a[i][0] = *(const uint32_t*)(sb + GOFF_ALO + r0 * GSTRIDE + kb);
                a[i][1] = *(const uint32_t*)(sb + GOFF_ALO + (r0 + 8) * GSTRIDE + kb);
                a[i][2] = *(const uint32_t*)(sb + GOFF_ALO + r0 * GSTRIDE + kb + 8);
                a[i][3] = *(const uint32_t*)(sb + GOFF_ALO + (r0 + 8) * GSTRIDE + kb + 8);
            }
#pragma unroll
            for (int i = 0; i < 4; i++)
#pragma unroll
                for (int j = 0; j < 4; j++)
                    mma16816(acc[i][j], a[i][0], a[i][1], a[i][2], a[i][3],
                             bh[j][0], bh[j][1]);
        }
    }

#pragma unroll
    for (int i = 0; i < 4; i++) {
        int gr = m0 + wm * 64 + i * 16 + qrow;
#pragma unroll
        for (int j = 0; j < 4; j++) {
            int gc = n0 + wn * 32 + j * 8 + qk2;
            float2 bv = *(const float2*)(bias + gc);
            float2 o0, o1;
            o0.x = acc[i][j][0] + bv.x; o0.y = acc[i][j][1] + bv.y;
            o1.x = acc[i][j][2] + bv.x; o1.y = acc[i][j][3] + bv.y;
            *(float2*)(C + (size_t)gr * N + gc)       = o0;
            *(float2*)(C + (size_t)(gr + 8) * N + gc) = o1;
        }
    }
}

// ===========================================================================
// Flash attention on mma.sync (unchanged), conv folded into Q'.
// ===========================================================================
#define AQH 0
#define AQL (128 * 72)
#define AKH (2 * 128 * 72)
#define AKL (3 * 128 * 72)
#define AVH (4 * 128 * 72)
#define AVL (5 * 128 * 72)
#define ATT_SMEM_BYTES (6 * 128 * 72 * 2)   // 110592

__global__ __launch_bounds__(256) void region_attn_mma_kernel(
    const float* __restrict__ epeg_w)
{
    extern __shared__ char smc[];
    __nv_bfloat16* sb = (__nv_bfloat16*)smc;
    const uint32_t sbu = smem_u32(smc);

    const int tid  = threadIdx.x;
    const int it   = blockIdx.x;
    const int h    = blockIdx.y;
    const int rg   = blockIdx.z;
    const int i0   = it << 7;

    const int warp = tid >> 5;
    const int lane = tid & 31;
    const int qr   = lane >> 2;
    const int q2   = (lane & 3) << 1;

    const float w0 = epeg_w[h * 5 + 0];
    const float w1 = epeg_w[h * 5 + 1];
    const float w2 = epeg_w[h * 5 + 2];
    const float w3 = epeg_w[h * 5 + 3];
    const float w4 = epeg_w[h * 5 + 4];

    float* Qf = (float*)(smc + AKH * 2);   // [132][68] fp32 staging
    for (int idx = tid; idx < 132 * 64; idx += 256) {
        int p = idx >> 6, d = idx & 63;
        int ii = i0 - 2 + p;
        float v = 0.f;
        if (ii >= 0 && ii < NREG)
            v = g_qkv[(size_t)tok_index(rg, ii) * QKVC + h * HD + d];
        Qf[p * 68 + d] = v;
    }
    __syncthreads();

    for (int idx = tid; idx < 128 * 64; idx += 256) {
        int i = idx >> 6, d = idx & 63;
        const float* col = Qf + i * 68 + d;
        float v = col[2 * 68]
                + w0 * col[0] + w1 * col[68] + w2 * col[2 * 68]
                + w3 * col[3 * 68] + w4 * col[4 * 68];
        v *= SCALE_Q;
        __nv_bfloat16 hi = __float2bfloat16(v);
        __nv_bfloat16 lo = __float2bfloat16(v - __bfloat162float(hi));
        sb[AQH + i * 72 + d] = hi;
        sb[AQL + i * 72 + d] = lo;
    }
    __syncthreads();

    uint32_t aQh[4][4], aQl[4][4];
    {
        int r0 = warp * 16;
#pragma unroll
        for (int ks = 0; ks < 4; ks++) {
            int kb = ks * 16 + q2;
            aQh[ks][0] = *(const uint32_t*)(sb + AQH + (r0 + qr) * 72 + kb);
            aQh[ks][1] = *(const uint32_t*)(sb + AQH + (r0 + qr + 8) * 72 + kb);
            aQh[ks][2] = *(const uint32_t*)(sb + AQH + (r0 + qr) * 72 + kb + 8);
            aQh[ks][3] = *(const uint32_t*)(sb + AQH + (r0 + qr + 8) * 72 + kb + 8);
            aQl[ks][0] = *(const uint32_t*)(sb + AQL + (r0 + qr) * 72 + kb);
            aQl[ks][1] = *(const uint32_t*)(sb + AQL + (r0 + qr + 8) * 72 + kb);
            aQl[ks][2] = *(const uint32_t*)(sb + AQL + (r0 + qr) * 72 + kb + 8);
            aQl[ks][3] = *(const uint32_t*)(sb + AQL + (r0 + qr + 8) * 72 + kb + 8);
        }
    }

    float sO[8][4];
#pragma unroll
    for (int i = 0; i < 8; i++)
#pragma unroll
        for (int c = 0; c < 4; c++) sO[i][c] = 0.f;
    float mA = -1e30f, mB = -1e30f, lA = 0.f, lB = 0.f;

    for (int jt = 0; jt < 8; jt++) {
        if (jt) __syncthreads();

#pragma unroll
        for (int s = 0; s < 8; s++) {
            int idx = tid + s * 256;
            int j = idx >> 4, c4 = (idx & 15) << 2;
            const float* base =
                g_qkv + (size_t)tok_index(rg, (jt << 7) + j) * QKVC + h * HD + c4;
            float4 k4 = *(const float4*)(base + 512);
            float4 v4 = *(const float4*)(base + 1024);
            uint2 hv, lv;
            split2(k4.x, k4.y, hv.x, lv.x);
            split2(k4.z, k4.w, hv.y, lv.y);
            *(uint2*)(sb + AKH + j * 72 + c4) = hv;
            *(uint2*)(sb + AKL + j * 72 + c4) = lv;
            split2(v4.x, v4.y, hv.x, lv.x);
            split2(v4.z, v4.w, hv.y, lv.y);
            *(uint2*)(sb + AVH + j * 72 + c4) = hv;
            *(uint2*)(sb + AVL + j * 72 + c4) = lv;
        }
        __syncthreads();

        float s[16][4];
#pragma unroll
        for (int nj = 0; nj < 16; nj++)
#pragma unroll
            for (int c = 0; c < 4; c++) s[nj][c] = 0.f;

#pragma unroll
        for (int ks = 0; ks < 4; ks++) {
            int kb = ks * 16 + q2;
#pragma unroll
            for (int nj = 0; nj < 16; nj++) {
                int nr = nj * 8 + qr;
                uint32_t bh0 = *(const uint32_t*)(sb + AKH + nr * 72 + kb);
                uint32_t bh1 = *(const uint32_t*)(sb + AKH + nr * 72 + kb + 8);
                uint32_t bl0 = *(const uint32_t*)(sb + AKL + nr * 72 + kb);
                uint32_t bl1 = *(const uint32_t*)(sb + AKL + nr * 72 + kb + 8);
                mma16816(s[nj], aQh[ks][0], aQh[ks][1], aQh[ks][2], aQh[ks][3], bh0, bh1);
                mma16816(s[nj], aQh[ks][0], aQh[ks][1], aQh[ks][2], aQh[ks][3], bl0, bl1);
                mma16816(s[nj], aQl[ks][0], aQl[ks][1], aQl[ks][2], aQl[ks][3], bh0, bh1);
            }
        }

        float mtA = -1e30f, mtB = -1e30f;
#pragma unroll
        for (int nj = 0; nj < 16; nj++) {
            mtA = fmaxf(mtA, fmaxf(s[nj][0], s[nj][1]));
            mtB = fmaxf(mtB, fmaxf(s[nj][2], s[nj][3]));
        }
        mtA = fmaxf(mtA, __shfl_xor_sync(0xffffffffu, mtA, 1));
        mtA = fmaxf(mtA, __shfl_xor_sync(0xffffffffu, mtA, 2));
        mtB = fmaxf(mtB, __shfl_xor_sync(0xffffffffu, mtB, 1));
        mtB = fmaxf(mtB, __shfl_xor_sync(0xffffffffu, mtB, 2));
        float mnA = fmaxf(mA, mtA), mnB = fmaxf(mB, mtB);
        float alA = __expf(mA - mnA), alB = __expf(mB - mnB);
        mA = mnA; mB = mnB;

        float rsA = 0.f, rsB = 0.f;
#pragma unroll
        for (int nj = 0; nj < 16; nj++) {
            s[nj][0] = __expf(s[nj][0] - mnA);
            s[nj][1] = __expf(s[nj][1] - mnA);
            s[nj][2] = __expf(s[nj][2] - mnB);
            s[nj][3] = __expf(s[nj][3] - mnB);
            rsA += s[nj][0] + s[nj][1];
            rsB += s[nj][2] + s[nj][3];
        }
        rsA += __shfl_xor_sync(0xffffffffu, rsA, 1);
        rsA += __shfl_xor_sync(0xffffffffu, rsA, 2);
        rsB += __shfl_xor_sync(0xffffffffu, rsB, 1);
        rsB += __shfl_xor_sync(0xffffffffu, rsB, 2);
        lA = lA * alA + rsA;
        lB = lB * alB + rsB;

#pragma unroll
        for (int nd = 0; nd < 8; nd++) {
            sO[nd][0] *= alA; sO[nd][1] *= alA;
            sO[nd][2] *= alB; sO[nd][3] *= alB;
        }

#pragma unroll
        for (int kk = 0; kk < 8; kk++) {
            uint32_t pah[4], pal[4];
            split2(s[2 * kk][0],     s[2 * kk][1],     pah[0], pal[0]);
            split2(s[2 * kk][2],     s[2 * kk][3],     pah[1], pal[1]);
            split2(s[2 * kk + 1][0], s[2 * kk + 1][1], pah[2], pal[2]);
            split2(s[2 * kk + 1][2], s[2 * kk + 1][3], pah[3], pal[3]);
            int j0 = kk * 16;
            int vrow = j0 + (lane & 15);
            int vcol = (lane >> 4) << 3;
#pragma unroll
            for (int ndp = 0; ndp < 4; ndp++) {
                int d0 = ndp * 16;
                uint32_t vh0, vh1, vh2, vh3, vl0, vl1, vl2, vl3;
                uint32_t ah = sbu + (uint32_t)(AVH + vrow * 72 + d0 + vcol) * 2u;
                uint32_t al = sbu + (uint32_t)(AVL + vrow * 72 + d0 + vcol) * 2u;
                asm volatile(
                    "ldmatrix.sync.aligned.m8n8.x4.trans.shared.b16 {%0,%1,%2,%3}, [%4];"
                    : "=r"(vh0), "=r"(vh1), "=r"(vh2), "=r"(vh3) : "r"(ah));
                asm volatile(
                    "ldmatrix.sync.aligned.m8n8.x4.trans.shared.b16 {%0,%1,%2,%3}, [%4];"
                    : "=r"(vl0), "=r"(vl1), "=r"(vl2), "=r"(vl3) : "r"(al));
                mma16816(sO[2 * ndp],     pah[0], pah[1], pah[2], pah[3], vh0, vh1);
                mma16816(sO[2 * ndp],     pah[0], pah[1], pah[2], pah[3], vl0, vl1);
                mma16816(sO[2 * ndp],     pal[0], pal[1], pal[2], pal[3], vh0, vh1);
                mma16816(sO[2 * ndp + 1], pah[0], pah[1], pah[2], pah[3], vh2, vh3);
                mma16816(sO[2 * ndp + 1], pah[0], pah[1], pah[2], pah[3], vl2, vl3);
                mma16816(sO[2 * ndp + 1], pal[0], pal[1], pal[2], pal[3], vh2, vh3);
            }
        }
    }

    float iA = 1.0f / lA, iB = 1.0f / lB;
    int rA = i0 + warp * 16 + qr;
    int tokA = tok_index(rg, rA);
    int tokB = tok_index(rg, rA + 8);
#pragma unroll
    for (int nd = 0; nd < 8; nd++) {
        int c = h * HD + nd * 8 + q2;
        float2 oa, ob;
        oa.x = sO[nd][0] * iA; oa.y = sO[nd][1] * iA;
        ob.x = sO[nd][2] * iB; ob.y = sO[nd][3] * iB;
        *(float2*)(g_att + (size_t)tokA * DIMC + c) = oa;
        *(float2*)(g_att + (size_t)tokB * DIMC + c) = ob;
    }
}

// ---------------------------------------------------------------------------
extern "C" void kernel_launch(void* const* d_in, const int* in_sizes, int n_in,
                              void* d_out, int out_size) {
    const float* x      = (const float*)d_in[0];
    const float* qkv_w  = (const float*)d_in[1];
    const float* qkv_b  = (const float*)d_in[2];
    const float* proj_w = (const float*)d_in[3];
    const float* proj_b = (const float*)d_in[4];
    const float* epeg_w = (const float*)d_in[5];
    float* out = (float*)d_out;

    float* qkv_buf = nullptr;
    float* att_buf = nullptr;
    cudaGetSymbolAddress((void**)&qkv_buf, g_qkv);
    cudaGetSymbolAddress((void**)&att_buf, g_att);

    cudaFuncSetAttribute(gemm_mma_kernel,
                         cudaFuncAttributeMaxDynamicSharedMemorySize,
                         GEMM_SMEM_BYTES);
    cudaFuncSetAttribute(region_attn_mma_kernel,
                         cudaFuncAttributeMaxDynamicSharedMemorySize,
                         ATT_SMEM_BYTES);

    // qkv = x @ qkv_w^T + qkv_b
    gemm_mma_kernel<<<dim3(QKVC / 128, LTOK / 128), 256, GEMM_SMEM_BYTES>>>(
        x, qkv_w, qkv_b, qkv_buf, LTOK, QKVC, DIMC);

    // flash region attention (conv folded into Q')
    region_attn_mma_kernel<<<dim3(8, NH, 16), 256, ATT_SMEM_BYTES>>>(epeg_w);

    // out = att @ proj_w^T + proj_b
    gemm_mma_kernel<<<dim3(DIMC / 128, LTOK / 128), 256, GEMM_SMEM_BYTES>>>(
        att_buf, proj_w, proj_b, out, LTOK, DIMC, DIMC);
}

// round 11
// speedup vs baseline: 2.9882x; 1.0957x over previous
#include <cuda_runtime.h>
#include <cuda_bf16.h>
#include <cstdint>

// ---------------------------------------------------------------------------
// RegionAttention R11:
//  - dense GEMMs: unchanged from R10 (single-buffer, 2 CTAs/SM).
//  - attention: K/V j-tile 128 -> 64 keys, smem 110.6KB -> 73.7KB,
//    __launch_bounds__(256,2) -> 2 CTAs/SM (same cross-CTA interleave
//    mechanism that won R10 on the GEMM).
// ---------------------------------------------------------------------------

#define LTOK   16384
#define DIMC   512
#define QKVC   1536
#define NH     8
#define HD     64
#define NREG   1024
#define SCALE_Q 0.125f

__device__ float g_qkv[LTOK * QKVC];   // (l, 3*512): q +0, k +512, v +1024
__device__ float g_att[LTOK * DIMC];   // attention output in token order

__device__ __forceinline__ int tok_index(int rg, int n) {
    return ((rg >> 2) << 12) | ((n >> 5) << 7) | ((rg & 3) << 5) | (n & 31);
}

__device__ __forceinline__ uint32_t smem_u32(const void* p) {
    uint32_t a;
    asm("{ .reg .u64 t; cvta.to.shared.u64 t, %1; cvt.u32.u64 %0, t; }"
        : "=r"(a) : "l"(p));
    return a;
}

__device__ __forceinline__ void mma16816(float c[4],
                                         uint32_t a0, uint32_t a1,
                                         uint32_t a2, uint32_t a3,
                                         uint32_t b0, uint32_t b1) {
    asm volatile(
        "mma.sync.aligned.m16n8k16.row.col.f32.bf16.bf16.f32 "
        "{%0,%1,%2,%3}, {%4,%5,%6,%7}, {%8,%9}, {%0,%1,%2,%3};"
        : "+f"(c[0]), "+f"(c[1]), "+f"(c[2]), "+f"(c[3])
        : "r"(a0), "r"(a1), "r"(a2), "r"(a3), "r"(b0), "r"(b1));
}

__device__ __forceinline__ void split2(float x, float y, uint32_t& hi, uint32_t& lo) {
    __nv_bfloat162 h = __floats2bfloat162_rn(x, y);
    __nv_bfloat162 l = __floats2bfloat162_rn(x - __low2float(h), y - __high2float(h));
    hi = *(uint32_t*)&h;
    lo = *(uint32_t*)&l;
}

// ===========================================================================
// mma.sync bf16 GEMM (unchanged from R10): single-buffer, 2 CTAs/SM.
// ===========================================================================
#define GSTRIDE 72
#define GOFF_AHI 0
#define GOFF_ALO (128 * GSTRIDE)
#define GOFF_WHI (2 * 128 * GSTRIDE)
#define GOFF_WLO (3 * 128 * GSTRIDE)
#define GEMM_SMEM_BYTES (4 * 128 * GSTRIDE * 2)   // 73728

__global__ __launch_bounds__(256, 2) void gemm_mma_kernel(
    const float* __restrict__ A, const float* __restrict__ W,
    const float* __restrict__ bias, float* __restrict__ C,
    int M, int N, int K)
{
    extern __shared__ char smc[];
    __nv_bfloat16* sb = (__nv_bfloat16*)smc;

    const int tid  = threadIdx.x;
    const int m0   = blockIdx.y << 7;
    const int n0   = blockIdx.x << 7;
    const int wid  = tid >> 5;
    const int lane = tid & 31;
    const int wm   = wid & 1;
    const int wn   = wid >> 1;

    const int lr = tid >> 4;
    const int lc = (tid & 15) << 2;

    const int qrow = lane >> 2;
    const int qk2  = (lane & 3) << 1;

    float acc[4][4][4];
#pragma unroll
    for (int i = 0; i < 4; i++)
#pragma unroll
        for (int j = 0; j < 4; j++)
#pragma unroll
            for (int c = 0; c < 4; c++) acc[i][j][c] = 0.f;

    const int nchunks = K >> 6;
    for (int kc = 0; kc < nchunks; kc++) {
        const int k0 = kc << 6;
        const float* Ab = A + (size_t)m0 * K + k0;
        const float* Wb = W + (size_t)n0 * K + k0;

        if (kc > 0) __syncthreads();

#pragma unroll
        for (int it = 0; it < 8; it++) {
            int r = it * 16 + lr;
            float4 a4 = *(const float4*)(Ab + (size_t)r * K + lc);
            float4 w4 = *(const float4*)(Wb + (size_t)r * K + lc);
            int base = r * GSTRIDE + lc;
            uint2 hv, lv;
            split2(a4.x, a4.y, hv.x, lv.x);
            split2(a4.z, a4.w, hv.y, lv.y);
            *(uint2*)(sb + GOFF_AHI + base) = hv;
            *(uint2*)(sb + GOFF_ALO + base) = lv;
            split2(w4.x, w4.y, hv.x, lv.x);
            split2(w4.z, w4.w, hv.y, lv.y);
            *(uint2*)(sb + GOFF_WHI + base) = hv;
            *(uint2*)(sb + GOFF_WLO + base) = lv;
        }
        __syncthreads();

#pragma unroll
        for (int ks = 0; ks < 4; ks++) {
            const int kb = ks * 16 + qk2;
            uint32_t a[4][4], bh[4][2], bl[4][2];

#pragma unroll
            for (int i = 0; i < 4; i++) {
                int r0 = wm * 64 + i * 16 + qrow;
                a[i][0] = *(const uint32_t*)(sb + GOFF_AHI + r0 * GSTRIDE + kb);
                a[i][1] = *(const uint32_t*)(sb + GOFF_AHI + (r0 + 8) * GSTRIDE + kb);
                a[i][2] = *(const uint32_t*)(sb + GOFF_AHI + r0 * GSTRIDE + kb + 8);
                a[i][3] = *(const uint32_t*)(sb + GOFF_AHI + (r0 + 8) * GSTRIDE + kb + 8);
            }
#pragma unroll
            for (int j = 0; j < 4; j++) {
                int nr = wn * 32 + j * 8 + qrow;
                bh[j][0] = *(const uint32_t*)(sb + GOFF_WHI + nr * GSTRIDE + kb);
                bh[j][1] = *(const uint32_t*)(sb + GOFF_WHI + nr * GSTRIDE + kb + 8);
            }
#pragma unroll
            for (int i = 0; i < 4; i++)
#pragma unroll
                for (int j = 0; j < 4; j++)
                    mma16816(acc[i][j], a[i][0], a[i][1], a[i][2], a[i][3],
                             bh[j][0], bh[j][1]);

#pragma unroll
            for (int j = 0; j < 4; j++) {
                int nr = wn * 32 + j * 8 + qrow;
                bl[j][0] = *(const uint32_t*)(sb + GOFF_WLO + nr * GSTRIDE + kb);
                bl[j][1] = *(const uint32_t*)(sb + GOFF_WLO + nr * GSTRIDE + kb + 8);
            }
#pragma unroll
            for (int i = 0; i < 4; i++)
#pragma unroll
                for (int j = 0; j < 4; j++)
                    mma16816(acc[i][j], a[i][0], a[i][1], a[i][2], a[i][3],
                             bl[j][0], bl[j][1]);

#pragma unroll
            for (int i = 0; i < 4; i++) {
                int r0 = wm * 64 + i * 16 + qrow;
                a[i][0] = *(const uint32_t*)(sb + GOFF_ALO + r0 * GSTRIDE + kb);
                a[i][1] = *(const uint32_t*)(sb + GOFF_ALO + (r0 + 8) * GSTRIDE + kb);
                a[i][2] = *(const uint32_t*)(sb + GOFF_ALO + r0 * GSTRIDE + kb + 8);
                a[i][3] = *(const uint32_t*)(sb + GOFF_ALO + (r0 + 8) * GSTRIDE + kb + 8);
            }
#pragma unroll
            for (int i = 0; i < 4; i++)
#pragma unroll
                for (int j = 0; j < 4; j++)
                    mma16816(acc[i][j], a[i][0], a[i][1], a[i][2], a[i][3],
                             bh[j][0], bh[j][1]);
        }
    }

#pragma unroll
    for (int i = 0; i < 4; i++) {
        int gr = m0 + wm * 64 + i * 16 + qrow;
#pragma unroll
        for (int j = 0; j < 4; j++) {
            int gc = n0 + wn * 32 + j * 8 + qk2;
            float2 bv = *(const float2*)(bias + gc);
            float2 o0, o1;
            o0.x = acc[i][j][0] + bv.x; o0.y = acc[i][j][1] + bv.y;
            o1.x = acc[i][j][2] + bv.x; o1.y = acc[i][j][3] + bv.y;
            *(float2*)(C + (size_t)gr * N + gc)       = o0;
            *(float2*)(C + (size_t)(gr + 8) * N + gc) = o1;
        }
    }
}

// ===========================================================================
// Flash attention R11: 64-key j-tiles, 73.7KB smem, 2 CTAs/SM.
// grid: (row_tile 0..7 [128 rows], head 0..7, region 0..15), 256 thr, 8 warps.
// smem bf16 elems: Q'hi[128*72], Q'lo[128*72], Khi/Klo/Vhi/Vlo[64*72 each].
// ===========================================================================
#define AQH 0
#define AQL (128 * 72)
#define AKH (2 * 128 * 72)
#define AKL (AKH + 64 * 72)
#define AVH (AKH + 2 * 64 * 72)
#define AVL (AKH + 3 * 64 * 72)
#define ATT_SMEM_BYTES ((2 * 128 * 72 + 4 * 64 * 72) * 2)   // 73728

__global__ __launch_bounds__(256, 2) void region_attn_mma_kernel(
    const float* __restrict__ epeg_w)
{
    extern __shared__ char smc[];
    __nv_bfloat16* sb = (__nv_bfloat16*)smc;
    const uint32_t sbu = smem_u32(smc);

    const int tid  = threadIdx.x;
    const int it   = blockIdx.x;
    const int h    = blockIdx.y;
    const int rg   = blockIdx.z;
    const int i0   = it << 7;

    const int warp = tid >> 5;
    const int lane = tid & 31;
    const int qr   = lane >> 2;
    const int q2   = (lane & 3) << 1;

    const float w0 = epeg_w[h * 5 + 0];
    const float w1 = epeg_w[h * 5 + 1];
    const float w2 = epeg_w[h * 5 + 2];
    const float w3 = epeg_w[h * 5 + 3];
    const float w4 = epeg_w[h * 5 + 4];

    // fp32 Q staging in the K/V smem region (132*68*4 = 35904 <= 36864 B)
    float* Qf = (float*)(smc + AKH * 2);
    for (int idx = tid; idx < 132 * 64; idx += 256) {
        int p = idx >> 6, d = idx & 63;
        int ii = i0 - 2 + p;
        float v = 0.f;
        if (ii >= 0 && ii < NREG)
            v = g_qkv[(size_t)tok_index(rg, ii) * QKVC + h * HD + d];
        Qf[p * 68 + d] = v;
    }
    __syncthreads();

    for (int idx = tid; idx < 128 * 64; idx += 256) {
        int i = idx >> 6, d = idx & 63;
        const float* col = Qf + i * 68 + d;
        float v = col[2 * 68]
                + w0 * col[0] + w1 * col[68] + w2 * col[2 * 68]
                + w3 * col[3 * 68] + w4 * col[4 * 68];
        v *= SCALE_Q;
        __nv_bfloat16 hi = __float2bfloat16(v);
        __nv_bfloat16 lo = __float2bfloat16(v - __bfloat162float(hi));
        sb[AQH + i * 72 + d] = hi;
        sb[AQL + i * 72 + d] = lo;
    }
    __syncthreads();

    // persistent Q a-frags (warp rows r0..r0+15)
    uint32_t aQh[4][4], aQl[4][4];
    {
        int r0 = warp * 16;
#pragma unroll
        for (int ks = 0; ks < 4; ks++) {
            int kb = ks * 16 + q2;
            aQh[ks][0] = *(const uint32_t*)(sb + AQH + (r0 + qr) * 72 + kb);
            aQh[ks][1] = *(const uint32_t*)(sb + AQH + (r0 + qr + 8) * 72 + kb);
            aQh[ks][2] = *(const uint32_t*)(sb + AQH + (r0 + qr) * 72 + kb + 8);
            aQh[ks][3] = *(const uint32_t*)(sb + AQH + (r0 + qr + 8) * 72 + kb + 8);
            aQl[ks][0] = *(const uint32_t*)(sb + AQL + (r0 + qr) * 72 + kb);
            aQl[ks][1] = *(const uint32_t*)(sb + AQL + (r0 + qr + 8) * 72 + kb);
            aQl[ks][2] = *(const uint32_t*)(sb + AQL + (r0 + qr) * 72 + kb + 8);
            aQl[ks][3] = *(const uint32_t*)(sb + AQL + (r0 + qr + 8) * 72 + kb + 8);
        }
    }

    float sO[8][4];
#pragma unroll
    for (int i = 0; i < 8; i++)
#pragma unroll
        for (int c = 0; c < 4; c++) sO[i][c] = 0.f;
    float mA = -1e30f, mB = -1e30f, lA = 0.f, lB = 0.f;

    for (int jt = 0; jt < 16; jt++) {
        if (jt) __syncthreads();

        // ---- load K,V tile (64 tokens x 64 d), split hi/lo: 1024 slots
#pragma unroll
        for (int s = 0; s < 4; s++) {
            int idx = tid + s * 256;
            int j = idx >> 4, c4 = (idx & 15) << 2;
            const float* base =
                g_qkv + (size_t)tok_index(rg, (jt << 6) + j) * QKVC + h * HD + c4;
            float4 k4 = *(const float4*)(base + 512);
            float4 v4 = *(const float4*)(base + 1024);
            uint2 hv, lv;
            split2(k4.x, k4.y, hv.x, lv.x);
            split2(k4.z, k4.w, hv.y, lv.y);
            *(uint2*)(sb + AKH + j * 72 + c4) = hv;
            *(uint2*)(sb + AKL + j * 72 + c4) = lv;
            split2(v4.x, v4.y, hv.x, lv.x);
            split2(v4.z, v4.w, hv.y, lv.y);
            *(uint2*)(sb + AVH + j * 72 + c4) = hv;
            *(uint2*)(sb + AVL + j * 72 + c4) = lv;
        }
        __syncthreads();

        // ---- S = Q' @ K^T  (warp: 16 rows x 64 cols, 3-term)
        float s[8][4];
#pragma unroll
        for (int nj = 0; nj < 8; nj++)
#pragma unroll
            for (int c = 0; c < 4; c++) s[nj][c] = 0.f;

#pragma unroll
        for (int ks = 0; ks < 4; ks++) {
            int kb = ks * 16 + q2;
#pragma unroll
            for (int nj = 0; nj < 8; nj++) {
                int nr = nj * 8 + qr;
                uint32_t bh0 = *(const uint32_t*)(sb + AKH + nr * 72 + kb);
                uint32_t bh1 = *(const uint32_t*)(sb + AKH + nr * 72 + kb + 8);
                uint32_t bl0 = *(const uint32_t*)(sb + AKL + nr * 72 + kb);
                uint32_t bl1 = *(const uint32_t*)(sb + AKL + nr * 72 + kb + 8);
                mma16816(s[nj], aQh[ks][0], aQh[ks][1], aQh[ks][2], aQh[ks][3], bh0, bh1);
                mma16816(s[nj], aQh[ks][0], aQh[ks][1], aQh[ks][2], aQh[ks][3], bl0, bl1);
                mma16816(s[nj], aQl[ks][0], aQl[ks][1], aQl[ks][2], aQl[ks][3], bh0, bh1);
            }
        }

        // ---- register online softmax (rows A=qr, B=qr+8)
        float mtA = -1e30f, mtB = -1e30f;
#pragma unroll
        for (int nj = 0; nj < 8; nj++) {
            mtA = fmaxf(mtA, fmaxf(s[nj][0], s[nj][1]));
            mtB = fmaxf(mtB, fmaxf(s[nj][2], s[nj][3]));
        }
        mtA = fmaxf(mtA, __shfl_xor_sync(0xffffffffu, mtA, 1));
        mtA = fmaxf(mtA, __shfl_xor_sync(0xffffffffu, mtA, 2));
        mtB = fmaxf(mtB, __shfl_xor_sync(0xffffffffu, mtB, 1));
        mtB = fmaxf(mtB, __shfl_xor_sync(0xffffffffu, mtB, 2));
        float mnA = fmaxf(mA, mtA), mnB = fmaxf(mB, mtB);
        float alA = __expf(mA - mnA), alB = __expf(mB - mnB);
        mA = mnA; mB = mnB;

        float rsA = 0.f, rsB = 0.f;
#pragma unroll
        for (int nj = 0; nj < 8; nj++) {
            s[nj][0] = __expf(s[nj][0] - mnA);
            s[nj][1] = __expf(s[nj][1] - mnA);
            s[nj][2] = __expf(s[nj][2] - mnB);
            s[nj][3] = __expf(s[nj][3] - mnB);
            rsA += s[nj][0] + s[nj][1];
            rsB += s[nj][2] + s[nj][3];
        }
        rsA += __shfl_xor_sync(0xffffffffu, rsA, 1);
        rsA += __shfl_xor_sync(0xffffffffu, rsA, 2);
        rsB += __shfl_xor_sync(0xffffffffu, rsB, 1);
        rsB += __shfl_xor_sync(0xffffffffu, rsB, 2);
        lA = lA * alA + rsA;
        lB = lB * alB + rsB;

#pragma unroll
        for (int nd = 0; nd < 8; nd++) {
            sO[nd][0] *= alA; sO[nd][1] *= alA;
            sO[nd][2] *= alB; sO[nd][3] *= alB;
        }

        // ---- O += P @ V  (4 k-steps of 16 keys)
#pragma unroll
        for (int kk = 0; kk < 4; kk++) {
            uint32_t pah[4], pal[4];
            split2(s[2 * kk][0],     s[2 * kk][1],     pah[0], pal[0]);
            split2(s[2 * kk][2],     s[2 * kk][3],     pah[1], pal[1]);
            split2(s[2 * kk + 1][0], s[2 * kk + 1][1], pah[2], pal[2]);
            split2(s[2 * kk + 1][2], s[2 * kk + 1][3], pah[3], pal[3]);
            int j0 = kk * 16;
            int vrow = j0 + (lane & 15);
            int vcol = (lane >> 4) << 3;
#pragma unroll
            for (int ndp = 0; ndp < 4; ndp++) {
                int d0 = ndp * 16;
                uint32_t vh0, vh1, vh2, vh3, vl0, vl1, vl2, vl3;
                uint32_t ah = sbu + (uint32_t)(AVH + vrow * 72 + d0 + vcol) * 2u;
                uint32_t al = sbu + (uint32_t)(AVL + vrow * 72 + d0 + vcol) * 2u;
                asm volatile(
                    "ldmatrix.sync.aligned.m8n8.x4.trans.shared.b16 {%0,%1,%2,%3}, [%4];"
                    : "=r"(vh0), "=r"(vh1), "=r"(vh2), "=r"(vh3) : "r"(ah));
                asm volatile(
                    "ldmatrix.sync.aligned.m8n8.x4.trans.shared.b16 {%0,%1,%2,%3}, [%4];"
                    : "=r"(vl0), "=r"(vl1), "=r"(vl2), "=r"(vl3) : "r"(al));
                mma16816(sO[2 * ndp],     pah[0], pah[1], pah[2], pah[3], vh0, vh1);
                mma16816(sO[2 * ndp],     pah[0], pah[1], pah[2], pah[3], vl0, vl1);
                mma16816(sO[2 * ndp],     pal[0], pal[1], pal[2], pal[3], vh0, vh1);
                mma16816(sO[2 * ndp + 1], pah[0], pah[1], pah[2], pah[3], vh2, vh3);
                mma16816(sO[2 * ndp + 1], pah[0], pah[1], pah[2], pah[3], vl2, vl3);
                mma16816(sO[2 * ndp + 1], pal[0], pal[1], pal[2], pal[3], vh2, vh3);
            }
        }
    }

    // ---- epilogue: O/l -> g_att (token order)
    float iA = 1.0f / lA, iB = 1.0f / lB;
    int rA = i0 + warp * 16 + qr;
    int tokA = tok_index(rg, rA);
    int tokB = tok_index(rg, rA + 8);
#pragma unroll
    for (int nd = 0; nd < 8; nd++) {
        int c = h * HD + nd * 8 + q2;
        float2 oa, ob;
        oa.x = sO[nd][0] * iA; oa.y = sO[nd][1] * iA;
        ob.x = sO[nd][2] * iB; ob.y = sO[nd][3] * iB;
        *(float2*)(g_att + (size_t)tokA * DIMC + c) = oa;
        *(float2*)(g_att + (size_t)tokB * DIMC + c) = ob;
    }
}

// ---------------------------------------------------------------------------
extern "C" void kernel_launch(void* const* d_in, const int* in_sizes, int n_in,
                              void* d_out, int out_size) {
    const float* x      = (const float*)d_in[0];
    const float* qkv_w  = (const float*)d_in[1];
    const float* qkv_b  = (const float*)d_in[2];
    const float* proj_w = (const float*)d_in[3];
    const float* proj_b = (const float*)d_in[4];
    const float* epeg_w = (const float*)d_in[5];
    float* out = (float*)d_out;

    float* qkv_buf = nullptr;
    float* att_buf = nullptr;
    cudaGetSymbolAddress((void**)&qkv_buf, g_qkv);
    cudaGetSymbolAddress((void**)&att_buf, g_att);

    cudaFuncSetAttribute(gemm_mma_kernel,
                         cudaFuncAttributeMaxDynamicSharedMemorySize,
                         GEMM_SMEM_BYTES);
    cudaFuncSetAttribute(region_attn_mma_kernel,
                         cudaFuncAttributeMaxDynamicSharedMemorySize,
                         ATT_SMEM_BYTES);

    // qkv = x @ qkv_w^T + qkv_b
    gemm_mma_kernel<<<dim3(QKVC / 128, LTOK / 128), 256, GEMM_SMEM_BYTES>>>(
        x, qkv_w, qkv_b, qkv_buf, LTOK, QKVC, DIMC);

    // flash region attention (conv folded into Q')
    region_attn_mma_kernel<<<dim3(8, NH, 16), 256, ATT_SMEM_BYTES>>>(epeg_w);

    // out = att @ proj_w^T + proj_b
    gemm_mma_kernel<<<dim3(DIMC / 128, LTOK / 128), 256, GEMM_SMEM_BYTES>>>(
        att_buf, proj_w, proj_b, out, LTOK, DIMC, DIMC);
}

// round 12
// speedup vs baseline: 2.9958x; 1.0025x over previous
#include <cuda_runtime.h>
#include <cuda_bf16.h>
#include <cstdint>

// ---------------------------------------------------------------------------
// RegionAttention R12:
//  - QKV GEMM epilogue now writes q as fp32 (g_q) and k/v pre-split into
//    bf16 hi/lo (g_kv[tok][head][khi|klo|vhi|vlo][64]).
//  - attention: K/V tiles fetched with cp.async.cg into a double buffer that
//    ping-pongs with the dead Q' smem region (73.7KB total, 2 CTAs/SM kept);
//    load+convert phase removed from the critical path.
//  - proj GEMM unchanged.
// ---------------------------------------------------------------------------

#define LTOK   16384
#define DIMC   512
#define QKVC   1536
#define NH     8
#define HD     64
#define NREG   1024
#define SCALE_Q 0.125f

__device__ float g_q[LTOK * DIMC];                 // q, fp32, bias applied
__device__ __nv_bfloat16 g_kv[LTOK * 2048];        // [tok][head][4][64]: khi,klo,vhi,vlo
__device__ float g_att[LTOK * DIMC];               // attention output, token order

__device__ __forceinline__ int tok_index(int rg, int n) {
    return ((rg >> 2) << 12) | ((n >> 5) << 7) | ((rg & 3) << 5) | (n & 31);
}

__device__ __forceinline__ uint32_t smem_u32(const void* p) {
    uint32_t a;
    asm("{ .reg .u64 t; cvta.to.shared.u64 t, %1; cvt.u32.u64 %0, t; }"
        : "=r"(a) : "l"(p));
    return a;
}

__device__ __forceinline__ void mma16816(float c[4],
                                         uint32_t a0, uint32_t a1,
                                         uint32_t a2, uint32_t a3,
                                         uint32_t b0, uint32_t b1) {
    asm volatile(
        "mma.sync.aligned.m16n8k16.row.col.f32.bf16.bf16.f32 "
        "{%0,%1,%2,%3}, {%4,%5,%6,%7}, {%8,%9}, {%0,%1,%2,%3};"
        : "+f"(c[0]), "+f"(c[1]), "+f"(c[2]), "+f"(c[3])
        : "r"(a0), "r"(a1), "r"(a2), "r"(a3), "r"(b0), "r"(b1));
}

__device__ __forceinline__ void split2(float x, float y, uint32_t& hi, uint32_t& lo) {
    __nv_bfloat162 h = __floats2bfloat162_rn(x, y);
    __nv_bfloat162 l = __floats2bfloat162_rn(x - __low2float(h), y - __high2float(h));
    hi = *(uint32_t*)&h;
    lo = *(uint32_t*)&l;
}

#define CP_ASYNC16(dst, src) \
    asm volatile("cp.async.cg.shared.global [%0], [%1], 16;" \
                 :: "r"(dst), "l"(src) : "memory")
#define CP_COMMIT() asm volatile("cp.async.commit_group;" ::: "memory")
#define CP_WAIT0()  asm volatile("cp.async.wait_group 0;" ::: "memory")

// ===========================================================================
// mma.sync bf16 GEMM, single-buffer, 2 CTAs/SM. C = A @ W^T + bias.
// If KV != nullptr (QKV gemm): cols [0,512) -> fp32 C (stride 512),
// cols [512,1536) -> bf16 hi/lo split into KV. Else plain fp32 C (stride N).
// ===========================================================================
#define GSTRIDE 72
#define GOFF_AHI 0
#define GOFF_ALO (128 * GSTRIDE)
#define GOFF_WHI (2 * 128 * GSTRIDE)
#define GOFF_WLO (3 * 128 * GSTRIDE)
#define GEMM_SMEM_BYTES (4 * 128 * GSTRIDE * 2)   // 73728

__global__ __launch_bounds__(256, 2) void gemm_mma_kernel(
    const float* __restrict__ A, const float* __restrict__ W,
    const float* __restrict__ bias, float* __restrict__ C,
    __nv_bfloat16* __restrict__ KV,
    int M, int N, int K)
{
    extern __shared__ char smc[];
    __nv_bfloat16* sb = (__nv_bfloat16*)smc;

    const int tid  = threadIdx.x;
    const int m0   = blockIdx.y << 7;
    const int n0   = blockIdx.x << 7;
    const int wid  = tid >> 5;
    const int lane = tid & 31;
    const int wm   = wid & 1;
    const int wn   = wid >> 1;

    const int lr = tid >> 4;
    const int lc = (tid & 15) << 2;

    const int qrow = lane >> 2;
    const int qk2  = (lane & 3) << 1;

    float acc[4][4][4];
#pragma unroll
    for (int i = 0; i < 4; i++)
#pragma unroll
        for (int j = 0; j < 4; j++)
#pragma unroll
            for (int c = 0; c < 4; c++) acc[i][j][c] = 0.f;

    const int nchunks = K >> 6;
    for (int kc = 0; kc < nchunks; kc++) {
        const int k0 = kc << 6;
        const float* Ab = A + (size_t)m0 * K + k0;
        const float* Wb = W + (size_t)n0 * K + k0;

        if (kc > 0) __syncthreads();

#pragma unroll
        for (int it = 0; it < 8; it++) {
            int r = it * 16 + lr;
            float4 a4 = *(const float4*)(Ab + (size_t)r * K + lc);
            float4 w4 = *(const float4*)(Wb + (size_t)r * K + lc);
            int base = r * GSTRIDE + lc;
            uint2 hv, lv;
            split2(a4.x, a4.y, hv.x, lv.x);
            split2(a4.z, a4.w, hv.y, lv.y);
            *(uint2*)(sb + GOFF_AHI + base) = hv;
            *(uint2*)(sb + GOFF_ALO + base) = lv;
            split2(w4.x, w4.y, hv.x, lv.x);
            split2(w4.z, w4.w, hv.y, lv.y);
            *(uint2*)(sb + GOFF_WHI + base) = hv;
            *(uint2*)(sb + GOFF_WLO + base) = lv;
        }
        __syncthreads();

#pragma unroll
        for (int ks = 0; ks < 4; ks++) {
            const int kb = ks * 16 + qk2;
            uint32_t a[4][4], bh[4][2], bl[4][2];

#pragma unroll
            for (int i = 0; i < 4; i++) {
                int r0 = wm * 64 + i * 16 + qrow;
                a[i][0] = *(const uint32_t*)(sb + GOFF_AHI + r0 * GSTRIDE + kb);
                a[i][1] = *(const uint32_t*)(sb + GOFF_AHI + (r0 + 8) * GSTRIDE + kb);
                a[i][2] = *(const uint32_t*)(sb + GOFF_AHI + r0 * GSTRIDE + kb + 8);
                a[i][3] = *(const uint32_t*)(sb + GOFF_AHI + (r0 + 8) * GSTRIDE + kb + 8);
            }
#pragma unroll
            for (int j = 0; j < 4; j++) {
                int nr = wn * 32 + j * 8 + qrow;
                bh[j][0] = *(const uint32_t*)(sb + GOFF_WHI + nr * GSTRIDE + kb);
                bh[j][1] = *(const uint32_t*)(sb + GOFF_WHI + nr * GSTRIDE + kb + 8);
            }
#pragma unroll
            for (int i = 0; i < 4; i++)
#pragma unroll
                for (int j = 0; j < 4; j++)
                    mma16816(acc[i][j], a[i][0], a[i][1], a[i][2], a[i][3],
                             bh[j][0], bh[j][1]);

#pragma unroll
            for (int j = 0; j < 4; j++) {
                int nr = wn * 32 + j * 8 + qrow;
                bl[j][0] = *(const uint32_t*)(sb + GOFF_WLO + nr * GSTRIDE + kb);
                bl[j][1] = *(const uint32_t*)(sb + GOFF_WLO + nr * GSTRIDE + kb + 8);
            }
#pragma unroll
            for (int i = 0; i < 4; i++)
#pragma unroll
                for (int j = 0; j < 4; j++)
                    mma16816(acc[i][j], a[i][0], a[i][1], a[i][2], a[i][3],
                             bl[j][0], bl[j][1]);

#pragma unroll
            for (int i = 0; i < 4; i++) {
                int r0 = wm * 64 + i * 16 + qrow;
                a[i][0] = *(const uint32_t*)(sb + GOFF_ALO + r0 * GSTRIDE + kb);
                a[i][1] = *(const uint32_t*)(sb + GOFF_ALO + (r0 + 8) * GSTRIDE + kb);
                a[i][2] = *(const uint32_t*)(sb + GOFF_ALO + r0 * GSTRIDE + kb + 8);
                a[i][3] = *(const uint32_t*)(sb + GOFF_ALO + (r0 + 8) * GSTRIDE + kb + 8);
            }
#pragma unroll
            for (int i = 0; i < 4; i++)
#pragma unroll
                for (int j = 0; j < 4; j++)
                    mma16816(acc[i][j], a[i][0], a[i][1], a[i][2], a[i][3],
                             bh[j][0], bh[j][1]);
        }
    }

    // ---- epilogue
#pragma unroll
    for (int i = 0; i < 4; i++) {
        int gr = m0 + wm * 64 + i * 16 + qrow;
#pragma unroll
        for (int j = 0; j < 4; j++) {
            int gc = n0 + wn * 32 + j * 8 + qk2;
            float2 bv = *(const float2*)(bias + gc);
            float v00 = acc[i][j][0] + bv.x, v01 = acc[i][j][1] + bv.y;  // row gr
            float v10 = acc[i][j][2] + bv.x, v11 = acc[i][j][3] + bv.y;  // row gr+8
            if (KV == nullptr) {
                *(float2*)(C + (size_t)gr * N + gc)       = make_float2(v00, v01);
                *(float2*)(C + (size_t)(gr + 8) * N + gc) = make_float2(v10, v11);
            } else if (gc < 512) {
                *(float2*)(C + (size_t)gr * 512 + gc)       = make_float2(v00, v01);
                *(float2*)(C + (size_t)(gr + 8) * 512 + gc) = make_float2(v10, v11);
            } else {
                int isV  = gc >= 1024;
                int xx   = gc - (isV ? 1024 : 512);
                int head = xx >> 6, d = xx & 63;
                int arrh = isV ? 2 : 0;
                uint32_t hi, lo;
                __nv_bfloat16* p0 = KV + (size_t)gr * 2048 + head * 256 + d;
                split2(v00, v01, hi, lo);
                *(uint32_t*)(p0 + arrh * 64)       = hi;
                *(uint32_t*)(p0 + (arrh + 1) * 64) = lo;
                __nv_bfloat16* p1 = KV + (size_t)(gr + 8) * 2048 + head * 256 + d;
                split2(v10, v11, hi, lo);
                *(uint32_t*)(p1 + arrh * 64)       = hi;
                *(uint32_t*)(p1 + (arrh + 1) * 64) = lo;
            }
        }
    }
}

// ===========================================================================
// Flash attention R12: 64-key j-tiles, cp.async double buffer in 73.7KB,
// 2 CTAs/SM. grid: (row_tile 0..7, head 0..7, region 0..15), 256 thr.
// smem: region A [0,18432) bf16 = Q'hi/lo then K/V buf1;
//       region B [18432,36864) = fp32 Q staging then K/V buf0.
// In-buffer: KHI +0, KLO +4608, VHI +9216, VLO +13824 (bf16 elems, stride 72).
// ===========================================================================
#define REGA 0
#define REGB 18432
#define BKH 0
#define BKL 4608
#define BVH 9216
#define BVL 13824
#define ATT_SMEM_BYTES (36864 * 2)   // 73728

__device__ __forceinline__ void attn_cp_tile(
    uint32_t sbu, int bufoff, const __nv_bfloat16* __restrict__ gkv,
    int rg, int h, int jt, int tid)
{
    const int t0  = tid >> 5;          // 0..7
    const int arr = (tid >> 3) & 3;    // 0..3
    const int c   = tid & 7;           // 0..7 (16B chunk)
    const int jb  = jt << 6;
#pragma unroll
    for (int s = 0; s < 8; s++) {
        int tok = t0 + s * 8;
        const char* src = (const char*)(gkv
            + (size_t)tok_index(rg, jb + tok) * 2048 + h * 256) + arr * 128 + c * 16;
        uint32_t dst = sbu + (uint32_t)(bufoff + arr * 4608 + tok * 72) * 2u + c * 16;
        CP_ASYNC16(dst, src);
    }
}

__global__ __launch_bounds__(256, 2) void region_attn_mma_kernel(
    const float* __restrict__ epeg_w)
{
    extern __shared__ char smc[];
    __nv_bfloat16* sb = (__nv_bfloat16*)smc;
    const uint32_t sbu = smem_u32(smc);

    const int tid  = threadIdx.x;
    const int it   = blockIdx.x;
    const int h    = blockIdx.y;
    const int rg   = blockIdx.z;
    const int i0   = it << 7;

    const int warp = tid >> 5;
    const int lane = tid & 31;
    const int qr   = lane >> 2;
    const int q2   = (lane & 3) << 1;

    const float w0 = epeg_w[h * 5 + 0];
    const float w1 = epeg_w[h * 5 + 1];
    const float w2 = epeg_w[h * 5 + 2];
    const float w3 = epeg_w[h * 5 + 3];
    const float w4 = epeg_w[h * 5 + 4];

    // ---- stage fp32 Q rows i0-2..i0+129 into region B
    float* Qf = (float*)(smc + REGB * 2);   // [132][68] fp32 (35904 B)
    for (int idx = tid; idx < 132 * 64; idx += 256) {
        int p = idx >> 6, d = idx & 63;
        int ii = i0 - 2 + p;
        float v = 0.f;
        if (ii >= 0 && ii < NREG)
            v = g_q[(size_t)tok_index(rg, ii) * DIMC + h * HD + d];
        Qf[p * 68 + d] = v;
    }
    __syncthreads();

    // ---- Q' = SCALE*(q + conv5(q)) -> bf16 hi/lo into region A
    for (int idx = tid; idx < 128 * 64; idx += 256) {
        int i = idx >> 6, d = idx & 63;
        const float* col = Qf + i * 68 + d;
        float v = col[2 * 68]
                + w0 * col[0] + w1 * col[68] + w2 * col[2 * 68]
                + w3 * col[3 * 68] + w4 * col[4 * 68];
        v *= SCALE_Q;
        __nv_bfloat16 hi = __float2bfloat16(v);
        __nv_bfloat16 lo = __float2bfloat16(v - __bfloat162float(hi));
        sb[REGA + i * 72 + d]            = hi;
        sb[REGA + 128 * 72 + i * 72 + d] = lo;
    }
    __syncthreads();   // region B (Qf) now dead

    // ---- issue tile 0 cp.async into region B (buf0); overlap with frag preload
    attn_cp_tile(sbu, REGB, g_kv, rg, h, 0, tid);
    CP_COMMIT();

    // persistent Q a-frags from region A
    uint32_t aQh[4][4], aQl[4][4];
    {
        int r0 = warp * 16;
#pragma unroll
        for (int ks = 0; ks < 4; ks++) {
            int kb = ks * 16 + q2;
            aQh[ks][0] = *(const uint32_t*)(sb + REGA + (r0 + qr) * 72 + kb);
            aQh[ks][1] = *(const uint32_t*)(sb + REGA + (r0 + qr + 8) * 72 + kb);
            aQh[ks][2] = *(const uint32_t*)(sb + REGA + (r0 + qr) * 72 + kb + 8);
            aQh[ks][3] = *(const uint32_t*)(sb + REGA + (r0 + qr + 8) * 72 + kb + 8);
            aQl[ks][0] = *(const uint32_t*)(sb + REGA + 9216 + (r0 + qr) * 72 + kb);
            aQl[ks][1] = *(const uint32_t*)(sb + REGA + 9216 + (r0 + qr + 8) * 72 + kb);
            aQl[ks][2] = *(const uint32_t*)(sb + REGA + 9216 + (r0 + qr) * 72 + kb + 8);
            aQl[ks][3] = *(const uint32_t*)(sb + REGA + 9216 + (r0 + qr + 8) * 72 + kb + 8);
        }
    }

    CP_WAIT0();
    __syncthreads();   // tile 0 ready; region A reads (frags) complete

    float sO[8][4];
#pragma unroll
    for (int i = 0; i < 8; i++)
#pragma unroll
        for (int c = 0; c < 4; c++) sO[i][c] = 0.f;
    float mA = -1e30f, mB = -1e30f, lA = 0.f, lB = 0.f;

    for (int jt = 0; jt < 16; jt++) {
        const int buf  = (jt & 1) ? REGA : REGB;
        // issue next tile into the other buffer
        if (jt + 1 < 16)
            attn_cp_tile(sbu, (jt & 1) ? REGB : REGA, g_kv, rg, h, jt + 1, tid);
        CP_COMMIT();

        // ---- S = Q' @ K^T  (warp: 16 rows x 64 cols, 3-term)
        float s[8][4];
#pragma unroll
        for (int nj = 0; nj < 8; nj++)
#pragma unroll
            for (int c = 0; c < 4; c++) s[nj][c] = 0.f;

#pragma unroll
        for (int ks = 0; ks < 4; ks++) {
            int kb = ks * 16 + q2;
#pragma unroll
            for (int nj = 0; nj < 8; nj++) {
                int nr = nj * 8 + qr;
                uint32_t bh0 = *(const uint32_t*)(sb + buf + BKH + nr * 72 + kb);
                uint32_t bh1 = *(const uint32_t*)(sb + buf + BKH + nr * 72 + kb + 8);
                uint32_t bl0 = *(const uint32_t*)(sb + buf + BKL + nr * 72 + kb);
                uint32_t bl1 = *(const uint32_t*)(sb + buf + BKL + nr * 72 + kb + 8);
                mma16816(s[nj], aQh[ks][0], aQh[ks][1], aQh[ks][2], aQh[ks][3], bh0, bh1);
                mma16816(s[nj], aQh[ks][0], aQh[ks][1], aQh[ks][2], aQh[ks][3], bl0, bl1);
                mma16816(s[nj], aQl[ks][0], aQl[ks][1], aQl[ks][2], aQl[ks][3], bh0, bh1);
            }
        }

        // ---- register online softmax (rows A=qr, B=qr+8)
        float mtA = -1e30f, mtB = -1e30f;
#pragma unroll
        for (int nj = 0; nj < 8; nj++) {
            mtA = fmaxf(mtA, fmaxf(s[nj][0], s[nj][1]));
            mtB = fmaxf(mtB, fmaxf(s[nj][2], s[nj][3]));
        }
        mtA = fmaxf(mtA, __shfl_xor_sync(0xffffffffu, mtA, 1));
        mtA = fmaxf(mtA, __shfl_xor_sync(0xffffffffu, mtA, 2));
        mtB = fmaxf(mtB, __shfl_xor_sync(0xffffffffu, mtB, 1));
        mtB = fmaxf(mtB, __shfl_xor_sync(0xffffffffu, mtB, 2));
        float mnA = fmaxf(mA, mtA), mnB = fmaxf(mB, mtB);
        float alA = __expf(mA - mnA), alB = __expf(mB - mnB);
        mA = mnA; mB = mnB;

        float rsA = 0.f, rsB = 0.f;
#pragma unroll
        for (int nj = 0; nj < 8; nj++) {
            s[nj][0] = __expf(s[nj][0] - mnA);
            s[nj][1] = __expf(s[nj][1] - mnA);
            s[nj][2] = __expf(s[nj][2] - mnB);
            s[nj][3] = __expf(s[nj][3] - mnB);
            rsA += s[nj][0] + s[nj][1];
            rsB += s[nj][2] + s[nj][3];
        }
        rsA += __shfl_xor_sync(0xffffffffu, rsA, 1);
        rsA += __shfl_xor_sync(0xffffffffu, rsA, 2);
        rsB += __shfl_xor_sync(0xffffffffu, rsB, 1);
        rsB += __shfl_xor_sync(0xffffffffu, rsB, 2);
        lA = lA * alA + rsA;
        lB = lB * alB + rsB;

#pragma unroll
        for (int nd = 0; nd < 8; nd++) {
            sO[nd][0] *= alA; sO[nd][1] *= alA;
            sO[nd][2] *= alB; sO[nd][3] *= alB;
        }

        // ---- O += P @ V
#pragma unroll
        for (int kk = 0; kk < 4; kk++) {
            uint32_t pah[4], pal[4];
            split2(s[2 * kk][0],     s[2 * kk][1],     pah[0], pal[0]);
            split2(s[2 * kk][2],     s[2 * kk][3],     pah[1], pal[1]);
            split2(s[2 * kk + 1][0], s[2 * kk + 1][1], pah[2], pal[2]);
            split2(s[2 * kk + 1][2], s[2 * kk + 1][3], pah[3], pal[3]);
            int j0 = kk * 16;
            int vrow = j0 + (lane & 15);
            int vcol = (lane >> 4) << 3;
#pragma unroll
            for (int ndp = 0; ndp < 4; ndp++) {
                int d0 = ndp * 16;
                uint32_t vh0, vh1, vh2, vh3, vl0, vl1, vl2, vl3;
                uint32_t ah = sbu + (uint32_t)(buf + BVH + vrow * 72 + d0 + vcol) * 2u;
                uint32_t al = sbu + (uint32_t)(buf + BVL + vrow * 72 + d0 + vcol) * 2u;
                asm volatile(
                    "ldmatrix.sync.aligned.m8n8.x4.trans.shared.b16 {%0,%1,%2,%3}, [%4];"
                    : "=r"(vh0), "=r"(vh1), "=r"(vh2), "=r"(vh3) : "r"(ah));
                asm volatile(
                    "ldmatrix.sync.aligned.m8n8.x4.trans.shared.b16 {%0,%1,%2,%3}, [%4];"
                    : "=r"(vl0), "=r"(vl1), "=r"(vl2), "=r"(vl3) : "r"(al));
                mma16816(sO[2 * ndp],     pah[0], pah[1], pah[2], pah[3], vh0, vh1);
                mma16816(sO[2 * ndp],     pah[0], pah[1], pah[2], pah[3], vl0, vl1);
                mma16816(sO[2 * ndp],     pal[0], pal[1], pal[2], pal[3], vh0, vh1);
                mma16816(sO[2 * ndp + 1], pah[0], pah[1], pah[2], pah[3], vh2, vh3);
                mma16816(sO[2 * ndp + 1], pah[0], pah[1], pah[2], pah[3], vl2, vl3);
                mma16816(sO[2 * ndp + 1], pal[0], pal[1], pal[2], pal[3], vh2, vh3);
            }
        }

        CP_WAIT0();
        __syncthreads();   // next tile resident; current buffer free to overwrite
    }

    // ---- epilogue: O/l -> g_att (token order)
    float iA = 1.0f / lA, iB = 1.0f / lB;
    int rA = i0 + warp * 16 + qr;
    int tokA = tok_index(rg, rA);
    int tokB = tok_index(rg, rA + 8);
#pragma unroll
    for (int nd = 0; nd < 8; nd++) {
        int c = h * HD + nd * 8 + q2;
        float2 oa, ob;
        oa.x = sO[nd][0] * iA; oa.y = sO[nd][1] * iA;
        ob.x = sO[nd][2] * iB; ob.y = sO[nd][3] * iB;
        *(float2*)(g_att + (size_t)tokA * DIMC + c) = oa;
        *(float2*)(g_att + (size_t)tokB * DIMC + c) = ob;
    }
}

// ---------------------------------------------------------------------------
extern "C" void kernel_launch(void* const* d_in, const int* in_sizes, int n_in,
                              void* d_out, int out_size) {
    const float* x      = (const float*)d_in[0];
    const float* qkv_w  = (const float*)d_in[1];
    const float* qkv_b  = (const float*)d_in[2];
    const float* proj_w = (const float*)d_in[3];
    const float* proj_b = (const float*)d_in[4];
    const float* epeg_w = (const float*)d_in[5];
    float* out = (float*)d_out;

    float* q_buf = nullptr;
    __nv_bfloat16* kv_buf = nullptr;
    float* att_buf = nullptr;
    cudaGetSymbolAddress((void**)&q_buf, g_q);
    cudaGetSymbolAddress((void**)&kv_buf, g_kv);
    cudaGetSymbolAddress((void**)&att_buf, g_att);

    cudaFuncSetAttribute(gemm_mma_kernel,
                         cudaFuncAttributeMaxDynamicSharedMemorySize,
                         GEMM_SMEM_BYTES);
    cudaFuncSetAttribute(region_attn_mma_kernel,
                         cudaFuncAttributeMaxDynamicSharedMemorySize,
                         ATT_SMEM_BYTES);

    // qkv = x @ qkv_w^T + qkv_b -> g_q (fp32) + g_kv (bf16 hi/lo)
    gemm_mma_kernel<<<dim3(QKVC / 128, LTOK / 128), 256, GEMM_SMEM_BYTES>>>(
        x, qkv_w, qkv_b, q_buf, kv_buf, LTOK, QKVC, DIMC);

    // flash region attention (conv folded into Q', cp.async double buffer)
    region_attn_mma_kernel<<<dim3(8, NH, 16), 256, ATT_SMEM_BYTES>>>(epeg_w);

    // out = att @ proj_w^T + proj_b
    gemm_mma_kernel<<<dim3(DIMC / 128, LTOK / 128), 256, GEMM_SMEM_BYTES>>>(
        att_buf, proj_w, proj_b, out, nullptr, LTOK, DIMC, DIMC);
}

// round 13
// speedup vs baseline: 5.9259x; 1.9781x over previous
#include <cuda_runtime.h>
#include <cuda_fp16.h>
#include <cstdint>

// ---------------------------------------------------------------------------
// RegionAttention R13: single-term fp16 mma everywhere (was bf16 hi/lo 3-term).
// fp16 quantization error ~2.4e-4/element, predicted aggregate ~1e-4 << 1e-3.
// ldmatrix.x4 fragment loads (stride-144B rows are bank-conflict-free).
// GEMM: 128x128 tile, single smem buffer, 2 CTAs/SM.
// Attention: flash, conv folded into Q', 64-key tiles, cp.async double buffer.
// ---------------------------------------------------------------------------

#define LTOK   16384
#define DIMC   512
#define QKVC   1536
#define NH     8
#define HD     64
#define NREG   1024
#define SCALE_Q 0.125f

__device__ float  g_q[LTOK * DIMC];        // q, fp32, bias applied
__device__ __half g_kv[LTOK * 1024];       // [tok][head][k|v][64] fp16
__device__ float  g_att[LTOK * DIMC];      // attention output, token order

__device__ __forceinline__ int tok_index(int rg, int n) {
    return ((rg >> 2) << 12) | ((n >> 5) << 7) | ((rg & 3) << 5) | (n & 31);
}

__device__ __forceinline__ uint32_t smem_u32(const void* p) {
    uint32_t a;
    asm("{ .reg .u64 t; cvta.to.shared.u64 t, %1; cvt.u32.u64 %0, t; }"
        : "=r"(a) : "l"(p));
    return a;
}

__device__ __forceinline__ void mma_h(float c[4],
                                      uint32_t a0, uint32_t a1,
                                      uint32_t a2, uint32_t a3,
                                      uint32_t b0, uint32_t b1) {
    asm volatile(
        "mma.sync.aligned.m16n8k16.row.col.f32.f16.f16.f32 "
        "{%0,%1,%2,%3}, {%4,%5,%6,%7}, {%8,%9}, {%0,%1,%2,%3};"
        : "+f"(c[0]), "+f"(c[1]), "+f"(c[2]), "+f"(c[3])
        : "r"(a0), "r"(a1), "r"(a2), "r"(a3), "r"(b0), "r"(b1));
}

__device__ __forceinline__ uint32_t h2pack(float x, float y) {
    __half2 h = __floats2half2_rn(x, y);
    return *(uint32_t*)&h;
}

#define LDM_X4(r0_, r1_, r2_, r3_, addr) \
    asm volatile("ldmatrix.sync.aligned.m8n8.x4.shared.b16 {%0,%1,%2,%3}, [%4];" \
        : "=r"(r0_), "=r"(r1_), "=r"(r2_), "=r"(r3_) : "r"(addr))
#define LDM_X4_T(r0_, r1_, r2_, r3_, addr) \
    asm volatile("ldmatrix.sync.aligned.m8n8.x4.trans.shared.b16 {%0,%1,%2,%3}, [%4];" \
        : "=r"(r0_), "=r"(r1_), "=r"(r2_), "=r"(r3_) : "r"(addr))

#define CP_ASYNC16(dst, src) \
    asm volatile("cp.async.cg.shared.global [%0], [%1], 16;" \
                 :: "r"(dst), "l"(src) : "memory")
#define CP_COMMIT() asm volatile("cp.async.commit_group;" ::: "memory")
#define CP_WAIT0()  asm volatile("cp.async.wait_group 0;" ::: "memory")

// ===========================================================================
// fp16 single-term GEMM: C = A @ W^T + bias. Tile 128x128, K-chunk 64,
// 256 threads = 8 warps (2m x 4n), warp 64x32. 2 CTAs/SM.
// If KV != nullptr (QKV gemm): cols [0,512) -> fp32 C (stride 512),
// cols [512,1536) -> fp16 into KV. Else fp32 C (stride N).
// ===========================================================================
#define GSTRIDE 72                       // fp16 elems per row
#define GOFF_W  (128 * GSTRIDE)
#define GEMM_SMEM_BYTES (2 * 128 * GSTRIDE * 2)   // 36864

__global__ __launch_bounds__(256, 2) void gemm_mma_kernel(
    const float* __restrict__ A, const float* __restrict__ W,
    const float* __restrict__ bias, float* __restrict__ C,
    __half* __restrict__ KV,
    int M, int N, int K)
{
    extern __shared__ char smc[];
    __half* sb = (__half*)smc;
    const uint32_t sbu = smem_u32(smc);

    const int tid  = threadIdx.x;
    const int m0   = blockIdx.y << 7;
    const int n0   = blockIdx.x << 7;
    const int wid  = tid >> 5;
    const int lane = tid & 31;
    const int wm   = wid & 1;
    const int wn   = wid >> 1;

    const int lr = tid >> 4;
    const int lc = (tid & 15) << 2;

    const int qrow = lane >> 2;
    const int qk2  = (lane & 3) << 1;

    const int lml = lane & 15;           // ldmatrix row lane
    const int lmc = (lane >> 4) << 3;    // ldmatrix col half (0/8)

    float acc[4][4][4];
#pragma unroll
    for (int i = 0; i < 4; i++)
#pragma unroll
        for (int j = 0; j < 4; j++)
#pragma unroll
            for (int c = 0; c < 4; c++) acc[i][j][c] = 0.f;

    const int nchunks = K >> 6;
    for (int kc = 0; kc < nchunks; kc++) {
        const int k0 = kc << 6;
        const float* Ab = A + (size_t)m0 * K + k0;
        const float* Wb = W + (size_t)n0 * K + k0;

        if (kc > 0) __syncthreads();

#pragma unroll
        for (int it = 0; it < 8; it++) {
            int r = it * 16 + lr;
            float4 a4 = *(const float4*)(Ab + (size_t)r * K + lc);
            float4 w4 = *(const float4*)(Wb + (size_t)r * K + lc);
            uint2 av, wv;
            av.x = h2pack(a4.x, a4.y); av.y = h2pack(a4.z, a4.w);
            wv.x = h2pack(w4.x, w4.y); wv.y = h2pack(w4.z, w4.w);
            *(uint2*)(sb + r * GSTRIDE + lc)          = av;
            *(uint2*)(sb + GOFF_W + r * GSTRIDE + lc) = wv;
        }
        __syncthreads();

#pragma unroll
        for (int ks = 0; ks < 4; ks++) {
            const int co = ks * 16 + lmc;
            uint32_t a[4][4], b[2][4];
#pragma unroll
            for (int i = 0; i < 4; i++) {
                uint32_t ad = sbu +
                    (uint32_t)((wm * 64 + i * 16 + lml) * GSTRIDE + co) * 2u;
                LDM_X4(a[i][0], a[i][1], a[i][2], a[i][3], ad);
            }
#pragma unroll
            for (int jp = 0; jp < 2; jp++) {
                uint32_t ad = sbu +
                    (uint32_t)(GOFF_W + (wn * 32 + jp * 16 + lml) * GSTRIDE + co) * 2u;
                LDM_X4(b[jp][0], b[jp][1], b[jp][2], b[jp][3], ad);
            }
#pragma unroll
            for (int i = 0; i < 4; i++)
#pragma unroll
                for (int jp = 0; jp < 2; jp++) {
                    mma_h(acc[i][2 * jp],     a[i][0], a[i][1], a[i][2], a[i][3],
                          b[jp][0], b[jp][2]);
                    mma_h(acc[i][2 * jp + 1], a[i][0], a[i][1], a[i][2], a[i][3],
                          b[jp][1], b[jp][3]);
                }
        }
    }

    // ---- epilogue
#pragma unroll
    for (int i = 0; i < 4; i++) {
        int gr = m0 + wm * 64 + i * 16 + qrow;
#pragma unroll
        for (int j = 0; j < 4; j++) {
            int gc = n0 + wn * 32 + j * 8 + qk2;
            float2 bv = *(const float2*)(bias + gc);
            float v00 = acc[i][j][0] + bv.x, v01 = acc[i][j][1] + bv.y;
            float v10 = acc[i][j][2] + bv.x, v11 = acc[i][j][3] + bv.y;
            if (KV == nullptr) {
                *(float2*)(C + (size_t)gr * N + gc)       = make_float2(v00, v01);
                *(float2*)(C + (size_t)(gr + 8) * N + gc) = make_float2(v10, v11);
            } else if (gc < 512) {
                *(float2*)(C + (size_t)gr * 512 + gc)       = make_float2(v00, v01);
                *(float2*)(C + (size_t)(gr + 8) * 512 + gc) = make_float2(v10, v11);
            } else {
                int isV  = gc >= 1024;
                int xx   = gc - (isV ? 1024 : 512);
                int head = xx >> 6, d = xx & 63;
                int off  = head * 128 + (isV ? 64 : 0) + d;
                *(uint32_t*)(KV + (size_t)gr * 1024 + off)       = h2pack(v00, v01);
                *(uint32_t*)(KV + (size_t)(gr + 8) * 1024 + off) = h2pack(v10, v11);
            }
        }
    }
}

// ===========================================================================
// Flash attention R13: fp16 single-term, 64-key j-tiles, cp.async double
// buffer, 2 CTAs/SM. grid: (row_tile 0..7, head 0..7, region 0..15), 256 thr.
// smem fp16 elems: Q' [0,9216), bufA [9216,18432), bufB [18432,27648).
// In-buffer: K at +0, V at +4608 (stride 72).
// fp32 Q staging overlaps bufA+bufB (bytes 18432..54336).
// ===========================================================================
#define QOFF 0
#define BUFA 9216
#define BUFB 18432
#define BVOF 4608
#define ATT_SMEM_BYTES (27648 * 2)   // 55296

__device__ __forceinline__ void attn_cp_tile(
    uint32_t sbu, int bufoff, const __half* __restrict__ gkv,
    int rg, int h, int jt, int tid)
{
    const int tok = tid >> 2;
    const int c0  = tid & 3;
    const __half* srcb = gkv + (size_t)tok_index(rg, (jt << 6) + tok) * 1024 + h * 128;
#pragma unroll
    for (int s = 0; s < 4; s++) {
        int c = c0 + s * 4;   // 0..15; c<8 -> K chunk, else V chunk
        int de = (c < 8) ? (bufoff + tok * 72 + c * 8)
                         : (bufoff + BVOF + tok * 72 + (c - 8) * 8);
        CP_ASYNC16(sbu + (uint32_t)de * 2u, (const char*)srcb + c * 16);
    }
}

__global__ __launch_bounds__(256, 2) void region_attn_mma_kernel(
    const float* __restrict__ epeg_w)
{
    extern __shared__ char smc[];
    __half* sb = (__half*)smc;
    const uint32_t sbu = smem_u32(smc);

    const int tid  = threadIdx.x;
    const int it   = blockIdx.x;
    const int h    = blockIdx.y;
    const int rg   = blockIdx.z;
    const int i0   = it << 7;

    const int warp = tid >> 5;
    const int lane = tid & 31;
    const int qr   = lane >> 2;
    const int q2   = (lane & 3) << 1;
    const int lml  = lane & 15;
    const int lmc  = (lane >> 4) << 3;

    const float w0 = epeg_w[h * 5 + 0];
    const float w1 = epeg_w[h * 5 + 1];
    const float w2 = epeg_w[h * 5 + 2];
    const float w3 = epeg_w[h * 5 + 3];
    const float w4 = epeg_w[h * 5 + 4];

    // ---- stage fp32 Q rows i0-2..i0+129 (overlaps buf region)
    float* Qf = (float*)(smc + BUFA * 2);   // [132][68] fp32 (35904 B)
    for (int idx = tid; idx < 132 * 64; idx += 256) {
        int p = idx >> 6, d = idx & 63;
        int ii = i0 - 2 + p;
        float v = 0.f;
        if (ii >= 0 && ii < NREG)
            v = g_q[(size_t)tok_index(rg, ii) * DIMC + h * HD + d];
        Qf[p * 68 + d] = v;
    }
    __syncthreads();

    // ---- Q' = SCALE*(q + conv5(q)) -> fp16 into [0,9216)
    for (int idx = tid; idx < 128 * 64; idx += 256) {
        int i = idx >> 6, d = idx & 63;
        const float* col = Qf + i * 68 + d;
        float v = col[2 * 68]
                + w0 * col[0] + w1 * col[68] + w2 * col[2 * 68]
                + w3 * col[3 * 68] + w4 * col[4 * 68];
        sb[QOFF + i * 72 + d] = __float2half(v * SCALE_Q);
    }
    __syncthreads();   // Qf dead

    // ---- issue tile 0 into bufA; preload Q a-frags meanwhile
    attn_cp_tile(sbu, BUFA, g_kv, rg, h, 0, tid);
    CP_COMMIT();

    uint32_t aQ[4][4];
    {
        int r0 = warp * 16;
#pragma unroll
        for (int ks = 0; ks < 4; ks++) {
            uint32_t ad = sbu +
                (uint32_t)(QOFF + (r0 + lml) * 72 + ks * 16 + lmc) * 2u;
            LDM_X4(aQ[ks][0], aQ[ks][1], aQ[ks][2], aQ[ks][3], ad);
        }
    }

    CP_WAIT0();
    __syncthreads();

    float sO[8][4];
#pragma unroll
    for (int i = 0; i < 8; i++)
#pragma unroll
        for (int c = 0; c < 4; c++) sO[i][c] = 0.f;
    float mA = -1e30f, mB = -1e30f, lA = 0.f, lB = 0.f;

    for (int jt = 0; jt < 16; jt++) {
        const int buf = (jt & 1) ? BUFB : BUFA;
        if (jt + 1 < 16)
            attn_cp_tile(sbu, (jt & 1) ? BUFA : BUFB, g_kv, rg, h, jt + 1, tid);
        CP_COMMIT();

        // ---- S = Q' @ K^T (warp: 16 rows x 64 cols, single fp16)
        float s[8][4];
#pragma unroll
        for (int nj = 0; nj < 8; nj++)
#pragma unroll
            for (int c = 0; c < 4; c++) s[nj][c] = 0.f;

#pragma unroll
        for (int ks = 0; ks < 4; ks++) {
            const int co = ks * 16 + lmc;
#pragma unroll
            for (int njp = 0; njp < 4; njp++) {
                uint32_t k0_, k1_, k2_, k3_;
                uint32_t ad = sbu +
                    (uint32_t)(buf + (njp * 16 + lml) * 72 + co) * 2u;
                LDM_X4(k0_, k1_, k2_, k3_, ad);
                mma_h(s[2 * njp],     aQ[ks][0], aQ[ks][1], aQ[ks][2], aQ[ks][3], k0_, k2_);
                mma_h(s[2 * njp + 1], aQ[ks][0], aQ[ks][1], aQ[ks][2], aQ[ks][3], k1_, k3_);
            }
        }

        // ---- register online softmax (rows A=qr, B=qr+8)
        float mtA = -1e30f, mtB = -1e30f;
#pragma unroll
        for (int nj = 0; nj < 8; nj++) {
            mtA = fmaxf(mtA, fmaxf(s[nj][0], s[nj][1]));
            mtB = fmaxf(mtB, fmaxf(s[nj][2], s[nj][3]));
        }
        mtA = fmaxf(mtA, __shfl_xor_sync(0xffffffffu, mtA, 1));
        mtA = fmaxf(mtA, __shfl_xor_sync(0xffffffffu, mtA, 2));
        mtB = fmaxf(mtB, __shfl_xor_sync(0xffffffffu, mtB, 1));
        mtB = fmaxf(mtB, __shfl_xor_sync(0xffffffffu, mtB, 2));
        float mnA = fmaxf(mA, mtA), mnB = fmaxf(mB, mtB);
        float alA = __expf(mA - mnA), alB = __expf(mB - mnB);
        mA = mnA; mB = mnB;

        float rsA = 0.f, rsB = 0.f;
#pragma unroll
        for (int nj = 0; nj < 8; nj++) {
            s[nj][0] = __expf(s[nj][0] - mnA);
            s[nj][1] = __expf(s[nj][1] - mnA);
            s[nj][2] = __expf(s[nj][2] - mnB);
            s[nj][3] = __expf(s[nj][3] - mnB);
            rsA += s[nj][0] + s[nj][1];
            rsB += s[nj][2] + s[nj][3];
        }
        rsA += __shfl_xor_sync(0xffffffffu, rsA, 1);
        rsA += __shfl_xor_sync(0xffffffffu, rsA, 2);
        rsB += __shfl_xor_sync(0xffffffffu, rsB, 1);
        rsB += __shfl_xor_sync(0xffffffffu, rsB, 2);
        lA = lA * alA + rsA;
        lB = lB * alB + rsB;

#pragma unroll
        for (int nd = 0; nd < 8; nd++) {
            sO[nd][0] *= alA; sO[nd][1] *= alA;
            sO[nd][2] *= alB; sO[nd][3] *= alB;
        }

        // ---- O += P @ V (P fp16 from S regs; V frags via ldmatrix.trans)
#pragma unroll
        for (int kk = 0; kk < 4; kk++) {
            uint32_t pa[4];
            pa[0] = h2pack(s[2 * kk][0],     s[2 * kk][1]);
            pa[1] = h2pack(s[2 * kk][2],     s[2 * kk][3]);
            pa[2] = h2pack(s[2 * kk + 1][0], s[2 * kk + 1][1]);
            pa[3] = h2pack(s[2 * kk + 1][2], s[2 * kk + 1][3]);
            int vrow = kk * 16 + lml;
#pragma unroll
            for (int ndp = 0; ndp < 4; ndp++) {
                uint32_t v0_, v1_, v2_, v3_;
                uint32_t ad = sbu +
                    (uint32_t)(buf + BVOF + vrow * 72 + ndp * 16 + lmc) * 2u;
                LDM_X4_T(v0_, v1_, v2_, v3_, ad);
                mma_h(sO[2 * ndp],     pa[0], pa[1], pa[2], pa[3], v0_, v1_);
                mma_h(sO[2 * ndp + 1], pa[0], pa[1], pa[2], pa[3], v2_, v3_);
            }
        }

        CP_WAIT0();
        __syncthreads();
    }

    // ---- epilogue: O/l -> g_att (token order)
    float iA = 1.0f / lA, iB = 1.0f / lB;
    int rA = i0 + warp * 16 + qr;
    int tokA = tok_index(rg, rA);
    int tokB = tok_index(rg, rA + 8);
#pragma unroll
    for (int nd = 0; nd < 8; nd++) {
        int c = h * HD + nd * 8 + q2;
        float2 oa, ob;
        oa.x = sO[nd][0] * iA; oa.y = sO[nd][1] * iA;
        ob.x = sO[nd][2] * iB; ob.y = sO[nd][3] * iB;
        *(float2*)(g_att + (size_t)tokA * DIMC + c) = oa;
        *(float2*)(g_att + (size_t)tokB * DIMC + c) = ob;
    }
}

// ---------------------------------------------------------------------------
extern "C" void kernel_launch(void* const* d_in, const int* in_sizes, int n_in,
                              void* d_out, int out_size) {
    const float* x      = (const float*)d_in[0];
    const float* qkv_w  = (const float*)d_in[1];
    const float* qkv_b  = (const float*)d_in[2];
    const float* proj_w = (const float*)d_in[3];
    const float* proj_b = (const float*)d_in[4];
    const float* epeg_w = (const float*)d_in[5];
    float* out = (float*)d_out;

    float* q_buf = nullptr;
    __half* kv_buf = nullptr;
    float* att_buf = nullptr;
    cudaGetSymbolAddress((void**)&q_buf, g_q);
    cudaGetSymbolAddress((void**)&kv_buf, g_kv);
    cudaGetSymbolAddress((void**)&att_buf, g_att);

    cudaFuncSetAttribute(gemm_mma_kernel,
                         cudaFuncAttributeMaxDynamicSharedMemorySize,
                         GEMM_SMEM_BYTES);
    cudaFuncSetAttribute(region_attn_mma_kernel,
                         cudaFuncAttributeMaxDynamicSharedMemorySize,
                         ATT_SMEM_BYTES);

    // qkv = x @ qkv_w^T + qkv_b -> g_q (fp32) + g_kv (fp16)
    gemm_mma_kernel<<<dim3(QKVC / 128, LTOK / 128), 256, GEMM_SMEM_BYTES>>>(
        x, qkv_w, qkv_b, q_buf, kv_buf, LTOK, QKVC, DIMC);

    // flash region attention (conv folded into Q')
    region_attn_mma_kernel<<<dim3(8, NH, 16), 256, ATT_SMEM_BYTES>>>(epeg_w);

    // out = att @ proj_w^T + proj_b
    gemm_mma_kernel<<<dim3(DIMC / 128, LTOK / 128), 256, GEMM_SMEM_BYTES>>>(
        att_buf, proj_w, proj_b, out, nullptr, LTOK, DIMC, DIMC);
}

// round 14
// speedup vs baseline: 6.0765x; 1.0254x over previous
#include <cuda_runtime.h>
#include <cuda_fp16.h>
#include <cstdint>

// ---------------------------------------------------------------------------
// RegionAttention R14:
//  - NEW: fp32->fp16 pre-conversion of x, qkv_w, proj_w (streaming prepass);
//    GEMMs consume fp16 directly via cp.async (no per-chunk convert, half LDG);
//    attention epilogue writes g_att in fp16 (proj A operand ready-made).
//  - GEMM: fp16 single-term mma, 128x128 tile, single smem buffer, 2 CTAs/SM.
//  - attention: unchanged from R13 (flash fp16, conv folded into Q',
//    64-key tiles, cp.async double buffer, 2 CTAs/SM).
// ---------------------------------------------------------------------------

#define LTOK   16384
#define DIMC   512
#define QKVC   1536
#define NH     8
#define HD     64
#define NREG   1024
#define SCALE_Q 0.125f

__device__ float  g_q[LTOK * DIMC];        // q, fp32, bias applied
__device__ __half g_kv[LTOK * 1024];       // [tok][head][k|v][64] fp16
__device__ __half g_att[LTOK * DIMC];      // attention output fp16, token order
__device__ __half g_x16[LTOK * DIMC];      // x converted
__device__ __half g_w1[QKVC * DIMC];       // qkv_w converted
__device__ __half g_w2[DIMC * DIMC];       // proj_w converted

__device__ __forceinline__ int tok_index(int rg, int n) {
    return ((rg >> 2) << 12) | ((n >> 5) << 7) | ((rg & 3) << 5) | (n & 31);
}

__device__ __forceinline__ uint32_t smem_u32(const void* p) {
    uint32_t a;
    asm("{ .reg .u64 t; cvta.to.shared.u64 t, %1; cvt.u32.u64 %0, t; }"
        : "=r"(a) : "l"(p));
    return a;
}

__device__ __forceinline__ void mma_h(float c[4],
                                      uint32_t a0, uint32_t a1,
                                      uint32_t a2, uint32_t a3,
                                      uint32_t b0, uint32_t b1) {
    asm volatile(
        "mma.sync.aligned.m16n8k16.row.col.f32.f16.f16.f32 "
        "{%0,%1,%2,%3}, {%4,%5,%6,%7}, {%8,%9}, {%0,%1,%2,%3};"
        : "+f"(c[0]), "+f"(c[1]), "+f"(c[2]), "+f"(c[3])
        : "r"(a0), "r"(a1), "r"(a2), "r"(a3), "r"(b0), "r"(b1));
}

__device__ __forceinline__ uint32_t h2pack(float x, float y) {
    __half2 h = __floats2half2_rn(x, y);
    return *(uint32_t*)&h;
}

#define LDM_X4(r0_, r1_, r2_, r3_, addr) \
    asm volatile("ldmatrix.sync.aligned.m8n8.x4.shared.b16 {%0,%1,%2,%3}, [%4];" \
        : "=r"(r0_), "=r"(r1_), "=r"(r2_), "=r"(r3_) : "r"(addr))
#define LDM_X4_T(r0_, r1_, r2_, r3_, addr) \
    asm volatile("ldmatrix.sync.aligned.m8n8.x4.trans.shared.b16 {%0,%1,%2,%3}, [%4];" \
        : "=r"(r0_), "=r"(r1_), "=r"(r2_), "=r"(r3_) : "r"(addr))

#define CP_ASYNC16(dst, src) \
    asm volatile("cp.async.cg.shared.global [%0], [%1], 16;" \
                 :: "r"(dst), "l"(src) : "memory")
#define CP_COMMIT() asm volatile("cp.async.commit_group;" ::: "memory")
#define CP_WAIT0()  asm volatile("cp.async.wait_group 0;" ::: "memory")

// ===========================================================================
// Prepass: fp32 -> fp16 convert (vectorized, grid-stride).
// ===========================================================================
__global__ __launch_bounds__(256) void cvt16_kernel(
    const float* __restrict__ src, __half* __restrict__ dst, int n4)
{
    int i = blockIdx.x * 256 + threadIdx.x;
    int stride = gridDim.x * 256;
    for (; i < n4; i += stride) {
        float4 v = *(const float4*)(src + i * 4);
        uint2 o;
        o.x = h2pack(v.x, v.y);
        o.y = h2pack(v.z, v.w);
        *(uint2*)(dst + i * 4) = o;
    }
}

// ===========================================================================
// fp16 GEMM: C = A @ W^T + bias. A,W fp16 in gmem, cp.async loader.
// Tile 128x128, K-chunk 64, 256 threads = 8 warps (2m x 4n). 2 CTAs/SM.
// If KV != nullptr (QKV gemm): cols [0,512) -> fp32 C (stride 512),
// cols [512,1536) -> fp16 into KV. Else fp32 C (stride N).
// ===========================================================================
#define GSTRIDE 72
#define GOFF_W  (128 * GSTRIDE)
#define GEMM_SMEM_BYTES (2 * 128 * GSTRIDE * 2)   // 36864

__global__ __launch_bounds__(256, 2) void gemm_mma_kernel(
    const __half* __restrict__ A, const __half* __restrict__ W,
    const float* __restrict__ bias, float* __restrict__ C,
    __half* __restrict__ KV,
    int M, int N, int K)
{
    extern __shared__ char smc[];
    const uint32_t sbu = smem_u32(smc);

    const int tid  = threadIdx.x;
    const int m0   = blockIdx.y << 7;
    const int n0   = blockIdx.x << 7;
    const int wid  = tid >> 5;
    const int lane = tid & 31;
    const int wm   = wid & 1;
    const int wn   = wid >> 1;

    const int qrow = lane >> 2;
    const int qk2  = (lane & 3) << 1;
    const int lml  = lane & 15;
    const int lmc  = (lane >> 4) << 3;

    // loader: 1024 16B-chunks per operand, 4 per thread
    const int clr = tid >> 3;          // not used directly; see loop

    float acc[4][4][4];
#pragma unroll
    for (int i = 0; i < 4; i++)
#pragma unroll
        for (int j = 0; j < 4; j++)
#pragma unroll
            for (int c = 0; c < 4; c++) acc[i][j][c] = 0.f;

    const int nchunks = K >> 6;
    for (int kc = 0; kc < nchunks; kc++) {
        const int k0 = kc << 6;
        if (kc > 0) __syncthreads();

#pragma unroll
        for (int s = 0; s < 4; s++) {
            int id = tid + s * 256;        // 0..1023
            int r  = id >> 3;              // 0..127
            int cc = id & 7;               // 0..7 (16B chunk)
            CP_ASYNC16(sbu + (uint32_t)(r * GSTRIDE + cc * 8) * 2u,
                       A + (size_t)(m0 + r) * K + k0 + cc * 8);
            CP_ASYNC16(sbu + (uint32_t)(GOFF_W + r * GSTRIDE + cc * 8) * 2u,
                       W + (size_t)(n0 + r) * K + k0 + cc * 8);
        }
        CP_COMMIT();
        CP_WAIT0();
        __syncthreads();

#pragma unroll
        for (int ks = 0; ks < 4; ks++) {
            const int co = ks * 16 + lmc;
            uint32_t a[4][4], b[2][4];
#pragma unroll
            for (int i = 0; i < 4; i++) {
                uint32_t ad = sbu +
                    (uint32_t)((wm * 64 + i * 16 + lml) * GSTRIDE + co) * 2u;
                LDM_X4(a[i][0], a[i][1], a[i][2], a[i][3], ad);
            }
#pragma unroll
            for (int jp = 0; jp < 2; jp++) {
                uint32_t ad = sbu +
                    (uint32_t)(GOFF_W + (wn * 32 + jp * 16 + lml) * GSTRIDE + co) * 2u;
                LDM_X4(b[jp][0], b[jp][1], b[jp][2], b[jp][3], ad);
            }
#pragma unroll
            for (int i = 0; i < 4; i++)
#pragma unroll
                for (int jp = 0; jp < 2; jp++) {
                    mma_h(acc[i][2 * jp],     a[i][0], a[i][1], a[i][2], a[i][3],
                          b[jp][0], b[jp][2]);
                    mma_h(acc[i][2 * jp + 1], a[i][0], a[i][1], a[i][2], a[i][3],
                          b[jp][1], b[jp][3]);
                }
        }
    }

    // ---- epilogue
#pragma unroll
    for (int i = 0; i < 4; i++) {
        int gr = m0 + wm * 64 + i * 16 + qrow;
#pragma unroll
        for (int j = 0; j < 4; j++) {
            int gc = n0 + wn * 32 + j * 8 + qk2;
            float2 bv = *(const float2*)(bias + gc);
            float v00 = acc[i][j][0] + bv.x, v01 = acc[i][j][1] + bv.y;
            float v10 = acc[i][j][2] + bv.x, v11 = acc[i][j][3] + bv.y;
            if (KV == nullptr) {
                *(float2*)(C + (size_t)gr * N + gc)       = make_float2(v00, v01);
                *(float2*)(C + (size_t)(gr + 8) * N + gc) = make_float2(v10, v11);
            } else if (gc < 512) {
                *(float2*)(C + (size_t)gr * 512 + gc)       = make_float2(v00, v01);
                *(float2*)(C + (size_t)(gr + 8) * 512 + gc) = make_float2(v10, v11);
            } else {
                int isV  = gc >= 1024;
                int xx   = gc - (isV ? 1024 : 512);
                int head = xx >> 6, d = xx & 63;
                int off  = head * 128 + (isV ? 64 : 0) + d;
                *(uint32_t*)(KV + (size_t)gr * 1024 + off)       = h2pack(v00, v01);
                *(uint32_t*)(KV + (size_t)(gr + 8) * 1024 + off) = h2pack(v10, v11);
            }
        }
    }
}

// ===========================================================================
// Flash attention (unchanged from R13, epilogue now fp16 to g_att).
// ===========================================================================
#define QOFF 0
#define BUFA 9216
#define BUFB 18432
#define BVOF 4608
#define ATT_SMEM_BYTES (27648 * 2)   // 55296

__device__ __forceinline__ void attn_cp_tile(
    uint32_t sbu, int bufoff, const __half* __restrict__ gkv,
    int rg, int h, int jt, int tid)
{
    const int tok = tid >> 2;
    const int c0  = tid & 3;
    const __half* srcb = gkv + (size_t)tok_index(rg, (jt << 6) + tok) * 1024 + h * 128;
#pragma unroll
    for (int s = 0; s < 4; s++) {
        int c = c0 + s * 4;
        int de = (c < 8) ? (bufoff + tok * 72 + c * 8)
                         : (bufoff + BVOF + tok * 72 + (c - 8) * 8);
        CP_ASYNC16(sbu + (uint32_t)de * 2u, (const char*)srcb + c * 16);
    }
}

__global__ __launch_bounds__(256, 2) void region_attn_mma_kernel(
    const float* __restrict__ epeg_w)
{
    extern __shared__ char smc[];
    __half* sb = (__half*)smc;
    const uint32_t sbu = smem_u32(smc);

    const int tid  = threadIdx.x;
    const int it   = blockIdx.x;
    const int h    = blockIdx.y;
    const int rg   = blockIdx.z;
    const int i0   = it << 7;

    const int warp = tid >> 5;
    const int lane = tid & 31;
    const int qr   = lane >> 2;
    const int q2   = (lane & 3) << 1;
    const int lml  = lane & 15;
    const int lmc  = (lane >> 4) << 3;

    const float w0 = epeg_w[h * 5 + 0];
    const float w1 = epeg_w[h * 5 + 1];
    const float w2 = epeg_w[h * 5 + 2];
    const float w3 = epeg_w[h * 5 + 3];
    const float w4 = epeg_w[h * 5 + 4];

    float* Qf = (float*)(smc + BUFA * 2);   // [132][68] fp32 staging
    for (int idx = tid; idx < 132 * 64; idx += 256) {
        int p = idx >> 6, d = idx & 63;
        int ii = i0 - 2 + p;
        float v = 0.f;
        if (ii >= 0 && ii < NREG)
            v = g_q[(size_t)tok_index(rg, ii) * DIMC + h * HD + d];
        Qf[p * 68 + d] = v;
    }
    __syncthreads();

    for (int idx = tid; idx < 128 * 64; idx += 256) {
        int i = idx >> 6, d = idx & 63;
        const float* col = Qf + i * 68 + d;
        float v = col[2 * 68]
                + w0 * col[0] + w1 * col[68] + w2 * col[2 * 68]
                + w3 * col[3 * 68] + w4 * col[4 * 68];
        sb[QOFF + i * 72 + d] = __float2half(v * SCALE_Q);
    }
    __syncthreads();

    attn_cp_tile(sbu, BUFA, g_kv, rg, h, 0, tid);
    CP_COMMIT();

    uint32_t aQ[4][4];
    {
        int r0 = warp * 16;
#pragma unroll
        for (int ks = 0; ks < 4; ks++) {
            uint32_t ad = sbu +
                (uint32_t)(QOFF + (r0 + lml) * 72 + ks * 16 + lmc) * 2u;
            LDM_X4(aQ[ks][0], aQ[ks][1], aQ[ks][2], aQ[ks][3], ad);
        }
    }

    CP_WAIT0();
    __syncthreads();

    float sO[8][4];
#pragma unroll
    for (int i = 0; i < 8; i++)
#pragma unroll
        for (int c = 0; c < 4; c++) sO[i][c] = 0.f;
    float mA = -1e30f, mB = -1e30f, lA = 0.f, lB = 0.f;

    for (int jt = 0; jt < 16; jt++) {
        const int buf = (jt & 1) ? BUFB : BUFA;
        if (jt + 1 < 16)
            attn_cp_tile(sbu, (jt & 1) ? BUFA : BUFB, g_kv, rg, h, jt + 1, tid);
        CP_COMMIT();

        float s[8][4];
#pragma unroll
        for (int nj = 0; nj < 8; nj++)
#pragma unroll
            for (int c = 0; c < 4; c++) s[nj][c] = 0.f;

#pragma unroll
        for (int ks = 0; ks < 4; ks++) {
            const int co = ks * 16 + lmc;
#pragma unroll
            for (int njp = 0; njp < 4; njp++) {
                uint32_t k0_, k1_, k2_, k3_;
                uint32_t ad = sbu +
                    (uint32_t)(buf + (njp * 16 + lml) * 72 + co) * 2u;
                LDM_X4(k0_, k1_, k2_, k3_, ad);
                mma_h(s[2 * njp],     aQ[ks][0], aQ[ks][1], aQ[ks][2], aQ[ks][3], k0_, k2_);
                mma_h(s[2 * njp + 1], aQ[ks][0], aQ[ks][1], aQ[ks][2], aQ[ks][3], k1_, k3_);
            }
        }

        float mtA = -1e30f, mtB = -1e30f;
#pragma unroll
        for (int nj = 0; nj < 8; nj++) {
            mtA = fmaxf(mtA, fmaxf(s[nj][0], s[nj][1]));
            mtB = fmaxf(mtB, fmaxf(s[nj][2], s[nj][3]));
        }
        mtA = fmaxf(mtA, __shfl_xor_sync(0xffffffffu, mtA, 1));
        mtA = fmaxf(mtA, __shfl_xor_sync(0xffffffffu, mtA, 2));
        mtB = fmaxf(mtB, __shfl_xor_sync(0xffffffffu, mtB, 1));
        mtB = fmaxf(mtB, __shfl_xor_sync(0xffffffffu, mtB, 2));
        float mnA = fmaxf(mA, mtA), mnB = fmaxf(mB, mtB);
        float alA = __expf(mA - mnA), alB = __expf(mB - mnB);
        mA = mnA; mB = mnB;

        float rsA = 0.f, rsB = 0.f;
#pragma unroll
        for (int nj = 0; nj < 8; nj++) {
            s[nj][0] = __expf(s[nj][0] - mnA);
            s[nj][1] = __expf(s[nj][1] - mnA);
            s[nj][2] = __expf(s[nj][2] - mnB);
            s[nj][3] = __expf(s[nj][3] - mnB);
            rsA += s[nj][0] + s[nj][1];
            rsB += s[nj][2] + s[nj][3];
        }
        rsA += __shfl_xor_sync(0xffffffffu, rsA, 1);
        rsA += __shfl_xor_sync(0xffffffffu, rsA, 2);
        rsB += __shfl_xor_sync(0xffffffffu, rsB, 1);
        rsB += __shfl_xor_sync(0xffffffffu, rsB, 2);
        lA = lA * alA + rsA;
        lB = lB * alB + rsB;

#pragma unroll
        for (int nd = 0; nd < 8; nd++) {
            sO[nd][0] *= alA; sO[nd][1] *= alA;
            sO[nd][2] *= alB; sO[nd][3] *= alB;
        }

#pragma unroll
        for (int kk = 0; kk < 4; kk++) {
            uint32_t pa[4];
            pa[0] = h2pack(s[2 * kk][0],     s[2 * kk][1]);
            pa[1] = h2pack(s[2 * kk][2],     s[2 * kk][3]);
            pa[2] = h2pack(s[2 * kk + 1][0], s[2 * kk + 1][1]);
            pa[3] = h2pack(s[2 * kk + 1][2], s[2 * kk + 1][3]);
            int vrow = kk * 16 + lml;
#pragma unroll
            for (int ndp = 0; ndp < 4; ndp++) {
                uint32_t v0_, v1_, v2_, v3_;
                uint32_t ad = sbu +
                    (uint32_t)(buf + BVOF + vrow * 72 + ndp * 16 + lmc) * 2u;
                LDM_X4_T(v0_, v1_, v2_, v3_, ad);
                mma_h(sO[2 * ndp],     pa[0], pa[1], pa[2], pa[3], v0_, v1_);
                mma_h(sO[2 * ndp + 1], pa[0], pa[1], pa[2], pa[3], v2_, v3_);
            }
        }

        CP_WAIT0();
        __syncthreads();
    }

    // ---- epilogue: O/l -> g_att (fp16, token order)
    float iA = 1.0f / lA, iB = 1.0f / lB;
    int rA = i0 + warp * 16 + qr;
    int tokA = tok_index(rg, rA);
    int tokB = tok_index(rg, rA + 8);
#pragma unroll
    for (int nd = 0; nd < 8; nd++) {
        int c = h * HD + nd * 8 + q2;
        *(uint32_t*)(g_att + (size_t)tokA * DIMC + c) =
            h2pack(sO[nd][0] * iA, sO[nd][1] * iA);
        *(uint32_t*)(g_att + (size_t)tokB * DIMC + c) =
            h2pack(sO[nd][2] * iB, sO[nd][3] * iB);
    }
}

// ---------------------------------------------------------------------------
extern "C" void kernel_launch(void* const* d_in, const int* in_sizes, int n_in,
                              void* d_out, int out_size) {
    const float* x      = (const float*)d_in[0];
    const float* qkv_w  = (const float*)d_in[1];
    const float* qkv_b  = (const float*)d_in[2];
    const float* proj_w = (const float*)d_in[3];
    const float* proj_b = (const float*)d_in[4];
    const float* epeg_w = (const float*)d_in[5];
    float* out = (float*)d_out;

    float*  q_buf   = nullptr;
    __half* kv_buf  = nullptr;
    __half* att_buf = nullptr;
    __half* x16     = nullptr;
    __half* w1      = nullptr;
    __half* w2      = nullptr;
    cudaGetSymbolAddress((void**)&q_buf,   g_q);
    cudaGetSymbolAddress((void**)&kv_buf,  g_kv);
    cudaGetSymbolAddress((void**)&att_buf, g_att);
    cudaGetSymbolAddress((void**)&x16,     g_x16);
    cudaGetSymbolAddress((void**)&w1,      g_w1);
    cudaGetSymbolAddress((void**)&w2,      g_w2);

    cudaFuncSetAttribute(gemm_mma_kernel,
                         cudaFuncAttributeMaxDynamicSharedMemorySize,
                         GEMM_SMEM_BYTES);
    cudaFuncSetAttribute(region_attn_mma_kernel,
                         cudaFuncAttributeMaxDynamicSharedMemorySize,
                         ATT_SMEM_BYTES);

    // prepass: fp32 -> fp16
    cvt16_kernel<<<512, 256>>>(x,      x16, LTOK * DIMC / 4);
    cvt16_kernel<<<256, 256>>>(qkv_w,  w1,  QKVC * DIMC / 4);
    cvt16_kernel<<<128, 256>>>(proj_w, w2,  DIMC * DIMC / 4);

    // qkv = x @ qkv_w^T + qkv_b -> g_q (fp32) + g_kv (fp16)
    gemm_mma_kernel<<<dim3(QKVC / 128, LTOK / 128), 256, GEMM_SMEM_BYTES>>>(
        x16, w1, qkv_b, q_buf, kv_buf, LTOK, QKVC, DIMC);

    // flash region attention (conv folded into Q') -> g_att fp16
    region_attn_mma_kernel<<<dim3(8, NH, 16), 256, ATT_SMEM_BYTES>>>(epeg_w);

    // out = att @ proj_w^T + proj_b
    gemm_mma_kernel<<<dim3(DIMC / 128, LTOK / 128), 256, GEMM_SMEM_BYTES>>>(
        att_buf, w2, proj_b, out, nullptr, LTOK, DIMC, DIMC);
}

// round 15
// speedup vs baseline: 6.2344x; 1.0260x over previous
#include <cuda_runtime.h>
#include <cuda_fp16.h>
#include <cstdint>

// ---------------------------------------------------------------------------
// RegionAttention R15:
//  - GEMM: cp.async DOUBLE-BUFFERED pipeline (prefetch chunk k+1 before
//    waiting on chunk k; zero register cost). 73.7KB smem, 2 CTAs/SM.
//  - prepass fp32->fp16 of x / qkv_w / proj_w (unchanged from R14).
//  - attention: unchanged (flash fp16, conv folded into Q', 64-key tiles,
//    cp.async double buffer, 2 CTAs/SM).
// ---------------------------------------------------------------------------

#define LTOK   16384
#define DIMC   512
#define QKVC   1536
#define NH     8
#define HD     64
#define NREG   1024
#define SCALE_Q 0.125f

__device__ float  g_q[LTOK * DIMC];        // q, fp32, bias applied
__device__ __half g_kv[LTOK * 1024];       // [tok][head][k|v][64] fp16
__device__ __half g_att[LTOK * DIMC];      // attention output fp16, token order
__device__ __half g_x16[LTOK * DIMC];      // x converted
__device__ __half g_w1[QKVC * DIMC];       // qkv_w converted
__device__ __half g_w2[DIMC * DIMC];       // proj_w converted

__device__ __forceinline__ int tok_index(int rg, int n) {
    return ((rg >> 2) << 12) | ((n >> 5) << 7) | ((rg & 3) << 5) | (n & 31);
}

__device__ __forceinline__ uint32_t smem_u32(const void* p) {
    uint32_t a;
    asm("{ .reg .u64 t; cvta.to.shared.u64 t, %1; cvt.u32.u64 %0, t; }"
        : "=r"(a) : "l"(p));
    return a;
}

__device__ __forceinline__ void mma_h(float c[4],
                                      uint32_t a0, uint32_t a1,
                                      uint32_t a2, uint32_t a3,
                                      uint32_t b0, uint32_t b1) {
    asm volatile(
        "mma.sync.aligned.m16n8k16.row.col.f32.f16.f16.f32 "
        "{%0,%1,%2,%3}, {%4,%5,%6,%7}, {%8,%9}, {%0,%1,%2,%3};"
        : "+f"(c[0]), "+f"(c[1]), "+f"(c[2]), "+f"(c[3])
        : "r"(a0), "r"(a1), "r"(a2), "r"(a3), "r"(b0), "r"(b1));
}

__device__ __forceinline__ uint32_t h2pack(float x, float y) {
    __half2 h = __floats2half2_rn(x, y);
    return *(uint32_t*)&h;
}

#define LDM_X4(r0_, r1_, r2_, r3_, addr) \
    asm volatile("ldmatrix.sync.aligned.m8n8.x4.shared.b16 {%0,%1,%2,%3}, [%4];" \
        : "=r"(r0_), "=r"(r1_), "=r"(r2_), "=r"(r3_) : "r"(addr))
#define LDM_X4_T(r0_, r1_, r2_, r3_, addr) \
    asm volatile("ldmatrix.sync.aligned.m8n8.x4.trans.shared.b16 {%0,%1,%2,%3}, [%4];" \
        : "=r"(r0_), "=r"(r1_), "=r"(r2_), "=r"(r3_) : "r"(addr))

#define CP_ASYNC16(dst, src) \
    asm volatile("cp.async.cg.shared.global [%0], [%1], 16;" \
                 :: "r"(dst), "l"(src) : "memory")
#define CP_COMMIT() asm volatile("cp.async.commit_group;" ::: "memory")
#define CP_WAIT0()  asm volatile("cp.async.wait_group 0;" ::: "memory")
#define CP_WAIT1()  asm volatile("cp.async.wait_group 1;" ::: "memory")

// ===========================================================================
// Prepass: fp32 -> fp16 convert (vectorized, grid-stride).
// ===========================================================================
__global__ __launch_bounds__(256) void cvt16_kernel(
    const float* __restrict__ src, __half* __restrict__ dst, int n4)
{
    int i = blockIdx.x * 256 + threadIdx.x;
    int stride = gridDim.x * 256;
    for (; i < n4; i += stride) {
        float4 v = *(const float4*)(src + i * 4);
        uint2 o;
        o.x = h2pack(v.x, v.y);
        o.y = h2pack(v.z, v.w);
        *(uint2*)(dst + i * 4) = o;
    }
}

// ===========================================================================
// fp16 GEMM, cp.async double-buffered: C = A @ W^T + bias.
// Tile 128x128, K-chunk 64, 256 threads = 8 warps (2m x 4n). 2 CTAs/SM.
// If KV != nullptr (QKV gemm): cols [0,512) -> fp32 C (stride 512),
// cols [512,1536) -> fp16 into KV. Else fp32 C (stride N).
// ===========================================================================
#define GSTRIDE 72
#define GOFF_W  (128 * GSTRIDE)
#define GBUFH   (2 * 128 * GSTRIDE)               // fp16 elems per buffer
#define GEMM_SMEM_BYTES (2 * GBUFH * 2)           // 73728

__device__ __forceinline__ void gemm_issue_chunk(
    uint32_t sbu, int bufoff, const __half* __restrict__ A,
    const __half* __restrict__ W, int m0, int n0, int K, int k0, int tid)
{
#pragma unroll
    for (int s = 0; s < 4; s++) {
        int id = tid + s * 256;        // 0..1023
        int r  = id >> 3;              // 0..127
        int cc = id & 7;               // 16B chunk
        CP_ASYNC16(sbu + (uint32_t)(bufoff + r * GSTRIDE + cc * 8) * 2u,
                   A + (size_t)(m0 + r) * K + k0 + cc * 8);
        CP_ASYNC16(sbu + (uint32_t)(bufoff + GOFF_W + r * GSTRIDE + cc * 8) * 2u,
                   W + (size_t)(n0 + r) * K + k0 + cc * 8);
    }
    CP_COMMIT();
}

__global__ __launch_bounds__(256, 2) void gemm_mma_kernel(
    const __half* __restrict__ A, const __half* __restrict__ W,
    const float* __restrict__ bias, float* __restrict__ C,
    __half* __restrict__ KV,
    int M, int N, int K)
{
    extern __shared__ char smc[];
    const uint32_t sbu = smem_u32(smc);

    const int tid  = threadIdx.x;
    const int m0   = blockIdx.y << 7;
    const int n0   = blockIdx.x << 7;
    const int wid  = tid >> 5;
    const int lane = tid & 31;
    const int wm   = wid & 1;
    const int wn   = wid >> 1;

    const int qrow = lane >> 2;
    const int qk2  = (lane & 3) << 1;
    const int lml  = lane & 15;
    const int lmc  = (lane >> 4) << 3;

    float acc[4][4][4];
#pragma unroll
    for (int i = 0; i < 4; i++)
#pragma unroll
        for (int j = 0; j < 4; j++)
#pragma unroll
            for (int c = 0; c < 4; c++) acc[i][j][c] = 0.f;

    const int nchunks = K >> 6;

    // prologue: chunk 0 in flight
    gemm_issue_chunk(sbu, 0, A, W, m0, n0, K, 0, tid);

    for (int kc = 0; kc < nchunks; kc++) {
        const int buf = (kc & 1) ? GBUFH : 0;
        if (kc + 1 < nchunks) {
            gemm_issue_chunk(sbu, (kc & 1) ? 0 : GBUFH, A, W, m0, n0, K,
                             (kc + 1) << 6, tid);
            CP_WAIT1();     // chunk kc resident; kc+1 may still fly
        } else {
            CP_WAIT0();
        }
        __syncthreads();

#pragma unroll
        for (int ks = 0; ks < 4; ks++) {
            const int co = ks * 16 + lmc;
            uint32_t a[4][4], b[2][4];
#pragma unroll
            for (int i = 0; i < 4; i++) {
                uint32_t ad = sbu +
                    (uint32_t)(buf + (wm * 64 + i * 16 + lml) * GSTRIDE + co) * 2u;
                LDM_X4(a[i][0], a[i][1], a[i][2], a[i][3], ad);
            }
#pragma unroll
            for (int jp = 0; jp < 2; jp++) {
                uint32_t ad = sbu +
                    (uint32_t)(buf + GOFF_W + (wn * 32 + jp * 16 + lml) * GSTRIDE + co) * 2u;
                LDM_X4(b[jp][0], b[jp][1], b[jp][2], b[jp][3], ad);
            }
#pragma unroll
            for (int i = 0; i < 4; i++)
#pragma unroll
                for (int jp = 0; jp < 2; jp++) {
                    mma_h(acc[i][2 * jp],     a[i][0], a[i][1], a[i][2], a[i][3],
                          b[jp][0], b[jp][2]);
                    mma_h(acc[i][2 * jp + 1], a[i][0], a[i][1], a[i][2], a[i][3],
                          b[jp][1], b[jp][3]);
                }
        }
        __syncthreads();   // compute done before this buffer is re-filled
    }

    // ---- epilogue
#pragma unroll
    for (int i = 0; i < 4; i++) {
        int gr = m0 + wm * 64 + i * 16 + qrow;
#pragma unroll
        for (int j = 0; j < 4; j++) {
            int gc = n0 + wn * 32 + j * 8 + qk2;
            float2 bv = *(const float2*)(bias + gc);
            float v00 = acc[i][j][0] + bv.x, v01 = acc[i][j][1] + bv.y;
            float v10 = acc[i][j][2] + bv.x, v11 = acc[i][j][3] + bv.y;
            if (KV == nullptr) {
                *(float2*)(C + (size_t)gr * N + gc)       = make_float2(v00, v01);
                *(float2*)(C + (size_t)(gr + 8) * N + gc) = make_float2(v10, v11);
            } else if (gc < 512) {
                *(float2*)(C + (size_t)gr * 512 + gc)       = make_float2(v00, v01);
                *(float2*)(C + (size_t)(gr + 8) * 512 + gc) = make_float2(v10, v11);
            } else {
                int isV  = gc >= 1024;
                int xx   = gc - (isV ? 1024 : 512);
                int head = xx >> 6, d = xx & 63;
                int off  = head * 128 + (isV ? 64 : 0) + d;
                *(uint32_t*)(KV + (size_t)gr * 1024 + off)       = h2pack(v00, v01);
                *(uint32_t*)(KV + (size_t)(gr + 8) * 1024 + off) = h2pack(v10, v11);
            }
        }
    }
}

// ===========================================================================
// Flash attention (unchanged from R14).
// ===========================================================================
#define QOFF 0
#define BUFA 9216
#define BUFB 18432
#define BVOF 4608
#define ATT_SMEM_BYTES (27648 * 2)   // 55296

__device__ __forceinline__ void attn_cp_tile(
    uint32_t sbu, int bufoff, const __half* __restrict__ gkv,
    int rg, int h, int jt, int tid)
{
    const int tok = tid >> 2;
    const int c0  = tid & 3;
    const __half* srcb = gkv + (size_t)tok_index(rg, (jt << 6) + tok) * 1024 + h * 128;
#pragma unroll
    for (int s = 0; s < 4; s++) {
        int c = c0 + s * 4;
        int de = (c < 8) ? (bufoff + tok * 72 + c * 8)
                         : (bufoff + BVOF + tok * 72 + (c - 8) * 8);
        CP_ASYNC16(sbu + (uint32_t)de * 2u, (const char*)srcb + c * 16);
    }
}

__global__ __launch_bounds__(256, 2) void region_attn_mma_kernel(
    const float* __restrict__ epeg_w)
{
    extern __shared__ char smc[];
    __half* sb = (__half*)smc;
    const uint32_t sbu = smem_u32(smc);

    const int tid  = threadIdx.x;
    const int it   = blockIdx.x;
    const int h    = blockIdx.y;
    const int rg   = blockIdx.z;
    const int i0   = it << 7;

    const int warp = tid >> 5;
    const int lane = tid & 31;
    const int qr   = lane >> 2;
    const int q2   = (lane & 3) << 1;
    const int lml  = lane & 15;
    const int lmc  = (lane >> 4) << 3;

    const float w0 = epeg_w[h * 5 + 0];
    const float w1 = epeg_w[h * 5 + 1];
    const float w2 = epeg_w[h * 5 + 2];
    const float w3 = epeg_w[h * 5 + 3];
    const float w4 = epeg_w[h * 5 + 4];

    float* Qf = (float*)(smc + BUFA * 2);   // [132][68] fp32 staging
    for (int idx = tid; idx < 132 * 64; idx += 256) {
        int p = idx >> 6, d = idx & 63;
        int ii = i0 - 2 + p;
        float v = 0.f;
        if (ii >= 0 && ii < NREG)
            v = g_q[(size_t)tok_index(rg, ii) * DIMC + h * HD + d];
        Qf[p * 68 + d] = v;
    }
    __syncthreads();

    for (int idx = tid; idx < 128 * 64; idx += 256) {
        int i = idx >> 6, d = idx & 63;
        const float* col = Qf + i * 68 + d;
        float v = col[2 * 68]
                + w0 * col[0] + w1 * col[68] + w2 * col[2 * 68]
                + w3 * col[3 * 68] + w4 * col[4 * 68];
        sb[QOFF + i * 72 + d] = __float2half(v * SCALE_Q);
    }
    __syncthreads();

    attn_cp_tile(sbu, BUFA, g_kv, rg, h, 0, tid);
    CP_COMMIT();

    uint32_t aQ[4][4];
    {
        int r0 = warp * 16;
#pragma unroll
        for (int ks = 0; ks < 4; ks++) {
            uint32_t ad = sbu +
                (uint32_t)(QOFF + (r0 + lml) * 72 + ks * 16 + lmc) * 2u;
            LDM_X4(aQ[ks][0], aQ[ks][1], aQ[ks][2], aQ[ks][3], ad);
        }
    }

    CP_WAIT0();
    __syncthreads();

    float sO[8][4];
#pragma unroll
    for (int i = 0; i < 8; i++)
#pragma unroll
        for (int c = 0; c < 4; c++) sO[i][c] = 0.f;
    float mA = -1e30f, mB = -1e30f, lA = 0.f, lB = 0.f;

    for (int jt = 0; jt < 16; jt++) {
        const int buf = (jt & 1) ? BUFB : BUFA;
        if (jt + 1 < 16)
            attn_cp_tile(sbu, (jt & 1) ? BUFA : BUFB, g_kv, rg, h, jt + 1, tid);
        CP_COMMIT();

        float s[8][4];
#pragma unroll
        for (int nj = 0; nj < 8; nj++)
#pragma unroll
            for (int c = 0; c < 4; c++) s[nj][c] = 0.f;

#pragma unroll
        for (int ks = 0; ks < 4; ks++) {
            const int co = ks * 16 + lmc;
#pragma unroll
            for (int njp = 0; njp < 4; njp++) {
                uint32_t k0_, k1_, k2_, k3_;
                uint32_t ad = sbu +
                    (uint32_t)(buf + (njp * 16 + lml) * 72 + co) * 2u;
                LDM_X4(k0_, k1_, k2_, k3_, ad);
                mma_h(s[2 * njp],     aQ[ks][0], aQ[ks][1], aQ[ks][2], aQ[ks][3], k0_, k2_);
                mma_h(s[2 * njp + 1], aQ[ks][0], aQ[ks][1], aQ[ks][2], aQ[ks][3], k1_, k3_);
            }
        }

        float mtA = -1e30f, mtB = -1e30f;
#pragma unroll
        for (int nj = 0; nj < 8; nj++) {
            mtA = fmaxf(mtA, fmaxf(s[nj][0], s[nj][1]));
            mtB = fmaxf(mtB, fmaxf(s[nj][2], s[nj][3]));
        }
        mtA = fmaxf(mtA, __shfl_xor_sync(0xffffffffu, mtA, 1));
        mtA = fmaxf(mtA, __shfl_xor_sync(0xffffffffu, mtA, 2));
        mtB = fmaxf(mtB, __shfl_xor_sync(0xffffffffu, mtB, 1));
        mtB = fmaxf(mtB, __shfl_xor_sync(0xffffffffu, mtB, 2));
        float mnA = fmaxf(mA, mtA), mnB = fmaxf(mB, mtB);
        float alA = __expf(mA - mnA), alB = __expf(mB - mnB);
        mA = mnA; mB = mnB;

        float rsA = 0.f, rsB = 0.f;
#pragma unroll
        for (int nj = 0; nj < 8; nj++) {
            s[nj][0] = __expf(s[nj][0] - mnA);
            s[nj][1] = __expf(s[nj][1] - mnA);
            s[nj][2] = __expf(s[nj][2] - mnB);
            s[nj][3] = __expf(s[nj][3] - mnB);
            rsA += s[nj][0] + s[nj][1];
            rsB += s[nj][2] + s[nj][3];
        }
        rsA += __shfl_xor_sync(0xffffffffu, rsA, 1);
        rsA += __shfl_xor_sync(0xffffffffu, rsA, 2);
        rsB += __shfl_xor_sync(0xffffffffu, rsB, 1);
        rsB += __shfl_xor_sync(0xffffffffu, rsB, 2);
        lA = lA * alA + rsA;
        lB = lB * alB + rsB;

#pragma unroll
        for (int nd = 0; nd < 8; nd++) {
            sO[nd][0] *= alA; sO[nd][1] *= alA;
            sO[nd][2] *= alB; sO[nd][3] *= alB;
        }

#pragma unroll
        for (int kk = 0; kk < 4; kk++) {
            uint32_t pa[4];
            pa[0] = h2pack(s[2 * kk][0],     s[2 * kk][1]);
            pa[1] = h2pack(s[2 * kk][2],     s[2 * kk][3]);
            pa[2] = h2pack(s[2 * kk + 1][0], s[2 * kk + 1][1]);
            pa[3] = h2pack(s[2 * kk + 1][2], s[2 * kk + 1][3]);
            int vrow = kk * 16 + lml;
#pragma unroll
            for (int ndp = 0; ndp < 4; ndp++) {
                uint32_t v0_, v1_, v2_, v3_;
                uint32_t ad = sbu +
                    (uint32_t)(buf + BVOF + vrow * 72 + ndp * 16 + lmc) * 2u;
                LDM_X4_T(v0_, v1_, v2_, v3_, ad);
                mma_h(sO[2 * ndp],     pa[0], pa[1], pa[2], pa[3], v0_, v1_);
                mma_h(sO[2 * ndp + 1], pa[0], pa[1], pa[2], pa[3], v2_, v3_);
            }
        }

        CP_WAIT0();
        __syncthreads();
    }

    // ---- epilogue: O/l -> g_att (fp16, token order)
    float iA = 1.0f / lA, iB = 1.0f / lB;
    int rA = i0 + warp * 16 + qr;
    int tokA = tok_index(rg, rA);
    int tokB = tok_index(rg, rA + 8);
#pragma unroll
    for (int nd = 0; nd < 8; nd++) {
        int c = h * HD + nd * 8 + q2;
        *(uint32_t*)(g_att + (size_t)tokA * DIMC + c) =
            h2pack(sO[nd][0] * iA, sO[nd][1] * iA);
        *(uint32_t*)(g_att + (size_t)tokB * DIMC + c) =
            h2pack(sO[nd][2] * iB, sO[nd][3] * iB);
    }
}

// ---------------------------------------------------------------------------
extern "C" void kernel_launch(void* const* d_in, const int* in_sizes, int n_in,
                              void* d_out, int out_size) {
    const float* x      = (const float*)d_in[0];
    const float* qkv_w  = (const float*)d_in[1];
    const float* qkv_b  = (const float*)d_in[2];
    const float* proj_w = (const float*)d_in[3];
    const float* proj_b = (const float*)d_in[4];
    const float* epeg_w = (const float*)d_in[5];
    float* out = (float*)d_out;

    float*  q_buf   = nullptr;
    __half* kv_buf  = nullptr;
    __half* att_buf = nullptr;
    __half* x16     = nullptr;
    __half* w1      = nullptr;
    __half* w2      = nullptr;
    cudaGetSymbolAddress((void**)&q_buf,   g_q);
    cudaGetSymbolAddress((void**)&kv_buf,  g_kv);
    cudaGetSymbolAddress((void**)&att_buf, g_att);
    cudaGetSymbolAddress((void**)&x16,     g_x16);
    cudaGetSymbolAddress((void**)&w1,      g_w1);
    cudaGetSymbolAddress((void**)&w2,      g_w2);

    cudaFuncSetAttribute(gemm_mma_kernel,
                         cudaFuncAttributeMaxDynamicSharedMemorySize,
                         GEMM_SMEM_BYTES);
    cudaFuncSetAttribute(region_attn_mma_kernel,
                         cudaFuncAttributeMaxDynamicSharedMemorySize,
                         ATT_SMEM_BYTES);

    // prepass: fp32 -> fp16
    cvt16_kernel<<<512, 256>>>(x,      x16, LTOK * DIMC / 4);
    cvt16_kernel<<<256, 256>>>(qkv_w,  w1,  QKVC * DIMC / 4);
    cvt16_kernel<<<128, 256>>>(proj_w, w2,  DIMC * DIMC / 4);

    // qkv = x @ qkv_w^T + qkv_b -> g_q (fp32) + g_kv (fp16)
    gemm_mma_kernel<<<dim3(QKVC / 128, LTOK / 128), 256, GEMM_SMEM_BYTES>>>(
        x16, w1, qkv_b, q_buf, kv_buf, LTOK, QKVC, DIMC);

    // flash region attention (conv folded into Q') -> g_att fp16
    region_attn_mma_kernel<<<dim3(8, NH, 16), 256, ATT_SMEM_BYTES>>>(epeg_w);

    // out = att @ proj_w^T + proj_b
    gemm_mma_kernel<<<dim3(DIMC / 128, LTOK / 128), 256, GEMM_SMEM_BYTES>>>(
        att_buf, w2, proj_b, out, nullptr, LTOK, DIMC, DIMC);
}

// round 16
// speedup vs baseline: 6.4872x; 1.0405x over previous
#include <cuda_runtime.h>
#include <cuda_fp16.h>
#include <cstdint>

// ---------------------------------------------------------------------------
// RegionAttention R16:
//  - GEMM: one-sync cp.async pipeline (WAIT0 -> sync -> issue next -> compute);
//    half the barriers of R15, same overlap.
//  - attention: softmax in exp2 domain (log2e folded into Q' scale);
//    exp/alpha are single MUFU.EX2 ops.
//  - otherwise identical to R15 (fp16 single-term mma, prepass converts,
//    2 CTAs/SM everywhere).
// ---------------------------------------------------------------------------

#define LTOK   16384
#define DIMC   512
#define QKVC   1536
#define NH     8
#define HD     64
#define NREG   1024
#define SCALE_Q 0.125f
#define LOG2E  1.4426950408889634f

__device__ float  g_q[LTOK * DIMC];        // q, fp32, bias applied
__device__ __half g_kv[LTOK * 1024];       // [tok][head][k|v][64] fp16
__device__ __half g_att[LTOK * DIMC];      // attention output fp16, token order
__device__ __half g_x16[LTOK * DIMC];      // x converted
__device__ __half g_w1[QKVC * DIMC];       // qkv_w converted
__device__ __half g_w2[DIMC * DIMC];       // proj_w converted

__device__ __forceinline__ int tok_index(int rg, int n) {
    return ((rg >> 2) << 12) | ((n >> 5) << 7) | ((rg & 3) << 5) | (n & 31);
}

__device__ __forceinline__ uint32_t smem_u32(const void* p) {
    uint32_t a;
    asm("{ .reg .u64 t; cvta.to.shared.u64 t, %1; cvt.u32.u64 %0, t; }"
        : "=r"(a) : "l"(p));
    return a;
}

__device__ __forceinline__ float ex2f(float x) {
    float y;
    asm("ex2.approx.ftz.f32 %0, %1;" : "=f"(y) : "f"(x));
    return y;
}

__device__ __forceinline__ void mma_h(float c[4],
                                      uint32_t a0, uint32_t a1,
                                      uint32_t a2, uint32_t a3,
                                      uint32_t b0, uint32_t b1) {
    asm volatile(
        "mma.sync.aligned.m16n8k16.row.col.f32.f16.f16.f32 "
        "{%0,%1,%2,%3}, {%4,%5,%6,%7}, {%8,%9}, {%0,%1,%2,%3};"
        : "+f"(c[0]), "+f"(c[1]), "+f"(c[2]), "+f"(c[3])
        : "r"(a0), "r"(a1), "r"(a2), "r"(a3), "r"(b0), "r"(b1));
}

__device__ __forceinline__ uint32_t h2pack(float x, float y) {
    __half2 h = __floats2half2_rn(x, y);
    return *(uint32_t*)&h;
}

#define LDM_X4(r0_, r1_, r2_, r3_, addr) \
    asm volatile("ldmatrix.sync.aligned.m8n8.x4.shared.b16 {%0,%1,%2,%3}, [%4];" \
        : "=r"(r0_), "=r"(r1_), "=r"(r2_), "=r"(r3_) : "r"(addr))
#define LDM_X4_T(r0_, r1_, r2_, r3_, addr) \
    asm volatile("ldmatrix.sync.aligned.m8n8.x4.trans.shared.b16 {%0,%1,%2,%3}, [%4];" \
        : "=r"(r0_), "=r"(r1_), "=r"(r2_), "=r"(r3_) : "r"(addr))

#define CP_ASYNC16(dst, src) \
    asm volatile("cp.async.cg.shared.global [%0], [%1], 16;" \
                 :: "r"(dst), "l"(src) : "memory")
#define CP_COMMIT() asm volatile("cp.async.commit_group;" ::: "memory")
#define CP_WAIT0()  asm volatile("cp.async.wait_group 0;" ::: "memory")

// ===========================================================================
// Prepass: fp32 -> fp16 convert (vectorized, grid-stride).
// ===========================================================================
__global__ __launch_bounds__(256) void cvt16_kernel(
    const float* __restrict__ src, __half* __restrict__ dst, int n4)
{
    int i = blockIdx.x * 256 + threadIdx.x;
    int stride = gridDim.x * 256;
    for (; i < n4; i += stride) {
        float4 v = *(const float4*)(src + i * 4);
        uint2 o;
        o.x = h2pack(v.x, v.y);
        o.y = h2pack(v.z, v.w);
        *(uint2*)(dst + i * 4) = o;
    }
}

// ===========================================================================
// fp16 GEMM, one-sync cp.async pipeline: C = A @ W^T + bias.
// Tile 128x128, K-chunk 64, 256 threads = 8 warps (2m x 4n). 2 CTAs/SM.
// If KV != nullptr (QKV gemm): cols [0,512) -> fp32 C (stride 512),
// cols [512,1536) -> fp16 into KV. Else fp32 C (stride N).
// ===========================================================================
#define GSTRIDE 72
#define GOFF_W  (128 * GSTRIDE)
#define GBUFH   (2 * 128 * GSTRIDE)               // fp16 elems per buffer
#define GEMM_SMEM_BYTES (2 * GBUFH * 2)           // 73728

__device__ __forceinline__ void gemm_issue_chunk(
    uint32_t sbu, int bufoff, const __half* __restrict__ A,
    const __half* __restrict__ W, int m0, int n0, int K, int k0, int tid)
{
#pragma unroll
    for (int s = 0; s < 4; s++) {
        int id = tid + s * 256;        // 0..1023
        int r  = id >> 3;              // 0..127
        int cc = id & 7;               // 16B chunk
        CP_ASYNC16(sbu + (uint32_t)(bufoff + r * GSTRIDE + cc * 8) * 2u,
                   A + (size_t)(m0 + r) * K + k0 + cc * 8);
        CP_ASYNC16(sbu + (uint32_t)(bufoff + GOFF_W + r * GSTRIDE + cc * 8) * 2u,
                   W + (size_t)(n0 + r) * K + k0 + cc * 8);
    }
    CP_COMMIT();
}

__global__ __launch_bounds__(256, 2) void gemm_mma_kernel(
    const __half* __restrict__ A, const __half* __restrict__ W,
    const float* __restrict__ bias, float* __restrict__ C,
    __half* __restrict__ KV,
    int M, int N, int K)
{
    extern __shared__ char smc[];
    const uint32_t sbu = smem_u32(smc);

    const int tid  = threadIdx.x;
    const int m0   = blockIdx.y << 7;
    const int n0   = blockIdx.x << 7;
    const int wid  = tid >> 5;
    const int lane = tid & 31;
    const int wm   = wid & 1;
    const int wn   = wid >> 1;

    const int qrow = lane >> 2;
    const int qk2  = (lane & 3) << 1;
    const int lml  = lane & 15;
    const int lmc  = (lane >> 4) << 3;

    float acc[4][4][4];
#pragma unroll
    for (int i = 0; i < 4; i++)
#pragma unroll
        for (int j = 0; j < 4; j++)
#pragma unroll
            for (int c = 0; c < 4; c++) acc[i][j][c] = 0.f;

    const int nchunks = K >> 6;

    // prologue: chunk 0 in flight
    gemm_issue_chunk(sbu, 0, A, W, m0, n0, K, 0, tid);

    for (int kc = 0; kc < nchunks; kc++) {
        const int buf = (kc & 1) ? GBUFH : 0;

        CP_WAIT0();          // group(kc), issued one compute-phase ago, resident
        __syncthreads();     // all warps past compute(kc-1): other buffer free

        if (kc + 1 < nchunks)
            gemm_issue_chunk(sbu, (kc & 1) ? 0 : GBUFH, A, W, m0, n0, K,
                             (kc + 1) << 6, tid);

#pragma unroll
        for (int ks = 0; ks < 4; ks++) {
            const int co = ks * 16 + lmc;
            uint32_t a[4][4], b[2][4];
#pragma unroll
            for (int i = 0; i < 4; i++) {
                uint32_t ad = sbu +
                    (uint32_t)(buf + (wm * 64 + i * 16 + lml) * GSTRIDE + co) * 2u;
                LDM_X4(a[i][0], a[i][1], a[i][2], a[i][3], ad);
            }
#pragma unroll
            for (int jp = 0; jp < 2; jp++) {
                uint32_t ad = sbu +
                    (uint32_t)(buf + GOFF_W + (wn * 32 + jp * 16 + lml) * GSTRIDE + co) * 2u;
                LDM_X4(b[jp][0], b[jp][1], b[jp][2], b[jp][3], ad);
            }
#pragma unroll
            for (int i = 0; i < 4; i++)
#pragma unroll
                for (int jp = 0; jp < 2; jp++) {
                    mma_h(acc[i][2 * jp],     a[i][0], a[i][1], a[i][2], a[i][3],
                          b[jp][0], b[jp][2]);
                    mma_h(acc[i][2 * jp + 1], a[i][0], a[i][1], a[i][2], a[i][3],
                          b[jp][1], b[jp][3]);
                }
        }
    }

    // ---- epilogue
#pragma unroll
    for (int i = 0; i < 4; i++) {
        int gr = m0 + wm * 64 + i * 16 + qrow;
#pragma unroll
        for (int j = 0; j < 4; j++) {
            int gc = n0 + wn * 32 + j * 8 + qk2;
            float2 bv = *(const float2*)(bias + gc);
            float v00 = acc[i][j][0] + bv.x, v01 = acc[i][j][1] + bv.y;
            float v10 = acc[i][j][2] + bv.x, v11 = acc[i][j][3] + bv.y;
            if (KV == nullptr) {
                *(float2*)(C + (size_t)gr * N + gc)       = make_float2(v00, v01);
                *(float2*)(C + (size_t)(gr + 8) * N + gc) = make_float2(v10, v11);
            } else if (gc < 512) {
                *(float2*)(C + (size_t)gr * 512 + gc)       = make_float2(v00, v01);
                *(float2*)(C + (size_t)(gr + 8) * 512 + gc) = make_float2(v10, v11);
            } else {
                int isV  = gc >= 1024;
                int xx   = gc - (isV ? 1024 : 512);
                int head = xx >> 6, d = xx & 63;
                int off  = head * 128 + (isV ? 64 : 0) + d;
                *(uint32_t*)(KV + (size_t)gr * 1024 + off)       = h2pack(v00, v01);
                *(uint32_t*)(KV + (size_t)(gr + 8) * 1024 + off) = h2pack(v10, v11);
            }
        }
    }
}

// ===========================================================================
// Flash attention: exp2-domain softmax (log2e folded into Q' scale).
// 64-key j-tiles, cp.async double buffer, 2 CTAs/SM.
// ===========================================================================
#define QOFF 0
#define BUFA 9216
#define BUFB 18432
#define BVOF 4608
#define ATT_SMEM_BYTES (27648 * 2)   // 55296

__device__ __forceinline__ void attn_cp_tile(
    uint32_t sbu, int bufoff, const __half* __restrict__ gkv,
    int rg, int h, int jt, int tid)
{
    const int tok = tid >> 2;
    const int c0  = tid & 3;
    const __half* srcb = gkv + (size_t)tok_index(rg, (jt << 6) + tok) * 1024 + h * 128;
#pragma unroll
    for (int s = 0; s < 4; s++) {
        int c = c0 + s * 4;
        int de = (c < 8) ? (bufoff + tok * 72 + c * 8)
                         : (bufoff + BVOF + tok * 72 + (c - 8) * 8);
        CP_ASYNC16(sbu + (uint32_t)de * 2u, (const char*)srcb + c * 16);
    }
}

__global__ __launch_bounds__(256, 2) void region_attn_mma_kernel(
    const float* __restrict__ epeg_w)
{
    extern __shared__ char smc[];
    __half* sb = (__half*)smc;
    const uint32_t sbu = smem_u32(smc);

    const int tid  = threadIdx.x;
    const int it   = blockIdx.x;
    const int h    = blockIdx.y;
    const int rg   = blockIdx.z;
    const int i0   = it << 7;

    const int warp = tid >> 5;
    const int lane = tid & 31;
    const int qr   = lane >> 2;
    const int q2   = (lane & 3) << 1;
    const int lml  = lane & 15;
    const int lmc  = (lane >> 4) << 3;

    const float w0 = epeg_w[h * 5 + 0];
    const float w1 = epeg_w[h * 5 + 1];
    const float w2 = epeg_w[h * 5 + 2];
    const float w3 = epeg_w[h * 5 + 3];
    const float w4 = epeg_w[h * 5 + 4];

    float* Qf = (float*)(smc + BUFA * 2);   // [132][68] fp32 staging
    for (int idx = tid; idx < 132 * 64; idx += 256) {
        int p = idx >> 6, d = idx & 63;
        int ii = i0 - 2 + p;
        float v = 0.f;
        if (ii >= 0 && ii < NREG)
            v = g_q[(size_t)tok_index(rg, ii) * DIMC + h * HD + d];
        Qf[p * 68 + d] = v;
    }
    __syncthreads();

    // Q'' = SCALE*LOG2E*(q + conv5(q)) -> softmax runs in exp2 domain
    for (int idx = tid; idx < 128 * 64; idx += 256) {
        int i = idx >> 6, d = idx & 63;
        const float* col = Qf + i * 68 + d;
        float v = col[2 * 68]
                + w0 * col[0] + w1 * col[68] + w2 * col[2 * 68]
                + w3 * col[3 * 68] + w4 * col[4 * 68];
        sb[QOFF + i * 72 + d] = __float2half(v * (SCALE_Q * LOG2E));
    }
    __syncthreads();

    attn_cp_tile(sbu, BUFA, g_kv, rg, h, 0, tid);
    CP_COMMIT();

    uint32_t aQ[4][4];
    {
        int r0 = warp * 16;
#pragma unroll
        for (int ks = 0; ks < 4; ks++) {
            uint32_t ad = sbu +
                (uint32_t)(QOFF + (r0 + lml) * 72 + ks * 16 + lmc) * 2u;
            LDM_X4(aQ[ks][0], aQ[ks][1], aQ[ks][2], aQ[ks][3], ad);
        }
    }

    CP_WAIT0();
    __syncthreads();

    float sO[8][4];
#pragma unroll
    for (int i = 0; i < 8; i++)
#pragma unroll
        for (int c = 0; c < 4; c++) sO[i][c] = 0.f;
    float mA = -1e30f, mB = -1e30f, lA = 0.f, lB = 0.f;

    for (int jt = 0; jt < 16; jt++) {
        const int buf = (jt & 1) ? BUFB : BUFA;
        if (jt + 1 < 16)
            attn_cp_tile(sbu, (jt & 1) ? BUFA : BUFB, g_kv, rg, h, jt + 1, tid);
        CP_COMMIT();

        float s[8][4];
#pragma unroll
        for (int nj = 0; nj < 8; nj++)
#pragma unroll
            for (int c = 0; c < 4; c++) s[nj][c] = 0.f;

#pragma unroll
        for (int ks = 0; ks < 4; ks++) {
            const int co = ks * 16 + lmc;
#pragma unroll
            for (int njp = 0; njp < 4; njp++) {
                uint32_t k0_, k1_, k2_, k3_;
                uint32_t ad = sbu +
                    (uint32_t)(buf + (njp * 16 + lml) * 72 + co) * 2u;
                LDM_X4(k0_, k1_, k2_, k3_, ad);
                mma_h(s[2 * njp],     aQ[ks][0], aQ[ks][1], aQ[ks][2], aQ[ks][3], k0_, k2_);
                mma_h(s[2 * njp + 1], aQ[ks][0], aQ[ks][1], aQ[ks][2], aQ[ks][3], k1_, k3_);
            }
        }

        // ---- exp2-domain online softmax (rows A=qr, B=qr+8)
        float mtA = -1e30f, mtB = -1e30f;
#pragma unroll
        for (int nj = 0; nj < 8; nj++) {
            mtA = fmaxf(mtA, fmaxf(s[nj][0], s[nj][1]));
            mtB = fmaxf(mtB, fmaxf(s[nj][2], s[nj][3]));
        }
        mtA = fmaxf(mtA, __shfl_xor_sync(0xffffffffu, mtA, 1));
        mtA = fmaxf(mtA, __shfl_xor_sync(0xffffffffu, mtA, 2));
        mtB = fmaxf(mtB, __shfl_xor_sync(0xffffffffu, mtB, 1));
        mtB = fmaxf(mtB, __shfl_xor_sync(0xffffffffu, mtB, 2));
        float mnA = fmaxf(mA, mtA), mnB = fmaxf(mB, mtB);
        float alA = ex2f(mA - mnA), alB = ex2f(mB - mnB);
        mA = mnA; mB = mnB;

        float rsA = 0.f, rsB = 0.f;
#pragma unroll
        for (int nj = 0; nj < 8; nj++) {
            s[nj][0] = ex2f(s[nj][0] - mnA);
            s[nj][1] = ex2f(s[nj][1] - mnA);
            s[nj][2] = ex2f(s[nj][2] - mnB);
            s[nj][3] = ex2f(s[nj][3] - mnB);
            rsA += s[nj][0] + s[nj][1];
            rsB += s[nj][2] + s[nj][3];
        }
        rsA += __shfl_xor_sync(0xffffffffu, rsA, 1);
        rsA += __shfl_xor_sync(0xffffffffu, rsA, 2);
        rsB += __shfl_xor_sync(0xffffffffu, rsB, 1);
        rsB += __shfl_xor_sync(0xffffffffu, rsB, 2);
        lA = lA * alA + rsA;
        lB = lB * alB + rsB;

#pragma unroll
        for (int nd = 0; nd < 8; nd++) {
            sO[nd][0] *= alA; sO[nd][1] *= alA;
            sO[nd][2] *= alB; sO[nd][3] *= alB;
        }

#pragma unroll
        for (int kk = 0; kk < 4; kk++) {
            uint32_t pa[4];
            pa[0] = h2pack(s[2 * kk][0],     s[2 * kk][1]);
            pa[1] = h2pack(s[2 * kk][2],     s[2 * kk][3]);
            pa[2] = h2pack(s[2 * kk + 1][0], s[2 * kk + 1][1]);
            pa[3] = h2pack(s[2 * kk + 1][2], s[2 * kk + 1][3]);
            int vrow = kk * 16 + lml;
#pragma unroll
            for (int ndp = 0; ndp < 4; ndp++) {
                uint32_t v0_, v1_, v2_, v3_;
                uint32_t ad = sbu +
                    (uint32_t)(buf + BVOF + vrow * 72 + ndp * 16 + lmc) * 2u;
                LDM_X4_T(v0_, v1_, v2_, v3_, ad);
                mma_h(sO[2 * ndp],     pa[0], pa[1], pa[2], pa[3], v0_, v1_);
                mma_h(sO[2 * ndp + 1], pa[0], pa[1], pa[2], pa[3], v2_, v3_);
            }
        }

        CP_WAIT0();
        __syncthreads();
    }

    // ---- epilogue: O/l -> g_att (fp16, token order)
    float iA = 1.0f / lA, iB = 1.0f / lB;
    int rA = i0 + warp * 16 + qr;
    int tokA = tok_index(rg, rA);
    int tokB = tok_index(rg, rA + 8);
#pragma unroll
    for (int nd = 0; nd < 8; nd++) {
        int c = h * HD + nd * 8 + q2;
        *(uint32_t*)(g_att + (size_t)tokA * DIMC + c) =
            h2pack(sO[nd][0] * iA, sO[nd][1] * iA);
        *(uint32_t*)(g_att + (size_t)tokB * DIMC + c) =
            h2pack(sO[nd][2] * iB, sO[nd][3] * iB);
    }
}

// ---------------------------------------------------------------------------
extern "C" void kernel_launch(void* const* d_in, const int* in_sizes, int n_in,
                              void* d_out, int out_size) {
    const float* x      = (const float*)d_in[0];
    const float* qkv_w  = (const float*)d_in[1];
    const float* qkv_b  = (const float*)d_in[2];
    const float* proj_w = (const float*)d_in[3];
    const float* proj_b = (const float*)d_in[4];
    const float* epeg_w = (const float*)d_in[5];
    float* out = (float*)d_out;

    float*  q_buf   = nullptr;
    __half* kv_buf  = nullptr;
    __half* att_buf = nullptr;
    __half* x16     = nullptr;
    __half* w1      = nullptr;
    __half* w2      = nullptr;
    cudaGetSymbolAddress((void**)&q_buf,   g_q);
    cudaGetSymbolAddress((void**)&kv_buf,  g_kv);
    cudaGetSymbolAddress((void**)&att_buf, g_att);
    cudaGetSymbolAddress((void**)&x16,     g_x16);
    cudaGetSymbolAddress((void**)&w1,      g_w1);
    cudaGetSymbolAddress((void**)&w2,      g_w2);

    cudaFuncSetAttribute(gemm_mma_kernel,
                         cudaFuncAttributeMaxDynamicSharedMemorySize,
                         GEMM_SMEM_BYTES);
    cudaFuncSetAttribute(region_attn_mma_kernel,
                         cudaFuncAttributeMaxDynamicSharedMemorySize,
                         ATT_SMEM_BYTES);

    // prepass: fp32 -> fp16
    cvt16_kernel<<<512, 256>>>(x,      x16, LTOK * DIMC / 4);
    cvt16_kernel<<<256, 256>>>(qkv_w,  w1,  QKVC * DIMC / 4);
    cvt16_kernel<<<128, 256>>>(proj_w, w2,  DIMC * DIMC / 4);

    // qkv = x @ qkv_w^T + qkv_b -> g_q (fp32) + g_kv (fp16)
    gemm_mma_kernel<<<dim3(QKVC / 128, LTOK / 128), 256, GEMM_SMEM_BYTES>>>(
        x16, w1, qkv_b, q_buf, kv_buf, LTOK, QKVC, DIMC);

    // flash region attention (conv folded into Q'', exp2 softmax)
    region_attn_mma_kernel<<<dim3(8, NH, 16), 256, ATT_SMEM_BYTES>>>(epeg_w);

    // out = att @ proj_w^T + proj_b
    gemm_mma_kernel<<<dim3(DIMC / 128, LTOK / 128), 256, GEMM_SMEM_BYTES>>>(
        att_buf, w2, proj_b, out, nullptr, LTOK, DIMC, DIMC);
}